// round 2
// baseline (speedup 1.0000x reference)
#include <cuda_runtime.h>
#include <math.h>

#define NN 100000
#define NE 3200000
#define D1 256
#define D2 64
#define NPARTMAX 512

typedef unsigned long long u64;

// ---------------- static device scratch ----------------
__device__ int   g_cnt[NN];
__device__ int   g_woff[NN];
__device__ int   g_rowptr[NN + 1];
__device__ int   g_part[NPARTMAX];
__device__ int   g_partpre[NPARTMAX];
__device__ int   g_col[NE];
__device__ float g_w1[NE];
__device__ float g_w2[NE];
__device__ float g_dinv1[NN];
__device__ float g_dinv2[NN];
__device__ float g_bufA[(size_t)NN * D1];
__device__ float g_bufB[(size_t)NN * D1];
__device__ float g_bufG[(size_t)NN * D2];

// ---------------- packed f32x2 helpers ----------------
__device__ __forceinline__ void fma2(u64& d, u64 a, u64 b) {
    asm("fma.rn.f32x2 %0, %1, %2, %0;" : "+l"(d) : "l"(a), "l"(b));
}
__device__ __forceinline__ u64 pack2(float lo, float hi) {
    u64 r; asm("mov.b64 %0, {%1, %2};" : "=l"(r) : "f"(lo), "f"(hi)); return r;
}
__device__ __forceinline__ float2 unpack2(u64 v) {
    float2 f; asm("mov.b64 {%0, %1}, %2;" : "=f"(f.x), "=f"(f.y) : "l"(v)); return f;
}

__device__ __forceinline__ float selu_f(float x) {
    const float sc = 1.0507009873554804934f;
    const float al = 1.6732632423543772848f;
    return x > 0.f ? sc * x : sc * al * expm1f(x);
}

// ---------------- graph preprocessing ----------------
__global__ void k_clear(int n) {
    int i = blockIdx.x * blockDim.x + threadIdx.x;
    if (i < n) { g_cnt[i] = 0; g_woff[i] = 0; }
}

__global__ void k_count(const int* __restrict__ dst, int e) {
    int i = blockIdx.x * blockDim.x + threadIdx.x;
    if (i < e) atomicAdd(&g_cnt[dst[i]], 1);
}

__global__ void k_dinv(int n) {
    int i = blockIdx.x * blockDim.x + threadIdx.x;
    if (i < n) {
        int d = g_cnt[i];
        g_dinv1[i] = d > 0 ? rsqrtf((float)d) : 0.f;
        g_dinv2[i] = rsqrtf((float)(d + 1));
    }
}

// 3-stage scan: per-block reduce -> scan partials -> per-block scan + add
__global__ void k_reduce(int n) {
    __shared__ int s[256];
    int t = threadIdx.x, i = blockIdx.x * 256 + t;
    s[t] = (i < n) ? g_cnt[i] : 0;
    __syncthreads();
    for (int o = 128; o; o >>= 1) { if (t < o) s[t] += s[t + o]; __syncthreads(); }
    if (t == 0) g_part[blockIdx.x] = s[0];
}

__global__ void k_scanpart(int nparts, int n) {
    __shared__ int s[NPARTMAX];
    int t = threadIdx.x;
    int v = (t < nparts) ? g_part[t] : 0;
    s[t] = v;
    __syncthreads();
    for (int o = 1; o < NPARTMAX; o <<= 1) {
        int x = (t >= o) ? s[t - o] : 0;
        __syncthreads();
        s[t] += x;
        __syncthreads();
    }
    if (t < nparts) g_partpre[t] = s[t] - v;
    if (t == nparts - 1) g_rowptr[n] = s[t];
}

__global__ void k_scatter(int n) {
    __shared__ int s[256];
    int t = threadIdx.x, i = blockIdx.x * 256 + t;
    int v = (i < n) ? g_cnt[i] : 0;
    s[t] = v;
    __syncthreads();
    for (int o = 1; o < 256; o <<= 1) {
        int x = (t >= o) ? s[t - o] : 0;
        __syncthreads();
        s[t] += x;
        __syncthreads();
    }
    if (i < n) g_rowptr[i] = g_partpre[blockIdx.x] + s[t] - v;
}

__global__ void k_fill(const int* __restrict__ src, const int* __restrict__ dst, int e) {
    int i = blockIdx.x * blockDim.x + threadIdx.x;
    if (i < e) {
        int d = dst[i], s = src[i];
        int p = g_rowptr[d] + atomicAdd(&g_woff[d], 1);
        g_col[p] = s;
        g_w1[p]  = g_dinv1[s];
        g_w2[p]  = g_dinv2[s];
    }
}

// ---------------- 256-dim hop: out[i] = coeff*dinv[i]*sum_j w[j]*in[col[j]] ----------------
__global__ void __launch_bounds__(256) k_hop256(
    const float* __restrict__ xin, float* __restrict__ xout,
    const int* __restrict__ colidx, const float* __restrict__ wsrc,
    const float* __restrict__ dinv, float coeff, int n)
{
    int node = (blockIdx.x * blockDim.x + threadIdx.x) >> 5;
    int lane = threadIdx.x & 31;
    if (node >= n) return;
    int beg = g_rowptr[node], end = g_rowptr[node + 1];

    u64 A0 = 0, A1 = 0, A2 = 0, A3 = 0;

    for (int e0 = beg; e0 < end; e0 += 32) {
        int idx = e0 + lane;
        int c = 0; float w = 0.f;
        if (idx < end) { c = colidx[idx]; w = wsrc[idx]; }
        int cnt = min(32, end - e0);
        int j = 0;
        for (; j + 4 <= cnt; j += 4) {
            int   c0 = __shfl_sync(~0u, c, j + 0); float w0 = __shfl_sync(~0u, w, j + 0);
            int   c1 = __shfl_sync(~0u, c, j + 1); float w1 = __shfl_sync(~0u, w, j + 1);
            int   c2 = __shfl_sync(~0u, c, j + 2); float w2 = __shfl_sync(~0u, w, j + 2);
            int   c3 = __shfl_sync(~0u, c, j + 3); float w3 = __shfl_sync(~0u, w, j + 3);
            const ulonglong2* r0 = (const ulonglong2*)(xin + (size_t)c0 * D1);
            const ulonglong2* r1 = (const ulonglong2*)(xin + (size_t)c1 * D1);
            const ulonglong2* r2 = (const ulonglong2*)(xin + (size_t)c2 * D1);
            const ulonglong2* r3 = (const ulonglong2*)(xin + (size_t)c3 * D1);
            ulonglong2 v00 = __ldg(r0 + lane), v01 = __ldg(r0 + lane + 32);
            ulonglong2 v10 = __ldg(r1 + lane), v11 = __ldg(r1 + lane + 32);
            ulonglong2 v20 = __ldg(r2 + lane), v21 = __ldg(r2 + lane + 32);
            ulonglong2 v30 = __ldg(r3 + lane), v31 = __ldg(r3 + lane + 32);
            u64 wp0 = pack2(w0, w0), wp1 = pack2(w1, w1);
            u64 wp2 = pack2(w2, w2), wp3 = pack2(w3, w3);
            fma2(A0, wp0, v00.x); fma2(A1, wp0, v00.y); fma2(A2, wp0, v01.x); fma2(A3, wp0, v01.y);
            fma2(A0, wp1, v10.x); fma2(A1, wp1, v10.y); fma2(A2, wp1, v11.x); fma2(A3, wp1, v11.y);
            fma2(A0, wp2, v20.x); fma2(A1, wp2, v20.y); fma2(A2, wp2, v21.x); fma2(A3, wp2, v21.y);
            fma2(A0, wp3, v30.x); fma2(A1, wp3, v30.y); fma2(A2, wp3, v31.x); fma2(A3, wp3, v31.y);
        }
        for (; j < cnt; j++) {
            int   cj = __shfl_sync(~0u, c, j);
            float wj = __shfl_sync(~0u, w, j);
            const ulonglong2* r = (const ulonglong2*)(xin + (size_t)cj * D1);
            ulonglong2 v0 = __ldg(r + lane), v1 = __ldg(r + lane + 32);
            u64 wp = pack2(wj, wj);
            fma2(A0, wp, v0.x); fma2(A1, wp, v0.y); fma2(A2, wp, v1.x); fma2(A3, wp, v1.y);
        }
    }

    float s = coeff * __ldg(dinv + node);
    float2 f0 = unpack2(A0), f1 = unpack2(A1), f2 = unpack2(A2), f3 = unpack2(A3);
    float4 o0 = make_float4(s * f0.x, s * f0.y, s * f1.x, s * f1.y);
    float4 o1 = make_float4(s * f2.x, s * f2.y, s * f3.x, s * f3.y);
    float4* orow = (float4*)(xout + (size_t)node * D1);
    orow[lane]      = o0;
    orow[lane + 32] = o1;
}

// ---------------- fp32 tiled GEMM with packed f32x2 math ----------------
// C[M,N] = act(A[M,256] @ B[256,N] (+bias))
template<bool DO_SELU>
__global__ void __launch_bounds__(256) k_gemm(
    const float* __restrict__ A, const float* __restrict__ B,
    const float* __restrict__ bias, float* __restrict__ C, int M, int N)
{
    const int BM = 128, BN = 64, BK = 16;
    __shared__ float  As[BK][BM];
    __shared__ float2 Bs[BK][BN];   // duplicated {b,b} pairs

    int tid  = threadIdx.x;
    int trow = tid & 15;   // rows trow*8 .. +7
    int tcol = tid >> 4;   // cols tcol*4 .. +3
    int blockM = blockIdx.x * BM;
    int blockN = blockIdx.y * BN;

    u64 acc[4][4];   // [row-pair][col]
#pragma unroll
    for (int i = 0; i < 4; i++)
#pragma unroll
        for (int j = 0; j < 4; j++) acc[i][j] = 0ull;

    for (int k0 = 0; k0 < 256; k0 += BK) {
        // A tile: 128x16 transposed into As[k][m]
#pragma unroll
        for (int l = 0; l < 2; l++) {
            int pos = tid * 2 + l;
            int r  = pos >> 2;
            int cv = pos & 3;
            int gr = blockM + r;
            if (gr > M - 1) gr = M - 1;
            float4 v = *(const float4*)(A + (size_t)gr * 256 + k0 + cv * 4);
            As[cv * 4 + 0][r] = v.x;
            As[cv * 4 + 1][r] = v.y;
            As[cv * 4 + 2][r] = v.z;
            As[cv * 4 + 3][r] = v.w;
        }
        // B tile: 16x64, stored duplicated
        {
            int r  = tid >> 4;
            int cb = (tid & 15) * 4;
            float4 v = *(const float4*)(B + (size_t)(k0 + r) * N + blockN + cb);
            float4* bp = (float4*)&Bs[r][cb];
            bp[0] = make_float4(v.x, v.x, v.y, v.y);
            bp[1] = make_float4(v.z, v.z, v.w, v.w);
        }
        __syncthreads();
#pragma unroll
        for (int k = 0; k < BK; k++) {
            const ulonglong2* ap = (const ulonglong2*)&As[k][trow * 8];
            ulonglong2 a01 = ap[0], a23 = ap[1];
            u64 a_p[4] = { a01.x, a01.y, a23.x, a23.y };
            const ulonglong2* bp = (const ulonglong2*)&Bs[k][tcol * 4];
            ulonglong2 b01 = bp[0], b23 = bp[1];
            u64 b_d[4] = { b01.x, b01.y, b23.x, b23.y };
#pragma unroll
            for (int i = 0; i < 4; i++)
#pragma unroll
                for (int j = 0; j < 4; j++) fma2(acc[i][j], a_p[i], b_d[j]);
        }
        __syncthreads();
    }

    float2 accf[4][4];
#pragma unroll
    for (int i = 0; i < 4; i++)
#pragma unroll
        for (int j = 0; j < 4; j++) accf[i][j] = unpack2(acc[i][j]);

    float4 bias4 = make_float4(0.f, 0.f, 0.f, 0.f);
    if (DO_SELU) bias4 = *(const float4*)(bias + blockN + tcol * 4);

#pragma unroll
    for (int i = 0; i < 8; i++) {
        int gr = blockM + trow * 8 + i;
        if (gr < M) {
            int p = i >> 1;
            float r0 = (i & 1) ? accf[p][0].y : accf[p][0].x;
            float r1 = (i & 1) ? accf[p][1].y : accf[p][1].x;
            float r2 = (i & 1) ? accf[p][2].y : accf[p][2].x;
            float r3 = (i & 1) ? accf[p][3].y : accf[p][3].x;
            float4 v;
            if (DO_SELU) {
                v.x = selu_f(r0 + bias4.x);
                v.y = selu_f(r1 + bias4.y);
                v.z = selu_f(r2 + bias4.z);
                v.w = selu_f(r3 + bias4.w);
            } else {
                v.x = r0; v.y = r1; v.z = r2; v.w = r3;
            }
            *(float4*)(C + (size_t)gr * N + blockN + tcol * 4) = v;
        }
    }
}

// ---------------- final hop (D=64, self loops) + bias + log_softmax ----------------
__global__ void __launch_bounds__(256) k_out(
    const float* __restrict__ g, const float* __restrict__ dinv2,
    const int* __restrict__ colidx, const float* __restrict__ wsrc,
    const float* __restrict__ b2, float* __restrict__ out, int n)
{
    int node = (blockIdx.x * blockDim.x + threadIdx.x) >> 5;
    int lane = threadIdx.x & 31;
    if (node >= n) return;
    int beg = g_rowptr[node], end = g_rowptr[node + 1];

    float di = __ldg(dinv2 + node);
    // self loop term
    u64 acc = 0;
    {
        u64 sv = __ldg((const u64*)(g + (size_t)node * D2) + lane);
        u64 dp = pack2(di, di);
        fma2(acc, dp, sv);
    }

    for (int e0 = beg; e0 < end; e0 += 32) {
        int idx = e0 + lane;
        int c = 0; float w = 0.f;
        if (idx < end) { c = colidx[idx]; w = wsrc[idx]; }
        int cnt = min(32, end - e0);
        int j = 0;
        for (; j + 4 <= cnt; j += 4) {
            int   c0 = __shfl_sync(~0u, c, j + 0); float w0 = __shfl_sync(~0u, w, j + 0);
            int   c1 = __shfl_sync(~0u, c, j + 1); float w1 = __shfl_sync(~0u, w, j + 1);
            int   c2 = __shfl_sync(~0u, c, j + 2); float w2 = __shfl_sync(~0u, w, j + 2);
            int   c3 = __shfl_sync(~0u, c, j + 3); float w3 = __shfl_sync(~0u, w, j + 3);
            u64 v0 = __ldg((const u64*)(g + (size_t)c0 * D2) + lane);
            u64 v1 = __ldg((const u64*)(g + (size_t)c1 * D2) + lane);
            u64 v2 = __ldg((const u64*)(g + (size_t)c2 * D2) + lane);
            u64 v3 = __ldg((const u64*)(g + (size_t)c3 * D2) + lane);
            fma2(acc, pack2(w0, w0), v0);
            fma2(acc, pack2(w1, w1), v1);
            fma2(acc, pack2(w2, w2), v2);
            fma2(acc, pack2(w3, w3), v3);
        }
        for (; j < cnt; j++) {
            int   cj = __shfl_sync(~0u, c, j);
            float wj = __shfl_sync(~0u, w, j);
            u64 v = __ldg((const u64*)(g + (size_t)cj * D2) + lane);
            fma2(acc, pack2(wj, wj), v);
        }
    }

    float2 a = unpack2(acc);
    float p0 = di * a.x + __ldg(b2 + lane * 2);
    float p1 = di * a.y + __ldg(b2 + lane * 2 + 1);

    float m = fmaxf(p0, p1);
#pragma unroll
    for (int o = 16; o; o >>= 1) m = fmaxf(m, __shfl_xor_sync(~0u, m, o));
    float esum = expf(p0 - m) + expf(p1 - m);
#pragma unroll
    for (int o = 16; o; o >>= 1) esum += __shfl_xor_sync(~0u, esum, o);
    float lse = m + logf(esum);

    float2 res = make_float2(p0 - lse, p1 - lse);
    ((float2*)(out + (size_t)node * D2))[lane] = res;
}

// ---------------- launch ----------------
extern "C" void kernel_launch(void* const* d_in, const int* in_sizes, int n_in,
                              void* d_out, int out_size) {
    const float* x    = (const float*)d_in[0];
    const int*   esrc = (const int*)d_in[1];
    const int*   edst = (const int*)d_in[2];
    const float* W1   = (const float*)d_in[3];
    const float* b1   = (const float*)d_in[4];
    const float* W2   = (const float*)d_in[5];
    const float* b2   = (const float*)d_in[6];
    float* out = (float*)d_out;

    int n = in_sizes[0] / D1;   // 100000
    int e = in_sizes[1];        // 3200000

    float *bufA, *bufB, *bufG, *dinv1, *dinv2, *w1, *w2;
    int *colidx;
    cudaGetSymbolAddress((void**)&bufA, g_bufA);
    cudaGetSymbolAddress((void**)&bufB, g_bufB);
    cudaGetSymbolAddress((void**)&bufG, g_bufG);
    cudaGetSymbolAddress((void**)&dinv1, g_dinv1);
    cudaGetSymbolAddress((void**)&dinv2, g_dinv2);
    cudaGetSymbolAddress((void**)&colidx, g_col);
    cudaGetSymbolAddress((void**)&w1, g_w1);
    cudaGetSymbolAddress((void**)&w2, g_w2);

    int nb = (n + 255) / 256;
    int eb = (e + 255) / 256;
    int nparts = nb;            // 391 <= NPARTMAX
    int hopBlocks = (n * 32 + 255) / 256;

    // CSR build + normalization
    k_clear<<<nb, 256>>>(n);
    k_count<<<eb, 256>>>(edst, e);
    k_dinv<<<nb, 256>>>(n);
    k_reduce<<<nparts, 256>>>(n);
    k_scanpart<<<1, NPARTMAX>>>(nparts, n);
    k_scatter<<<nparts, 256>>>(n);
    k_fill<<<eb, 256>>>(esrc, edst, e);

    // conv1: two hops (coeff 1, exp(-1)), then Linear+SELU
    k_hop256<<<hopBlocks, 256>>>(x,    bufA, colidx, w1, dinv1, 1.0f, n);
    k_hop256<<<hopBlocks, 256>>>(bufA, bufB, colidx, w1, dinv1, 0.36787944117144233f, n);

    dim3 g1((n + 127) / 128, 4);
    k_gemm<true><<<g1, 256>>>(bufB, W1, b1, bufA, n, 256);

    // conv2 reordered: g = h @ W2 first (64-dim), then 1 hop w/ self loops + b2 + log_softmax
    dim3 g2((n + 127) / 128, 1);
    k_gemm<false><<<g2, 256>>>(bufA, W2, nullptr, bufG, n, 64);

    k_out<<<hopBlocks, 256>>>(bufG, dinv2, colidx, w2, b2, out, n);
}

// round 3
// speedup vs baseline: 1.1229x; 1.1229x over previous
#include <cuda_runtime.h>
#include <math.h>

#define NN 100000
#define NE 3200000
#define D1 256
#define D2 64
#define NPARTMAX 512

// ---------------- static device scratch ----------------
__device__ int   g_cnt[NN];
__device__ int   g_woff[NN];
__device__ int   g_rowptr[NN + 1];
__device__ int   g_part[NPARTMAX];
__device__ int   g_col[NE];
__device__ float g_dinv1[NN];
__device__ float g_dinv2[NN];
__device__ float g_bufA[(size_t)NN * D1];
__device__ float g_bufB[(size_t)NN * D1];
__device__ float g_bufG[(size_t)NN * D2];

// ---------------- small helpers ----------------
__device__ __forceinline__ void fma4(float4& a, float w, const float4& v) {
    a.x = fmaf(w, v.x, a.x);
    a.y = fmaf(w, v.y, a.y);
    a.z = fmaf(w, v.z, a.z);
    a.w = fmaf(w, v.w, a.w);
}

__device__ __forceinline__ float selu_f(float x) {
    const float sc = 1.0507009873554804934f;
    const float al = 1.6732632423543772848f;
    return x > 0.f ? sc * x : sc * al * expm1f(x);
}

// ---------------- graph preprocessing (5 launches before hop1) ----------------
__global__ void k_clear(int n) {
    int i = blockIdx.x * blockDim.x + threadIdx.x;
    if (i < n) g_cnt[i] = 0;
}

__global__ void k_count(const int* __restrict__ dst, int e) {
    int i = blockIdx.x * blockDim.x + threadIdx.x;
    if (i < e) atomicAdd(&g_cnt[dst[i]], 1);
}

// fused: per-node dinv + woff clear + per-block reduce of counts -> g_part
__global__ void k_dinvreduce(int n) {
    __shared__ int s[256];
    int t = threadIdx.x;
    int i = blockIdx.x * 256 + t;
    int d = 0;
    if (i < n) {
        d = g_cnt[i];
        g_woff[i] = 0;
        g_dinv1[i] = d > 0 ? rsqrtf((float)d) : 0.f;
        g_dinv2[i] = rsqrtf((float)(d + 1));
    }
    s[t] = d;
    __syncthreads();
    for (int o = 128; o; o >>= 1) { if (t < o) s[t] += s[t + o]; __syncthreads(); }
    if (t == 0) g_part[blockIdx.x] = s[0];
}

// fused: each block computes its partial-prefix itself, then block-scans counts
__global__ void k_scatter(int nparts, int n) {
    __shared__ int spart[NPARTMAX];
    __shared__ int s[256];
    __shared__ int red[8];
    int t = threadIdx.x;
    int b = blockIdx.x;

    for (int i = t; i < nparts; i += 256) spart[i] = g_part[i];
    __syncthreads();

    // prefix of partials [0, b): strided sum + block reduce
    int loc = 0;
    for (int i = t; i < b; i += 256) loc += spart[i];
#pragma unroll
    for (int o = 16; o; o >>= 1) loc += __shfl_xor_sync(~0u, loc, o);
    if ((t & 31) == 0) red[t >> 5] = loc;
    __syncthreads();
    int blockpre = red[0] + red[1] + red[2] + red[3] + red[4] + red[5] + red[6] + red[7];

    // block 0 also writes total edge count
    if (b == 0 && t == 0) {
        int tot = 0;
        for (int i = 0; i < nparts; i++) tot += spart[i];
        g_rowptr[n] = tot;
    }

    // inclusive scan of this block's 256 counts
    int i = b * 256 + t;
    int v = (i < n) ? g_cnt[i] : 0;
    s[t] = v;
    __syncthreads();
    for (int o = 1; o < 256; o <<= 1) {
        int x = (t >= o) ? s[t - o] : 0;
        __syncthreads();
        s[t] += x;
        __syncthreads();
    }
    if (i < n) g_rowptr[i] = blockpre + s[t] - v;
}

__global__ void k_fill(const int* __restrict__ src, const int* __restrict__ dst, int e) {
    int i = blockIdx.x * blockDim.x + threadIdx.x;
    if (i < e) {
        int d = dst[i];
        int p = g_rowptr[d] + atomicAdd(&g_woff[d], 1);
        g_col[p] = src[i];
    }
}

// ---------------- 256-dim propagation hop ----------------
__global__ void __launch_bounds__(256) k_hop256(
    const float* __restrict__ xin, float* __restrict__ xout,
    const float* __restrict__ dinv, const int* __restrict__ rowptr,
    const int* __restrict__ colidx, float coeff, int n)
{
    int node = (blockIdx.x * blockDim.x + threadIdx.x) >> 5;
    int lane = threadIdx.x & 31;
    if (node >= n) return;
    int beg = rowptr[node], end = rowptr[node + 1];

    float4 a0 = make_float4(0.f, 0.f, 0.f, 0.f);
    float4 a1 = make_float4(0.f, 0.f, 0.f, 0.f);

    for (int e0 = beg; e0 < end; e0 += 32) {
        int idx = e0 + lane;
        int c = 0; float w = 0.f;
        if (idx < end) { c = colidx[idx]; w = __ldg(dinv + c); }
        int cnt = min(32, end - e0);
        int j = 0;
        for (; j + 4 <= cnt; j += 4) {
            int   c0 = __shfl_sync(~0u, c, j + 0); float w0 = __shfl_sync(~0u, w, j + 0);
            int   c1 = __shfl_sync(~0u, c, j + 1); float w1 = __shfl_sync(~0u, w, j + 1);
            int   c2 = __shfl_sync(~0u, c, j + 2); float w2 = __shfl_sync(~0u, w, j + 2);
            int   c3 = __shfl_sync(~0u, c, j + 3); float w3 = __shfl_sync(~0u, w, j + 3);
            const float4* r0 = (const float4*)(xin + (size_t)c0 * D1);
            const float4* r1 = (const float4*)(xin + (size_t)c1 * D1);
            const float4* r2 = (const float4*)(xin + (size_t)c2 * D1);
            const float4* r3 = (const float4*)(xin + (size_t)c3 * D1);
            float4 v00 = __ldg(r0 + lane), v01 = __ldg(r0 + lane + 32);
            float4 v10 = __ldg(r1 + lane), v11 = __ldg(r1 + lane + 32);
            float4 v20 = __ldg(r2 + lane), v21 = __ldg(r2 + lane + 32);
            float4 v30 = __ldg(r3 + lane), v31 = __ldg(r3 + lane + 32);
            fma4(a0, w0, v00); fma4(a1, w0, v01);
            fma4(a0, w1, v10); fma4(a1, w1, v11);
            fma4(a0, w2, v20); fma4(a1, w2, v21);
            fma4(a0, w3, v30); fma4(a1, w3, v31);
        }
        for (; j < cnt; j++) {
            int   cj = __shfl_sync(~0u, c, j);
            float wj = __shfl_sync(~0u, w, j);
            const float4* r = (const float4*)(xin + (size_t)cj * D1);
            float4 v0 = __ldg(r + lane), v1 = __ldg(r + lane + 32);
            fma4(a0, wj, v0); fma4(a1, wj, v1);
        }
    }

    float s = coeff * __ldg(dinv + node);
    float4 o0 = make_float4(s * a0.x, s * a0.y, s * a0.z, s * a0.w);
    float4 o1 = make_float4(s * a1.x, s * a1.y, s * a1.z, s * a1.w);
    float4* orow = (float4*)(xout + (size_t)node * D1);
    orow[lane]      = o0;
    orow[lane + 32] = o1;
}

// ---------------- fp32 tiled GEMM: C[M,N] = act(A[M,256] @ B[256,N] (+bias)) ----------------
template<bool DO_SELU>
__global__ void __launch_bounds__(256) k_gemm(
    const float* __restrict__ A, const float* __restrict__ B,
    const float* __restrict__ bias, float* __restrict__ C, int M, int N)
{
    const int BM = 128, BN = 64, BK = 16;
    __shared__ float As[BK][BM];
    __shared__ float Bs[BK][BN];

    int tid  = threadIdx.x;
    int trow = tid & 15;
    int tcol = tid >> 4;
    int blockM = blockIdx.x * BM;
    int blockN = blockIdx.y * BN;

    float acc[8][4];
#pragma unroll
    for (int i = 0; i < 8; i++)
#pragma unroll
        for (int j = 0; j < 4; j++) acc[i][j] = 0.f;

    for (int k0 = 0; k0 < 256; k0 += BK) {
#pragma unroll
        for (int l = 0; l < 2; l++) {
            int pos = tid * 2 + l;
            int r  = pos >> 2;
            int cv = pos & 3;
            int gr = blockM + r;
            if (gr > M - 1) gr = M - 1;
            float4 v = *(const float4*)(A + (size_t)gr * 256 + k0 + cv * 4);
            As[cv * 4 + 0][r] = v.x;
            As[cv * 4 + 1][r] = v.y;
            As[cv * 4 + 2][r] = v.z;
            As[cv * 4 + 3][r] = v.w;
        }
        {
            int r = tid >> 4;
            int cb = (tid & 15) * 4;
            float4 v = *(const float4*)(B + (size_t)(k0 + r) * N + blockN + cb);
            *(float4*)&Bs[r][cb] = v;
        }
        __syncthreads();
#pragma unroll
        for (int k = 0; k < BK; k++) {
            float a[8], b[4];
#pragma unroll
            for (int i = 0; i < 8; i++) a[i] = As[k][trow * 8 + i];
#pragma unroll
            for (int j = 0; j < 4; j++) b[j] = Bs[k][tcol * 4 + j];
#pragma unroll
            for (int i = 0; i < 8; i++)
#pragma unroll
                for (int j = 0; j < 4; j++) acc[i][j] = fmaf(a[i], b[j], acc[i][j]);
        }
        __syncthreads();
    }

    float4 bias4 = make_float4(0.f, 0.f, 0.f, 0.f);
    if (DO_SELU) bias4 = *(const float4*)(bias + blockN + tcol * 4);

#pragma unroll
    for (int i = 0; i < 8; i++) {
        int gr = blockM + trow * 8 + i;
        if (gr < M) {
            float4 v;
            if (DO_SELU) {
                v.x = selu_f(acc[i][0] + bias4.x);
                v.y = selu_f(acc[i][1] + bias4.y);
                v.z = selu_f(acc[i][2] + bias4.z);
                v.w = selu_f(acc[i][3] + bias4.w);
            } else {
                v.x = acc[i][0]; v.y = acc[i][1]; v.z = acc[i][2]; v.w = acc[i][3];
            }
            *(float4*)(C + (size_t)gr * N + blockN + tcol * 4) = v;
        }
    }
}

// ---------------- final hop (D=64, self loops) + bias + log_softmax ----------------
__global__ void __launch_bounds__(256) k_out(
    const float* __restrict__ g, const float* __restrict__ dinv2,
    const int* __restrict__ rowptr, const int* __restrict__ colidx,
    const float* __restrict__ b2, float* __restrict__ out, int n)
{
    int node = (blockIdx.x * blockDim.x + threadIdx.x) >> 5;
    int lane = threadIdx.x & 31;
    if (node >= n) return;
    int beg = rowptr[node], end = rowptr[node + 1];

    float di = __ldg(dinv2 + node);
    float2 sv = __ldg((const float2*)(g + (size_t)node * D2) + lane);
    float ax = di * sv.x;
    float ay = di * sv.y;

    for (int e0 = beg; e0 < end; e0 += 32) {
        int idx = e0 + lane;
        int c = 0; float w = 0.f;
        if (idx < end) { c = colidx[idx]; w = __ldg(dinv2 + c); }
        int cnt = min(32, end - e0);
        int j = 0;
        for (; j + 4 <= cnt; j += 4) {
            int   c0 = __shfl_sync(~0u, c, j + 0); float w0 = __shfl_sync(~0u, w, j + 0);
            int   c1 = __shfl_sync(~0u, c, j + 1); float w1 = __shfl_sync(~0u, w, j + 1);
            int   c2 = __shfl_sync(~0u, c, j + 2); float w2 = __shfl_sync(~0u, w, j + 2);
            int   c3 = __shfl_sync(~0u, c, j + 3); float w3 = __shfl_sync(~0u, w, j + 3);
            float2 v0 = __ldg((const float2*)(g + (size_t)c0 * D2) + lane);
            float2 v1 = __ldg((const float2*)(g + (size_t)c1 * D2) + lane);
            float2 v2 = __ldg((const float2*)(g + (size_t)c2 * D2) + lane);
            float2 v3 = __ldg((const float2*)(g + (size_t)c3 * D2) + lane);
            ax = fmaf(w0, v0.x, ax); ay = fmaf(w0, v0.y, ay);
            ax = fmaf(w1, v1.x, ax); ay = fmaf(w1, v1.y, ay);
            ax = fmaf(w2, v2.x, ax); ay = fmaf(w2, v2.y, ay);
            ax = fmaf(w3, v3.x, ax); ay = fmaf(w3, v3.y, ay);
        }
        for (; j < cnt; j++) {
            int   cj = __shfl_sync(~0u, c, j);
            float wj = __shfl_sync(~0u, w, j);
            float2 v = __ldg((const float2*)(g + (size_t)cj * D2) + lane);
            ax = fmaf(wj, v.x, ax); ay = fmaf(wj, v.y, ay);
        }
    }

    float p0 = di * ax + __ldg(b2 + lane * 2);
    float p1 = di * ay + __ldg(b2 + lane * 2 + 1);

    float m = fmaxf(p0, p1);
#pragma unroll
    for (int o = 16; o; o >>= 1) m = fmaxf(m, __shfl_xor_sync(~0u, m, o));
    float esum = expf(p0 - m) + expf(p1 - m);
#pragma unroll
    for (int o = 16; o; o >>= 1) esum += __shfl_xor_sync(~0u, esum, o);
    float lse = m + logf(esum);

    float2 res = make_float2(p0 - lse, p1 - lse);
    ((float2*)(out + (size_t)node * D2))[lane] = res;
}

// ---------------- launch ----------------
extern "C" void kernel_launch(void* const* d_in, const int* in_sizes, int n_in,
                              void* d_out, int out_size) {
    const float* x    = (const float*)d_in[0];
    const int*   esrc = (const int*)d_in[1];
    const int*   edst = (const int*)d_in[2];
    const float* W1   = (const float*)d_in[3];
    const float* b1   = (const float*)d_in[4];
    const float* W2   = (const float*)d_in[5];
    const float* b2   = (const float*)d_in[6];
    float* out = (float*)d_out;

    int n = in_sizes[0] / D1;   // 100000
    int e = in_sizes[1];        // 3200000

    float *bufA, *bufB, *bufG, *dinv1, *dinv2;
    int *rowptr, *colidx;
    cudaGetSymbolAddress((void**)&bufA, g_bufA);
    cudaGetSymbolAddress((void**)&bufB, g_bufB);
    cudaGetSymbolAddress((void**)&bufG, g_bufG);
    cudaGetSymbolAddress((void**)&dinv1, g_dinv1);
    cudaGetSymbolAddress((void**)&dinv2, g_dinv2);
    cudaGetSymbolAddress((void**)&rowptr, g_rowptr);
    cudaGetSymbolAddress((void**)&colidx, g_col);

    int nb = (n + 255) / 256;          // 391
    int eb = (e + 255) / 256;
    int hopBlocks = (n * 32 + 255) / 256;

    // CSR build: 5 launches so hop1 is launch index 5 (ncu -s 5 profiles it)
    k_clear<<<nb, 256>>>(n);                    // 0
    k_count<<<eb, 256>>>(edst, e);              // 1
    k_dinvreduce<<<nb, 256>>>(n);               // 2
    k_scatter<<<nb, 256>>>(nb, n);              // 3
    k_fill<<<eb, 256>>>(esrc, edst, e);         // 4

    // conv1: two hops, then Linear+SELU
    k_hop256<<<hopBlocks, 256>>>(x,    bufA, dinv1, rowptr, colidx, 1.0f, n);               // 5
    k_hop256<<<hopBlocks, 256>>>(bufA, bufB, dinv1, rowptr, colidx, 0.36787944117144233f, n); // 6

    dim3 g1((n + 127) / 128, 4);
    k_gemm<true><<<g1, 256>>>(bufB, W1, b1, bufA, n, 256);                                  // 7

    dim3 g2((n + 127) / 128, 1);
    k_gemm<false><<<g2, 256>>>(bufA, W2, nullptr, bufG, n, 64);                             // 8

    k_out<<<hopBlocks, 256>>>(bufG, dinv2, rowptr, colidx, b2, out, n);                     // 9
}

// round 4
// speedup vs baseline: 1.8285x; 1.6284x over previous
#include <cuda_runtime.h>
#include <cuda_fp16.h>
#include <mma.h>
#include <math.h>

using namespace nvcuda;

#define NN 100000
#define NNP 100096           // padded to multiple of 128 for wmma tiles
#define NE 3200000
#define D1 256
#define D2 64
#define NPARTMAX 512

// ---------------- static device scratch ----------------
__device__ int    g_cnt[NN];
__device__ int    g_woff[NN];
__device__ int    g_rowptr[NN + 1];
__device__ int    g_part[NPARTMAX];
__device__ int    g_col[NE];
__device__ float  g_dinv1[NN];
__device__ float  g_dinv2[NN];
__device__ __half g_xh[(size_t)NN * D1];     // x in half
__device__ __half g_h1[(size_t)NN * D1];     // hop1 out
__device__ __half g_h2[(size_t)NNP * D1];    // hop2 out (padded; pad rows stay 0)
__device__ __half g_w1h[D1 * D1];            // W1 in half
__device__ float  g_raw[(size_t)NNP * D1];   // gemm1 raw out
__device__ float  g_act[(size_t)NN * D1];    // selu(raw+b1)
__device__ float  g_gf[(size_t)NN * D2];     // gemm2 out fp32
__device__ __half g_gh[(size_t)NN * D2];     // gemm2 out half (gather source)

// ---------------- helpers ----------------
__device__ __forceinline__ float selu_f(float x) {
    const float sc = 1.0507009873554804934f;
    const float al = 1.6732632423543772848f;
    return x > 0.f ? sc * x : sc * al * expm1f(x);
}

__device__ __forceinline__ void acch8(float2 a[4], float w, float4 v) {
    __half2* hp = (__half2*)&v;
#pragma unroll
    for (int q = 0; q < 4; q++) {
        float2 f = __half22float2(hp[q]);
        a[q].x = fmaf(w, f.x, a[q].x);
        a[q].y = fmaf(w, f.y, a[q].y);
    }
}

// ---------------- preprocessing ----------------
// convert x -> half, clear cnt/woff
__global__ void k_prep(const float* __restrict__ x, int n) {
    int total = n * (D1 / 4);   // float4 groups
    for (int i = blockIdx.x * blockDim.x + threadIdx.x; i < total; i += gridDim.x * blockDim.x) {
        float4 v = __ldg(((const float4*)x) + i);
        __half2 h0 = __floats2half2_rn(v.x, v.y);
        __half2 h1 = __floats2half2_rn(v.z, v.w);
        uint2 u = make_uint2(*(unsigned*)&h0, *(unsigned*)&h1);
        ((uint2*)g_xh)[i] = u;
        if (i < n) { g_cnt[i] = 0; g_woff[i] = 0; }
    }
}

__global__ void k_prepw(const float* __restrict__ W1) {
    int i = blockIdx.x * blockDim.x + threadIdx.x;   // 16384 threads, 4 each
    float4 v = __ldg(((const float4*)W1) + i);
    __half2 h0 = __floats2half2_rn(v.x, v.y);
    __half2 h1 = __floats2half2_rn(v.z, v.w);
    uint2 u = make_uint2(*(unsigned*)&h0, *(unsigned*)&h1);
    ((uint2*)g_w1h)[i] = u;
}

__global__ void k_count(const int* __restrict__ dst, int e) {
    int i = blockIdx.x * blockDim.x + threadIdx.x;
    if (i < e) atomicAdd(&g_cnt[dst[i]], 1);
}

__global__ void k_dinvreduce(int n) {
    __shared__ int s[256];
    int t = threadIdx.x;
    int i = blockIdx.x * 256 + t;
    int d = 0;
    if (i < n) {
        d = g_cnt[i];
        g_dinv1[i] = d > 0 ? rsqrtf((float)d) : 0.f;
        g_dinv2[i] = rsqrtf((float)(d + 1));
    }
    s[t] = d;
    __syncthreads();
    for (int o = 128; o; o >>= 1) { if (t < o) s[t] += s[t + o]; __syncthreads(); }
    if (t == 0) g_part[blockIdx.x] = s[0];
}

__global__ void k_scatter(int nparts, int n) {
    __shared__ int spart[NPARTMAX];
    __shared__ int s[256];
    __shared__ int red[8];
    int t = threadIdx.x;
    int b = blockIdx.x;

    for (int i = t; i < nparts; i += 256) spart[i] = g_part[i];
    __syncthreads();

    int loc = 0;
    for (int i = t; i < b; i += 256) loc += spart[i];
#pragma unroll
    for (int o = 16; o; o >>= 1) loc += __shfl_xor_sync(~0u, loc, o);
    if ((t & 31) == 0) red[t >> 5] = loc;
    __syncthreads();
    int blockpre = red[0] + red[1] + red[2] + red[3] + red[4] + red[5] + red[6] + red[7];

    if (b == 0 && t == 0) {
        int tot = 0;
        for (int i = 0; i < nparts; i++) tot += spart[i];
        g_rowptr[n] = tot;
    }

    int i = b * 256 + t;
    int v = (i < n) ? g_cnt[i] : 0;
    s[t] = v;
    __syncthreads();
    for (int o = 1; o < 256; o <<= 1) {
        int x = (t >= o) ? s[t - o] : 0;
        __syncthreads();
        s[t] += x;
        __syncthreads();
    }
    if (i < n) g_rowptr[i] = blockpre + s[t] - v;
}

__global__ void k_fill(const int* __restrict__ src, const int* __restrict__ dst, int e) {
    int i = blockIdx.x * blockDim.x + threadIdx.x;
    if (i < e) {
        int d = dst[i];
        int p = g_rowptr[d] + atomicAdd(&g_woff[d], 1);
        g_col[p] = src[i];
    }
}

// ---------------- 256-dim half->half propagation hop ----------------
__global__ void __launch_bounds__(256) k_hop_h(
    const __half* __restrict__ xin, __half* __restrict__ xout,
    const float* __restrict__ dinv, const int* __restrict__ rowptr,
    const int* __restrict__ colidx, float coeff, int n)
{
    int node = (blockIdx.x * blockDim.x + threadIdx.x) >> 5;
    int lane = threadIdx.x & 31;
    if (node >= n) return;
    int beg = rowptr[node], end = rowptr[node + 1];

    float2 a[4];
#pragma unroll
    for (int q = 0; q < 4; q++) a[q] = make_float2(0.f, 0.f);

    for (int e0 = beg; e0 < end; e0 += 32) {
        int idx = e0 + lane;
        int c = 0; float w = 0.f;
        if (idx < end) { c = colidx[idx]; w = __ldg(dinv + c); }
        int cnt = min(32, end - e0);
        int j = 0;
        for (; j + 4 <= cnt; j += 4) {
            int   c0 = __shfl_sync(~0u, c, j + 0); float w0 = __shfl_sync(~0u, w, j + 0);
            int   c1 = __shfl_sync(~0u, c, j + 1); float w1 = __shfl_sync(~0u, w, j + 1);
            int   c2 = __shfl_sync(~0u, c, j + 2); float w2 = __shfl_sync(~0u, w, j + 2);
            int   c3 = __shfl_sync(~0u, c, j + 3); float w3 = __shfl_sync(~0u, w, j + 3);
            float4 v0 = __ldg(((const float4*)(xin + (size_t)c0 * D1)) + lane);
            float4 v1 = __ldg(((const float4*)(xin + (size_t)c1 * D1)) + lane);
            float4 v2 = __ldg(((const float4*)(xin + (size_t)c2 * D1)) + lane);
            float4 v3 = __ldg(((const float4*)(xin + (size_t)c3 * D1)) + lane);
            acch8(a, w0, v0);
            acch8(a, w1, v1);
            acch8(a, w2, v2);
            acch8(a, w3, v3);
        }
        for (; j < cnt; j++) {
            int   cj = __shfl_sync(~0u, c, j);
            float wj = __shfl_sync(~0u, w, j);
            float4 v = __ldg(((const float4*)(xin + (size_t)cj * D1)) + lane);
            acch8(a, wj, v);
        }
    }

    float s = coeff * __ldg(dinv + node);
    __half2 o0 = __floats2half2_rn(s * a[0].x, s * a[0].y);
    __half2 o1 = __floats2half2_rn(s * a[1].x, s * a[1].y);
    __half2 o2 = __floats2half2_rn(s * a[2].x, s * a[2].y);
    __half2 o3 = __floats2half2_rn(s * a[3].x, s * a[3].y);
    uint4 u;
    u.x = *(unsigned*)&o0; u.y = *(unsigned*)&o1;
    u.z = *(unsigned*)&o2; u.w = *(unsigned*)&o3;
    ((uint4*)(xout + (size_t)node * D1))[lane] = u;
}

// ---------------- wmma GEMM1: raw = A[NNP,256](half) @ W1h[256,256](half) ----------------
__global__ void __launch_bounds__(256) k_gemm1_wmma(
    const __half* __restrict__ A, const __half* __restrict__ B, float* __restrict__ C)
{
    int warp = threadIdx.x >> 5;
    int wm = warp >> 1;               // 0..3
    int wn = warp & 1;                // 0..1
    int bm = blockIdx.x * 128;
    int bn = blockIdx.y * 128;
    int rowbase = bm + wm * 32;       // warp tile: 32 x 64
    int colbase = bn + wn * 64;

    wmma::fragment<wmma::accumulator, 16, 16, 16, float> acc[2][4];
#pragma unroll
    for (int r = 0; r < 2; r++)
#pragma unroll
        for (int c = 0; c < 4; c++) wmma::fill_fragment(acc[r][c], 0.f);

    for (int k = 0; k < D1; k += 16) {
        wmma::fragment<wmma::matrix_a, 16, 16, 16, __half, wmma::row_major> af[2];
        wmma::fragment<wmma::matrix_b, 16, 16, 16, __half, wmma::row_major> bf[4];
#pragma unroll
        for (int r = 0; r < 2; r++)
            wmma::load_matrix_sync(af[r], A + (size_t)(rowbase + r * 16) * D1 + k, D1);
#pragma unroll
        for (int c = 0; c < 4; c++)
            wmma::load_matrix_sync(bf[c], B + (size_t)k * D1 + colbase + c * 16, D1);
#pragma unroll
        for (int r = 0; r < 2; r++)
#pragma unroll
            for (int c = 0; c < 4; c++)
                wmma::mma_sync(acc[r][c], af[r], bf[c], acc[r][c]);
    }

#pragma unroll
    for (int r = 0; r < 2; r++)
#pragma unroll
        for (int c = 0; c < 4; c++)
            wmma::store_matrix_sync(C + (size_t)(rowbase + r * 16) * D1 + colbase + c * 16,
                                    acc[r][c], D1, wmma::mem_row_major);
}

// ---------------- epilogue: act = selu(raw + b1) ----------------
__global__ void k_epi(const float* __restrict__ b1, int n) {
    int total = n * (D1 / 4);
    for (int i = blockIdx.x * blockDim.x + threadIdx.x; i < total; i += gridDim.x * blockDim.x) {
        float4 v = __ldg(((const float4*)g_raw) + i);
        float4 b = __ldg(((const float4*)b1) + (i & 63));
        float4 o;
        o.x = selu_f(v.x + b.x);
        o.y = selu_f(v.y + b.y);
        o.z = selu_f(v.z + b.z);
        o.w = selu_f(v.w + b.w);
        ((float4*)g_act)[i] = o;
    }
}

// ---------------- fp32 SIMT GEMM (used for GEMM2): C = A[M,256] @ B[256,N] ----------------
__global__ void __launch_bounds__(256) k_gemm2(
    const float* __restrict__ A, const float* __restrict__ B,
    float* __restrict__ C, int M, int N)
{
    const int BM = 128, BK = 16;
    __shared__ float As[BK][BM];
    __shared__ float Bs[BK][64];

    int tid  = threadIdx.x;
    int trow = tid & 15;
    int tcol = tid >> 4;
    int blockM = blockIdx.x * BM;

    float acc[8][4];
#pragma unroll
    for (int i = 0; i < 8; i++)
#pragma unroll
        for (int j = 0; j < 4; j++) acc[i][j] = 0.f;

    for (int k0 = 0; k0 < 256; k0 += BK) {
#pragma unroll
        for (int l = 0; l < 2; l++) {
            int pos = tid * 2 + l;
            int r  = pos >> 2;
            int cv = pos & 3;
            int gr = blockM + r;
            if (gr > M - 1) gr = M - 1;
            float4 v = *(const float4*)(A + (size_t)gr * 256 + k0 + cv * 4);
            As[cv * 4 + 0][r] = v.x;
            As[cv * 4 + 1][r] = v.y;
            As[cv * 4 + 2][r] = v.z;
            As[cv * 4 + 3][r] = v.w;
        }
        {
            int r = tid >> 4;
            int cb = (tid & 15) * 4;
            float4 v = *(const float4*)(B + (size_t)(k0 + r) * N + cb);
            *(float4*)&Bs[r][cb] = v;
        }
        __syncthreads();
#pragma unroll
        for (int k = 0; k < BK; k++) {
            float a[8], b[4];
#pragma unroll
            for (int i = 0; i < 8; i++) a[i] = As[k][trow * 8 + i];
#pragma unroll
            for (int j = 0; j < 4; j++) b[j] = Bs[k][tcol * 4 + j];
#pragma unroll
            for (int i = 0; i < 8; i++)
#pragma unroll
                for (int j = 0; j < 4; j++) acc[i][j] = fmaf(a[i], b[j], acc[i][j]);
        }
        __syncthreads();
    }

#pragma unroll
    for (int i = 0; i < 8; i++) {
        int gr = blockM + trow * 8 + i;
        if (gr < M) {
            float4 v = make_float4(acc[i][0], acc[i][1], acc[i][2], acc[i][3]);
            *(float4*)(C + (size_t)gr * N + tcol * 4) = v;
        }
    }
}

// ---------------- convert gemm2 out to half ----------------
__global__ void k_f2h(int n) {
    int total = n * (D2 / 4);
    for (int i = blockIdx.x * blockDim.x + threadIdx.x; i < total; i += gridDim.x * blockDim.x) {
        float4 v = __ldg(((const float4*)g_gf) + i);
        __half2 h0 = __floats2half2_rn(v.x, v.y);
        __half2 h1 = __floats2half2_rn(v.z, v.w);
        uint2 u = make_uint2(*(unsigned*)&h0, *(unsigned*)&h1);
        ((uint2*)g_gh)[i] = u;
    }
}

// ---------------- final hop (D=64, self loops, half gather) + bias + log_softmax ----------------
__global__ void __launch_bounds__(256) k_out(
    const float* __restrict__ dinv2,
    const int* __restrict__ rowptr, const int* __restrict__ colidx,
    const float* __restrict__ b2, float* __restrict__ out, int n)
{
    int node = (blockIdx.x * blockDim.x + threadIdx.x) >> 5;
    int lane = threadIdx.x & 31;
    if (node >= n) return;
    int beg = rowptr[node], end = rowptr[node + 1];

    float di = __ldg(dinv2 + node);
    float2 sv = __half22float2(__ldg(((const __half2*)(g_gh + (size_t)node * D2)) + lane));
    float ax = di * sv.x;
    float ay = di * sv.y;

    for (int e0 = beg; e0 < end; e0 += 32) {
        int idx = e0 + lane;
        int c = 0; float w = 0.f;
        if (idx < end) { c = colidx[idx]; w = __ldg(dinv2 + c); }
        int cnt = min(32, end - e0);
        int j = 0;
        for (; j + 4 <= cnt; j += 4) {
            int   c0 = __shfl_sync(~0u, c, j + 0); float w0 = __shfl_sync(~0u, w, j + 0);
            int   c1 = __shfl_sync(~0u, c, j + 1); float w1 = __shfl_sync(~0u, w, j + 1);
            int   c2 = __shfl_sync(~0u, c, j + 2); float w2 = __shfl_sync(~0u, w, j + 2);
            int   c3 = __shfl_sync(~0u, c, j + 3); float w3 = __shfl_sync(~0u, w, j + 3);
            float2 v0 = __half22float2(__ldg(((const __half2*)(g_gh + (size_t)c0 * D2)) + lane));
            float2 v1 = __half22float2(__ldg(((const __half2*)(g_gh + (size_t)c1 * D2)) + lane));
            float2 v2 = __half22float2(__ldg(((const __half2*)(g_gh + (size_t)c2 * D2)) + lane));
            float2 v3 = __half22float2(__ldg(((const __half2*)(g_gh + (size_t)c3 * D2)) + lane));
            ax = fmaf(w0, v0.x, ax); ay = fmaf(w0, v0.y, ay);
            ax = fmaf(w1, v1.x, ax); ay = fmaf(w1, v1.y, ay);
            ax = fmaf(w2, v2.x, ax); ay = fmaf(w2, v2.y, ay);
            ax = fmaf(w3, v3.x, ax); ay = fmaf(w3, v3.y, ay);
        }
        for (; j < cnt; j++) {
            int   cj = __shfl_sync(~0u, c, j);
            float wj = __shfl_sync(~0u, w, j);
            float2 v = __half22float2(__ldg(((const __half2*)(g_gh + (size_t)cj * D2)) + lane));
            ax = fmaf(wj, v.x, ax); ay = fmaf(wj, v.y, ay);
        }
    }

    float p0 = di * ax + __ldg(b2 + lane * 2);
    float p1 = di * ay + __ldg(b2 + lane * 2 + 1);

    float m = fmaxf(p0, p1);
#pragma unroll
    for (int o = 16; o; o >>= 1) m = fmaxf(m, __shfl_xor_sync(~0u, m, o));
    float esum = expf(p0 - m) + expf(p1 - m);
#pragma unroll
    for (int o = 16; o; o >>= 1) esum += __shfl_xor_sync(~0u, esum, o);
    float lse = m + logf(esum);

    float2 res = make_float2(p0 - lse, p1 - lse);
    ((float2*)(out + (size_t)node * D2))[lane] = res;
}

// ---------------- launch ----------------
extern "C" void kernel_launch(void* const* d_in, const int* in_sizes, int n_in,
                              void* d_out, int out_size) {
    const float* x    = (const float*)d_in[0];
    const int*   esrc = (const int*)d_in[1];
    const int*   edst = (const int*)d_in[2];
    const float* W1   = (const float*)d_in[3];
    const float* b1   = (const float*)d_in[4];
    const float* W2   = (const float*)d_in[5];
    const float* b2   = (const float*)d_in[6];
    float* out = (float*)d_out;

    int n = in_sizes[0] / D1;   // 100000
    int e = in_sizes[1];        // 3200000

    __half *xh, *h1, *h2, *w1h;
    float *dinv1, *dinv2, *raw, *act, *gf;
    int *rowptr, *colidx;
    cudaGetSymbolAddress((void**)&xh, g_xh);
    cudaGetSymbolAddress((void**)&h1, g_h1);
    cudaGetSymbolAddress((void**)&h2, g_h2);
    cudaGetSymbolAddress((void**)&w1h, g_w1h);
    cudaGetSymbolAddress((void**)&raw, g_raw);
    cudaGetSymbolAddress((void**)&act, g_act);
    cudaGetSymbolAddress((void**)&gf, g_gf);
    cudaGetSymbolAddress((void**)&dinv1, g_dinv1);
    cudaGetSymbolAddress((void**)&dinv2, g_dinv2);
    cudaGetSymbolAddress((void**)&rowptr, g_rowptr);
    cudaGetSymbolAddress((void**)&colidx, g_col);

    int nb = (n + 255) / 256;          // 391
    int eb = (e + 255) / 256;
    int hopBlocks = (n * 32 + 255) / 256;

    // preprocessing
    k_prep<<<2048, 256>>>(x, n);
    k_prepw<<<64, 256>>>(W1);
    k_count<<<eb, 256>>>(edst, e);
    k_dinvreduce<<<nb, 256>>>(n);
    k_scatter<<<nb, 256>>>(nb, n);
    k_fill<<<eb, 256>>>(esrc, edst, e);

    // conv1: two hops (half path)
    k_hop_h<<<hopBlocks, 256>>>(xh, h1, dinv1, rowptr, colidx, 1.0f, n);
    k_hop_h<<<hopBlocks, 256>>>(h1, h2, dinv1, rowptr, colidx, 0.36787944117144233f, n);

    // GEMM1 on tensor cores (padded rows are zero), then bias+SELU epilogue
    dim3 g1(NNP / 128, 2);
    k_gemm1_wmma<<<g1, 256>>>(h2, w1h, raw);
    k_epi<<<2048, 256>>>(b1, n);

    // GEMM2 (fp32 SIMT), convert to half for the final gather
    k_gemm2<<<(n + 127) / 128, 256>>>(act, W2, gf, n, D2);
    k_f2h<<<512, 256>>>(n);

    k_out<<<hopBlocks, 256>>>(dinv2, rowptr, colidx, b2, out, n);
}

// round 7
// speedup vs baseline: 2.5534x; 1.3964x over previous
#include <cuda_runtime.h>
#include <cuda_fp16.h>
#include <mma.h>
#include <math.h>

using namespace nvcuda;

#define NN 100000
#define NNP 100096           // padded to multiple of 128 for wmma tiles
#define NE 3200000
#define D1 256
#define D2 64
#define NPARTMAX 512

// ---------------- static device scratch ----------------
__device__ int    g_cnt[NN];
__device__ int    g_woff[NN];
__device__ int    g_rowptr[NN + 1];
__device__ int    g_part[NPARTMAX];
__device__ int    g_col[NE];
__device__ float  g_dinv1[NN];
__device__ float  g_dinv2[NN];
__device__ __half g_xh[(size_t)NN * D1];     // x in half
__device__ __half g_h1[(size_t)NN * D1];     // hop1 out
__device__ __half g_h2[(size_t)NNP * D1];    // hop2 out (padded; pad rows stay 0)
__device__ __half g_w1h[D1 * D1];            // W1 half
__device__ __half g_w2h[D1 * D2];            // W2 half
__device__ float  g_raw[(size_t)NNP * D1];   // gemm1 raw out (fp32)
__device__ __half g_acth[(size_t)NNP * D1];  // selu(raw+b1) in half (pad rows stay 0)
__device__ __half g_gh[(size_t)NNP * D2];    // gemm2 out half (gather source)

// ---------------- helpers ----------------
__device__ __forceinline__ float selu_f(float x) {
    const float sc = 1.0507009873554804934f;
    const float al = 1.6732632423543772848f;
    return x > 0.f ? sc * x : sc * al * expm1f(x);
}

__device__ __forceinline__ void acch8(float2 a[4], float w, float4 v) {
    __half2* hp = (__half2*)&v;
#pragma unroll
    for (int q = 0; q < 4; q++) {
        float2 f = __half22float2(hp[q]);
        a[q].x = fmaf(w, f.x, a[q].x);
        a[q].y = fmaf(w, f.y, a[q].y);
    }
}

__device__ __forceinline__ uint2 f4_to_h4(float4 v) {
    __half2 h0 = __floats2half2_rn(v.x, v.y);
    __half2 h1 = __floats2half2_rn(v.z, v.w);
    return make_uint2(*(unsigned*)&h0, *(unsigned*)&h1);
}

// ---------------- preprocessing ----------------
__global__ void k_prep(const float* __restrict__ x, const float* __restrict__ W1,
                       const float* __restrict__ W2, int n) {
    int total = n * (D1 / 4);   // float4 groups
    for (int i = blockIdx.x * blockDim.x + threadIdx.x; i < total; i += gridDim.x * blockDim.x) {
        ((uint2*)g_xh)[i] = f4_to_h4(__ldg(((const float4*)x) + i));
        if (i < n) { g_cnt[i] = 0; g_woff[i] = 0; }
        if (i < (D1 * D1) / 4) ((uint2*)g_w1h)[i] = f4_to_h4(__ldg(((const float4*)W1) + i));
        if (i < (D1 * D2) / 4) ((uint2*)g_w2h)[i] = f4_to_h4(__ldg(((const float4*)W2) + i));
    }
}

__global__ void k_count(const int* __restrict__ dst, int e) {
    int i = blockIdx.x * blockDim.x + threadIdx.x;
    if (i < e) atomicAdd(&g_cnt[dst[i]], 1);
}

__global__ void k_dinvreduce(int n) {
    __shared__ int s[256];
    int t = threadIdx.x;
    int i = blockIdx.x * 256 + t;
    int d = 0;
    if (i < n) {
        d = g_cnt[i];
        g_dinv1[i] = d > 0 ? rsqrtf((float)d) : 0.f;
        g_dinv2[i] = rsqrtf((float)(d + 1));
    }
    s[t] = d;
    __syncthreads();
    for (int o = 128; o; o >>= 1) { if (t < o) s[t] += s[t + o]; __syncthreads(); }
    if (t == 0) g_part[blockIdx.x] = s[0];
}

__global__ void k_scatter(int nparts, int n) {
    __shared__ int spart[NPARTMAX];
    __shared__ int s[256];
    __shared__ int red[8];
    int t = threadIdx.x;
    int b = blockIdx.x;

    for (int i = t; i < nparts; i += 256) spart[i] = g_part[i];
    __syncthreads();

    int loc = 0;
    for (int i = t; i < b; i += 256) loc += spart[i];
#pragma unroll
    for (int o = 16; o; o >>= 1) loc += __shfl_xor_sync(~0u, loc, o);
    if ((t & 31) == 0) red[t >> 5] = loc;
    __syncthreads();
    int blockpre = red[0] + red[1] + red[2] + red[3] + red[4] + red[5] + red[6] + red[7];

    if (b == 0 && t == 0) {
        int tot = 0;
        for (int i = 0; i < nparts; i++) tot += spart[i];
        g_rowptr[n] = tot;
    }

    int i = b * 256 + t;
    int v = (i < n) ? g_cnt[i] : 0;
    s[t] = v;
    __syncthreads();
    for (int o = 1; o < 256; o <<= 1) {
        int x = (t >= o) ? s[t - o] : 0;
        __syncthreads();
        s[t] += x;
        __syncthreads();
    }
    if (i < n) g_rowptr[i] = blockpre + s[t] - v;
}

__global__ void k_fill(const int* __restrict__ src, const int* __restrict__ dst, int e) {
    int i = blockIdx.x * blockDim.x + threadIdx.x;
    if (i < e) {
        int d = dst[i];
        int p = g_rowptr[d] + atomicAdd(&g_woff[d], 1);
        g_col[p] = src[i];
    }
}

// ---------------- 256-dim half->half propagation hop ----------------
__global__ void __launch_bounds__(256) k_hop_h(
    const __half* __restrict__ xin, __half* __restrict__ xout,
    const float* __restrict__ dinv, const int* __restrict__ rowptr,
    const int* __restrict__ colidx, float coeff, int n)
{
    int node = (blockIdx.x * blockDim.x + threadIdx.x) >> 5;
    int lane = threadIdx.x & 31;
    if (node >= n) return;
    int beg = rowptr[node], end = rowptr[node + 1];

    float2 a[4];
#pragma unroll
    for (int q = 0; q < 4; q++) a[q] = make_float2(0.f, 0.f);

    for (int e0 = beg; e0 < end; e0 += 32) {
        int idx = e0 + lane;
        int c = 0; float w = 0.f;
        if (idx < end) { c = colidx[idx]; w = __ldg(dinv + c); }
        int cnt = min(32, end - e0);
        int j = 0;
        for (; j + 4 <= cnt; j += 4) {
            int   c0 = __shfl_sync(~0u, c, j + 0); float w0 = __shfl_sync(~0u, w, j + 0);
            int   c1 = __shfl_sync(~0u, c, j + 1); float w1 = __shfl_sync(~0u, w, j + 1);
            int   c2 = __shfl_sync(~0u, c, j + 2); float w2 = __shfl_sync(~0u, w, j + 2);
            int   c3 = __shfl_sync(~0u, c, j + 3); float w3 = __shfl_sync(~0u, w, j + 3);
            float4 v0 = __ldg(((const float4*)(xin + (size_t)c0 * D1)) + lane);
            float4 v1 = __ldg(((const float4*)(xin + (size_t)c1 * D1)) + lane);
            float4 v2 = __ldg(((const float4*)(xin + (size_t)c2 * D1)) + lane);
            float4 v3 = __ldg(((const float4*)(xin + (size_t)c3 * D1)) + lane);
            acch8(a, w0, v0);
            acch8(a, w1, v1);
            acch8(a, w2, v2);
            acch8(a, w3, v3);
        }
        for (; j < cnt; j++) {
            int   cj = __shfl_sync(~0u, c, j);
            float wj = __shfl_sync(~0u, w, j);
            float4 v = __ldg(((const float4*)(xin + (size_t)cj * D1)) + lane);
            acch8(a, wj, v);
        }
    }

    float s = coeff * __ldg(dinv + node);
    __half2 o0 = __floats2half2_rn(s * a[0].x, s * a[0].y);
    __half2 o1 = __floats2half2_rn(s * a[1].x, s * a[1].y);
    __half2 o2 = __floats2half2_rn(s * a[2].x, s * a[2].y);
    __half2 o3 = __floats2half2_rn(s * a[3].x, s * a[3].y);
    uint4 u;
    u.x = *(unsigned*)&o0; u.y = *(unsigned*)&o1;
    u.z = *(unsigned*)&o2; u.w = *(unsigned*)&o3;
    ((uint4*)(xout + (size_t)node * D1))[lane] = u;
}

// ---------------- GEMM1 (smem-staged wmma): raw = h2[NNP,256] @ W1h[256,256] ----------------
__global__ void __launch_bounds__(256) k_gemm1(
    const __half* __restrict__ A, const __half* __restrict__ B, float* __restrict__ C)
{
    const int BM = 128, BN = 128, BK = 32;
    __shared__ __half As[BM][BK + 8];    // 128 x 40 (row = 80B, 16B-multiple)
    __shared__ __half Bs[BK][BN + 8];    // 32 x 136 (row = 272B, 16B-multiple)

    int tid  = threadIdx.x;
    int warp = tid >> 5;
    int wm = warp >> 1;     // 0..3
    int wn = warp & 1;      // 0..1
    int bm = blockIdx.x * BM;
    int bn = blockIdx.y * BN;

    wmma::fragment<wmma::accumulator, 16, 16, 16, float> acc[2][4];
#pragma unroll
    for (int r = 0; r < 2; r++)
#pragma unroll
        for (int c = 0; c < 4; c++) wmma::fill_fragment(acc[r][c], 0.f);

    for (int k0 = 0; k0 < D1; k0 += BK) {
        // A tile: 128x32 halfs = 512 8-half chunks; 2 per thread
#pragma unroll
        for (int q = tid; q < (BM * BK) / 8; q += 256) {
            int r  = q >> 2;          // 4 chunks per row
            int ch = (q & 3) * 8;
            *(uint4*)&As[r][ch] = *(const uint4*)(A + (size_t)(bm + r) * D1 + k0 + ch);
        }
        // B tile: 32x128 halfs = 512 chunks; 2 per thread
#pragma unroll
        for (int q = tid; q < (BK * BN) / 8; q += 256) {
            int r  = q >> 4;          // 16 chunks per row
            int ch = (q & 15) * 8;
            *(uint4*)&Bs[r][ch] = *(const uint4*)(B + (size_t)(k0 + r) * D1 + bn + ch);
        }
        __syncthreads();
#pragma unroll
        for (int kk = 0; kk < BK; kk += 16) {
            wmma::fragment<wmma::matrix_a, 16, 16, 16, __half, wmma::row_major> af[2];
            wmma::fragment<wmma::matrix_b, 16, 16, 16, __half, wmma::row_major> bf[4];
#pragma unroll
            for (int r = 0; r < 2; r++)
                wmma::load_matrix_sync(af[r], &As[wm * 32 + r * 16][kk], BK + 8);
#pragma unroll
            for (int c = 0; c < 4; c++)
                wmma::load_matrix_sync(bf[c], &Bs[kk][wn * 64 + c * 16], BN + 8);
#pragma unroll
            for (int r = 0; r < 2; r++)
#pragma unroll
                for (int c = 0; c < 4; c++)
                    wmma::mma_sync(acc[r][c], af[r], bf[c], acc[r][c]);
        }
        __syncthreads();
    }

#pragma unroll
    for (int r = 0; r < 2; r++)
#pragma unroll
        for (int c = 0; c < 4; c++)
            wmma::store_matrix_sync(C + (size_t)(bm + wm * 32 + r * 16) * D1 + bn + wn * 64 + c * 16,
                                    acc[r][c], D1, wmma::mem_row_major);
}

// ---------------- epilogue: acth = half(selu(raw + b1)) ----------------
__global__ void k_epi(const float* __restrict__ b1, int n) {
    int total = n * (D1 / 4);
    for (int i = blockIdx.x * blockDim.x + threadIdx.x; i < total; i += gridDim.x * blockDim.x) {
        float4 v = __ldg(((const float4*)g_raw) + i);
        float4 b = __ldg(((const float4*)b1) + (i & 63));
        float4 o;
        o.x = selu_f(v.x + b.x);
        o.y = selu_f(v.y + b.y);
        o.z = selu_f(v.z + b.z);
        o.w = selu_f(v.w + b.w);
        ((uint2*)g_acth)[i] = f4_to_h4(o);
    }
}

// ---------------- GEMM2 (smem-staged wmma, half out): gh = acth[NNP,256] @ W2h[256,64] ----------------
__global__ void __launch_bounds__(256) k_gemm2(
    const __half* __restrict__ A, const __half* __restrict__ B, __half* __restrict__ Cg)
{
    const int BM = 128, BN = 64, BK = 32;
    __shared__ __half As[BM][BK + 8];       // 128 x 40
    __shared__ __half Bs[BK][BN + 8];       // 32 x 72 (row = 144B, 16B-multiple)
    __shared__ float  Cs[8][32][36];        // ldm=36 floats = 144B (16B-multiple, legal)

    int tid  = threadIdx.x;
    int warp = tid >> 5;
    int lane = tid & 31;
    int wm = warp >> 1;     // 0..3 (rows)
    int wn = warp & 1;      // 0..1 (cols)
    int bm = blockIdx.x * BM;

    wmma::fragment<wmma::accumulator, 16, 16, 16, float> acc[2][2];
#pragma unroll
    for (int r = 0; r < 2; r++)
#pragma unroll
        for (int c = 0; c < 2; c++) wmma::fill_fragment(acc[r][c], 0.f);

    for (int k0 = 0; k0 < D1; k0 += BK) {
        // A tile: 128x32 halfs = 512 chunks; 2 per thread
#pragma unroll
        for (int q = tid; q < (BM * BK) / 8; q += 256) {
            int r  = q >> 2;
            int ch = (q & 3) * 8;
            *(uint4*)&As[r][ch] = *(const uint4*)(A + (size_t)(bm + r) * D1 + k0 + ch);
        }
        // B tile: 32x64 halfs = 256 chunks; 1 per thread
        {
            int r  = tid >> 3;        // 8 chunks per row
            int ch = (tid & 7) * 8;
            *(uint4*)&Bs[r][ch] = *(const uint4*)(B + (size_t)(k0 + r) * D2 + ch);
        }
        __syncthreads();
#pragma unroll
        for (int kk = 0; kk < BK; kk += 16) {
            wmma::fragment<wmma::matrix_a, 16, 16, 16, __half, wmma::row_major> af[2];
            wmma::fragment<wmma::matrix_b, 16, 16, 16, __half, wmma::row_major> bf[2];
#pragma unroll
            for (int r = 0; r < 2; r++)
                wmma::load_matrix_sync(af[r], &As[wm * 32 + r * 16][kk], BK + 8);
#pragma unroll
            for (int c = 0; c < 2; c++)
                wmma::load_matrix_sync(bf[c], &Bs[kk][wn * 32 + c * 16], BN + 8);
#pragma unroll
            for (int r = 0; r < 2; r++)
#pragma unroll
                for (int c = 0; c < 2; c++)
                    wmma::mma_sync(acc[r][c], af[r], bf[c], acc[r][c]);
        }
        __syncthreads();
    }

    // stage fp32 accumulators to smem (ldm=36 floats, legal), convert to half, coalesced store
#pragma unroll
    for (int r = 0; r < 2; r++)
#pragma unroll
        for (int c = 0; c < 2; c++)
            wmma::store_matrix_sync(&Cs[warp][r * 16][c * 16], acc[r][c], 36, wmma::mem_row_major);
    __syncwarp();

    // each lane: one 32-float row -> 16 half2 -> 4 x 16B stores
    float* rowp = &Cs[warp][lane][0];
    size_t grow = (size_t)(bm + wm * 32 + lane) * D2 + wn * 32;
#pragma unroll
    for (int ch = 0; ch < 4; ch++) {
        float4 v0 = make_float4(rowp[ch * 8 + 0], rowp[ch * 8 + 1], rowp[ch * 8 + 2], rowp[ch * 8 + 3]);
        float4 v1 = make_float4(rowp[ch * 8 + 4], rowp[ch * 8 + 5], rowp[ch * 8 + 6], rowp[ch * 8 + 7]);
        uint2 a = f4_to_h4(v0);
        uint2 b = f4_to_h4(v1);
        *(uint4*)(Cg + grow + ch * 8) = make_uint4(a.x, a.y, b.x, b.y);
    }
}

// ---------------- final hop (D=64, self loops, half gather) + bias + log_softmax ----------------
__global__ void __launch_bounds__(256) k_out(
    const float* __restrict__ dinv2,
    const int* __restrict__ rowptr, const int* __restrict__ colidx,
    const float* __restrict__ b2, float* __restrict__ out, int n)
{
    int node = (blockIdx.x * blockDim.x + threadIdx.x) >> 5;
    int lane = threadIdx.x & 31;
    if (node >= n) return;
    int beg = rowptr[node], end = rowptr[node + 1];

    float di = __ldg(dinv2 + node);
    float2 sv = __half22float2(__ldg(((const __half2*)(g_gh + (size_t)node * D2)) + lane));
    float ax = di * sv.x;
    float ay = di * sv.y;

    for (int e0 = beg; e0 < end; e0 += 32) {
        int idx = e0 + lane;
        int c = 0; float w = 0.f;
        if (idx < end) { c = colidx[idx]; w = __ldg(dinv2 + c); }
        int cnt = min(32, end - e0);
        int j = 0;
        for (; j + 4 <= cnt; j += 4) {
            int   c0 = __shfl_sync(~0u, c, j + 0); float w0 = __shfl_sync(~0u, w, j + 0);
            int   c1 = __shfl_sync(~0u, c, j + 1); float w1 = __shfl_sync(~0u, w, j + 1);
            int   c2 = __shfl_sync(~0u, c, j + 2); float w2 = __shfl_sync(~0u, w, j + 2);
            int   c3 = __shfl_sync(~0u, c, j + 3); float w3 = __shfl_sync(~0u, w, j + 3);
            float2 v0 = __half22float2(__ldg(((const __half2*)(g_gh + (size_t)c0 * D2)) + lane));
            float2 v1 = __half22float2(__ldg(((const __half2*)(g_gh + (size_t)c1 * D2)) + lane));
            float2 v2 = __half22float2(__ldg(((const __half2*)(g_gh + (size_t)c2 * D2)) + lane));
            float2 v3 = __half22float2(__ldg(((const __half2*)(g_gh + (size_t)c3 * D2)) + lane));
            ax = fmaf(w0, v0.x, ax); ay = fmaf(w0, v0.y, ay);
            ax = fmaf(w1, v1.x, ax); ay = fmaf(w1, v1.y, ay);
            ax = fmaf(w2, v2.x, ax); ay = fmaf(w2, v2.y, ay);
            ax = fmaf(w3, v3.x, ax); ay = fmaf(w3, v3.y, ay);
        }
        for (; j < cnt; j++) {
            int   cj = __shfl_sync(~0u, c, j);
            float wj = __shfl_sync(~0u, w, j);
            float2 v = __half22float2(__ldg(((const __half2*)(g_gh + (size_t)cj * D2)) + lane));
            ax = fmaf(wj, v.x, ax); ay = fmaf(wj, v.y, ay);
        }
    }

    float p0 = di * ax + __ldg(b2 + lane * 2);
    float p1 = di * ay + __ldg(b2 + lane * 2 + 1);

    float m = fmaxf(p0, p1);
#pragma unroll
    for (int o = 16; o; o >>= 1) m = fmaxf(m, __shfl_xor_sync(~0u, m, o));
    float esum = expf(p0 - m) + expf(p1 - m);
#pragma unroll
    for (int o = 16; o; o >>= 1) esum += __shfl_xor_sync(~0u, esum, o);
    float lse = m + logf(esum);

    float2 res = make_float2(p0 - lse, p1 - lse);
    ((float2*)(out + (size_t)node * D2))[lane] = res;
}

// ---------------- launch ----------------
extern "C" void kernel_launch(void* const* d_in, const int* in_sizes, int n_in,
                              void* d_out, int out_size) {
    const float* x    = (const float*)d_in[0];
    const int*   esrc = (const int*)d_in[1];
    const int*   edst = (const int*)d_in[2];
    const float* W1   = (const float*)d_in[3];
    const float* b1   = (const float*)d_in[4];
    const float* W2   = (const float*)d_in[5];
    const float* b2   = (const float*)d_in[6];
    float* out = (float*)d_out;

    int n = in_sizes[0] / D1;   // 100000
    int e = in_sizes[1];        // 3200000

    __half *xh, *h1, *h2, *w1h, *w2h, *acth, *gh;
    float *dinv1, *dinv2, *raw;
    int *rowptr, *colidx;
    cudaGetSymbolAddress((void**)&xh, g_xh);
    cudaGetSymbolAddress((void**)&h1, g_h1);
    cudaGetSymbolAddress((void**)&h2, g_h2);
    cudaGetSymbolAddress((void**)&w1h, g_w1h);
    cudaGetSymbolAddress((void**)&w2h, g_w2h);
    cudaGetSymbolAddress((void**)&acth, g_acth);
    cudaGetSymbolAddress((void**)&gh, g_gh);
    cudaGetSymbolAddress((void**)&raw, g_raw);
    cudaGetSymbolAddress((void**)&dinv1, g_dinv1);
    cudaGetSymbolAddress((void**)&dinv2, g_dinv2);
    cudaGetSymbolAddress((void**)&rowptr, g_rowptr);
    cudaGetSymbolAddress((void**)&colidx, g_col);

    int nb = (n + 255) / 256;          // 391
    int eb = (e + 255) / 256;
    int hopBlocks = (n * 32 + 255) / 256;

    // preprocessing
    k_prep<<<2048, 256>>>(x, W1, W2, n);
    k_count<<<eb, 256>>>(edst, e);
    k_dinvreduce<<<nb, 256>>>(n);
    k_scatter<<<nb, 256>>>(nb, n);
    k_fill<<<eb, 256>>>(esrc, edst, e);

    // conv1: two hops (half path)
    k_hop_h<<<hopBlocks, 256>>>(xh, h1, dinv1, rowptr, colidx, 1.0f, n);
    k_hop_h<<<hopBlocks, 256>>>(h1, h2, dinv1, rowptr, colidx, 0.36787944117144233f, n);

    // GEMM1 (tensor cores, smem staged), then bias+SELU epilogue -> half
    dim3 g1(NNP / 128, 2);
    k_gemm1<<<g1, 256>>>(h2, w1h, raw);
    k_epi<<<2048, 256>>>(b1, n);

    // GEMM2 (tensor cores, half out via legal smem staging)
    k_gemm2<<<NNP / 128, 256>>>(acth, w2h, gh);

    k_out<<<hopBlocks, 256>>>(dinv2, rowptr, colidx, b2, out, n);
}

// round 8
// speedup vs baseline: 2.6143x; 1.0238x over previous
#include <cuda_runtime.h>
#include <cuda_fp16.h>
#include <mma.h>
#include <math.h>

using namespace nvcuda;

#define NN 100000
#define NNP 100096           // padded to multiple of 128 for wmma tiles
#define NE 3200000
#define D1 256
#define D2 64
#define NPARTMAX 512

// ---------------- static device scratch ----------------
__device__ int    g_cnt[NN];
__device__ int    g_woff[NN];
__device__ int    g_rowptr[NN + 1];
__device__ int    g_part[NPARTMAX];
__device__ int    g_col[NE];
__device__ float  g_dinv1[NN];
__device__ float  g_dinv2[NN];
__device__ __half g_xh[(size_t)NN * D1];     // x in half
__device__ __half g_h1[(size_t)NN * D1];     // hop1 out
__device__ __half g_h2[(size_t)NNP * D1];    // hop2 out (padded; pad rows stay 0)
__device__ __half g_w1h[D1 * D1];            // W1 half
__device__ __half g_w2h[D1 * D2];            // W2 half
__device__ __half g_acth[(size_t)NNP * D1];  // selu(h2@W1+b1) in half
__device__ __half g_gh[(size_t)NNP * D2];    // gemm2 out half (gather source)

// ---------------- helpers ----------------
__device__ __forceinline__ float selu_f(float x) {
    const float sc = 1.0507009873554804934f;
    const float al = 1.6732632423543772848f;
    return x > 0.f ? sc * x : sc * al * expm1f(x);
}

__device__ __forceinline__ void acch8(float2 a[4], float w, float4 v) {
    __half2* hp = (__half2*)&v;
#pragma unroll
    for (int q = 0; q < 4; q++) {
        float2 f = __half22float2(hp[q]);
        a[q].x = fmaf(w, f.x, a[q].x);
        a[q].y = fmaf(w, f.y, a[q].y);
    }
}

__device__ __forceinline__ uint2 f4_to_h4(float4 v) {
    __half2 h0 = __floats2half2_rn(v.x, v.y);
    __half2 h1 = __floats2half2_rn(v.z, v.w);
    return make_uint2(*(unsigned*)&h0, *(unsigned*)&h1);
}

// ---------------- preprocessing ----------------
__global__ void k_prep(const float* __restrict__ x, const float* __restrict__ W1,
                       const float* __restrict__ W2, int n) {
    int total = n * (D1 / 4);   // float4 groups
    for (int i = blockIdx.x * blockDim.x + threadIdx.x; i < total; i += gridDim.x * blockDim.x) {
        ((uint2*)g_xh)[i] = f4_to_h4(__ldg(((const float4*)x) + i));
        if (i < n) { g_cnt[i] = 0; g_woff[i] = 0; }
        if (i < (D1 * D1) / 4) ((uint2*)g_w1h)[i] = f4_to_h4(__ldg(((const float4*)W1) + i));
        if (i < (D1 * D2) / 4) ((uint2*)g_w2h)[i] = f4_to_h4(__ldg(((const float4*)W2) + i));
    }
}

__global__ void k_count(const int* __restrict__ dst, int e) {
    int i = blockIdx.x * blockDim.x + threadIdx.x;
    if (i < e) atomicAdd(&g_cnt[dst[i]], 1);
}

__global__ void k_dinvreduce(int n) {
    __shared__ int s[256];
    int t = threadIdx.x;
    int i = blockIdx.x * 256 + t;
    int d = 0;
    if (i < n) {
        d = g_cnt[i];
        g_dinv1[i] = d > 0 ? rsqrtf((float)d) : 0.f;
        g_dinv2[i] = rsqrtf((float)(d + 1));
    }
    s[t] = d;
    __syncthreads();
    for (int o = 128; o; o >>= 1) { if (t < o) s[t] += s[t + o]; __syncthreads(); }
    if (t == 0) g_part[blockIdx.x] = s[0];
}

__global__ void k_scatter(int nparts, int n) {
    __shared__ int spart[NPARTMAX];
    __shared__ int s[256];
    __shared__ int red[8];
    int t = threadIdx.x;
    int b = blockIdx.x;

    for (int i = t; i < nparts; i += 256) spart[i] = g_part[i];
    __syncthreads();

    int loc = 0;
    for (int i = t; i < b; i += 256) loc += spart[i];
#pragma unroll
    for (int o = 16; o; o >>= 1) loc += __shfl_xor_sync(~0u, loc, o);
    if ((t & 31) == 0) red[t >> 5] = loc;
    __syncthreads();
    int blockpre = red[0] + red[1] + red[2] + red[3] + red[4] + red[5] + red[6] + red[7];

    if (b == 0 && t == 0) {
        int tot = 0;
        for (int i = 0; i < nparts; i++) tot += spart[i];
        g_rowptr[n] = tot;
    }

    int i = b * 256 + t;
    int v = (i < n) ? g_cnt[i] : 0;
    s[t] = v;
    __syncthreads();
    for (int o = 1; o < 256; o <<= 1) {
        int x = (t >= o) ? s[t - o] : 0;
        __syncthreads();
        s[t] += x;
        __syncthreads();
    }
    if (i < n) g_rowptr[i] = blockpre + s[t] - v;
}

__global__ void k_fill(const int* __restrict__ src, const int* __restrict__ dst, int e) {
    int i = blockIdx.x * blockDim.x + threadIdx.x;
    if (i < e) {
        int d = dst[i];
        int p = g_rowptr[d] + atomicAdd(&g_woff[d], 1);
        g_col[p] = src[i];
    }
}

// ---------------- 256-dim half->half propagation hop ----------------
__global__ void __launch_bounds__(256) k_hop_h(
    const __half* __restrict__ xin, __half* __restrict__ xout,
    const float* __restrict__ dinv, const int* __restrict__ rowptr,
    const int* __restrict__ colidx, float coeff, int n)
{
    int node = (blockIdx.x * blockDim.x + threadIdx.x) >> 5;
    int lane = threadIdx.x & 31;
    if (node >= n) return;
    int beg = rowptr[node], end = rowptr[node + 1];

    float2 a[4];
#pragma unroll
    for (int q = 0; q < 4; q++) a[q] = make_float2(0.f, 0.f);

    for (int e0 = beg; e0 < end; e0 += 32) {
        int idx = e0 + lane;
        int c = 0; float w = 0.f;
        if (idx < end) { c = colidx[idx]; w = __ldg(dinv + c); }
        int cnt = min(32, end - e0);
        int j = 0;
        for (; j + 4 <= cnt; j += 4) {
            int   c0 = __shfl_sync(~0u, c, j + 0); float w0 = __shfl_sync(~0u, w, j + 0);
            int   c1 = __shfl_sync(~0u, c, j + 1); float w1 = __shfl_sync(~0u, w, j + 1);
            int   c2 = __shfl_sync(~0u, c, j + 2); float w2 = __shfl_sync(~0u, w, j + 2);
            int   c3 = __shfl_sync(~0u, c, j + 3); float w3 = __shfl_sync(~0u, w, j + 3);
            float4 v0 = __ldg(((const float4*)(xin + (size_t)c0 * D1)) + lane);
            float4 v1 = __ldg(((const float4*)(xin + (size_t)c1 * D1)) + lane);
            float4 v2 = __ldg(((const float4*)(xin + (size_t)c2 * D1)) + lane);
            float4 v3 = __ldg(((const float4*)(xin + (size_t)c3 * D1)) + lane);
            acch8(a, w0, v0);
            acch8(a, w1, v1);
            acch8(a, w2, v2);
            acch8(a, w3, v3);
        }
        for (; j < cnt; j++) {
            int   cj = __shfl_sync(~0u, c, j);
            float wj = __shfl_sync(~0u, w, j);
            float4 v = __ldg(((const float4*)(xin + (size_t)cj * D1)) + lane);
            acch8(a, wj, v);
        }
    }

    float s = coeff * __ldg(dinv + node);
    __half2 o0 = __floats2half2_rn(s * a[0].x, s * a[0].y);
    __half2 o1 = __floats2half2_rn(s * a[1].x, s * a[1].y);
    __half2 o2 = __floats2half2_rn(s * a[2].x, s * a[2].y);
    __half2 o3 = __floats2half2_rn(s * a[3].x, s * a[3].y);
    uint4 u;
    u.x = *(unsigned*)&o0; u.y = *(unsigned*)&o1;
    u.z = *(unsigned*)&o2; u.w = *(unsigned*)&o3;
    ((uint4*)(xout + (size_t)node * D1))[lane] = u;
}

// ---------------- GEMM1 + fused bias/SELU epilogue -> half ----------------
// acth = half(selu(h2[NNP,256] @ W1h[256,256] + b1))
__global__ void __launch_bounds__(256) k_gemm1(
    const __half* __restrict__ A, const __half* __restrict__ B,
    const float* __restrict__ bias, __half* __restrict__ Cg)
{
    const int BM = 128, BN = 128, BK = 32;
    const int AS_BYTES = BM * (BK + 8) * 2;             // 10240
    const int BS_BYTES = BK * (BN + 8) * 2;             // 8704
    const int CS_BYTES = 8 * 16 * 68 * 4;               // 34816
    __shared__ __align__(16) char smem_buf[CS_BYTES > AS_BYTES + BS_BYTES ? CS_BYTES : AS_BYTES + BS_BYTES];

    __half (*As)[BK + 8] = reinterpret_cast<__half(*)[BK + 8]>(smem_buf);
    __half (*Bs)[BN + 8] = reinterpret_cast<__half(*)[BN + 8]>(smem_buf + AS_BYTES);
    float  (*Cs)[68]     = reinterpret_cast<float(*)[68]>(smem_buf);  // reused after mainloop

    int tid  = threadIdx.x;
    int warp = tid >> 5;
    int lane = tid & 31;
    int wm = warp >> 1;     // 0..3
    int wn = warp & 1;      // 0..1
    int bm = blockIdx.x * BM;
    int bn = blockIdx.y * BN;

    wmma::fragment<wmma::accumulator, 16, 16, 16, float> acc[2][4];
#pragma unroll
    for (int r = 0; r < 2; r++)
#pragma unroll
        for (int c = 0; c < 4; c++) wmma::fill_fragment(acc[r][c], 0.f);

    for (int k0 = 0; k0 < D1; k0 += BK) {
        // A tile: 128x32 halfs = 512 8-half chunks; 2 per thread
#pragma unroll
        for (int q = tid; q < (BM * BK) / 8; q += 256) {
            int r  = q >> 2;          // 4 chunks per row
            int ch = (q & 3) * 8;
            *(uint4*)&As[r][ch] = *(const uint4*)(A + (size_t)(bm + r) * D1 + k0 + ch);
        }
        // B tile: 32x128 halfs = 512 chunks; 2 per thread
#pragma unroll
        for (int q = tid; q < (BK * BN) / 8; q += 256) {
            int r  = q >> 4;          // 16 chunks per row
            int ch = (q & 15) * 8;
            *(uint4*)&Bs[r][ch] = *(const uint4*)(B + (size_t)(k0 + r) * D1 + bn + ch);
        }
        __syncthreads();
#pragma unroll
        for (int kk = 0; kk < BK; kk += 16) {
            wmma::fragment<wmma::matrix_a, 16, 16, 16, __half, wmma::row_major> af[2];
            wmma::fragment<wmma::matrix_b, 16, 16, 16, __half, wmma::row_major> bf[4];
#pragma unroll
            for (int r = 0; r < 2; r++)
                wmma::load_matrix_sync(af[r], &As[wm * 32 + r * 16][kk], BK + 8);
#pragma unroll
            for (int c = 0; c < 4; c++)
                wmma::load_matrix_sync(bf[c], &Bs[kk][wn * 64 + c * 16], BN + 8);
#pragma unroll
            for (int r = 0; r < 2; r++)
#pragma unroll
                for (int c = 0; c < 4; c++)
                    wmma::mma_sync(acc[r][c], af[r], bf[c], acc[r][c]);
        }
        __syncthreads();   // also fences As/Bs before Cs reuse on last iter
    }

    // fused epilogue: per 16-row group, stage fp32 (ldm=68 floats = 272B, 16B mult),
    // add bias, SELU, convert to half, coalesced 16B stores
    int colbase = bn + wn * 64;
    // preload bias for this warp's 64-col strip: lane half (lane&1)*32 .. +31
    float bl[32];
    {
        int cb = colbase + (lane & 1) * 32;
#pragma unroll
        for (int ch = 0; ch < 8; ch++) {
            float4 b4 = __ldg((const float4*)(bias + cb + ch * 4));
            bl[ch * 4 + 0] = b4.x; bl[ch * 4 + 1] = b4.y;
            bl[ch * 4 + 2] = b4.z; bl[ch * 4 + 3] = b4.w;
        }
    }
#pragma unroll
    for (int r = 0; r < 2; r++) {
#pragma unroll
        for (int c = 0; c < 4; c++)
            wmma::store_matrix_sync(&Cs[warp * 16][0] + 0 * 68 + c * 16 + 0, acc[r][c], 68, wmma::mem_row_major),
            (void)0;
        // note: the line above stores fragment c at column offset c*16 of rows [warp*16, warp*16+16)
        __syncwarp();
        int row = lane >> 1;               // 0..15
        int half_sel = (lane & 1) * 32;    // 0 or 32
        float* rowp = &Cs[warp * 16 + row][half_sel];
        size_t grow = (size_t)(bm + wm * 32 + r * 16 + row) * D1 + colbase + half_sel;
#pragma unroll
        for (int ch = 0; ch < 4; ch++) {
            float4 v0 = make_float4(selu_f(rowp[ch * 8 + 0] + bl[ch * 8 + 0]),
                                    selu_f(rowp[ch * 8 + 1] + bl[ch * 8 + 1]),
                                    selu_f(rowp[ch * 8 + 2] + bl[ch * 8 + 2]),
                                    selu_f(rowp[ch * 8 + 3] + bl[ch * 8 + 3]));
            float4 v1 = make_float4(selu_f(rowp[ch * 8 + 4] + bl[ch * 8 + 4]),
                                    selu_f(rowp[ch * 8 + 5] + bl[ch * 8 + 5]),
                                    selu_f(rowp[ch * 8 + 6] + bl[ch * 8 + 6]),
                                    selu_f(rowp[ch * 8 + 7] + bl[ch * 8 + 7]));
            uint2 pa = f4_to_h4(v0);
            uint2 pb = f4_to_h4(v1);
            *(uint4*)(Cg + grow + ch * 8) = make_uint4(pa.x, pa.y, pb.x, pb.y);
        }
        __syncwarp();
    }
}

// ---------------- GEMM2 (smem-staged wmma, half out): gh = acth[NNP,256] @ W2h[256,64] ----------------
__global__ void __launch_bounds__(256) k_gemm2(
    const __half* __restrict__ A, const __half* __restrict__ B, __half* __restrict__ Cg)
{
    const int BM = 128, BN = 64, BK = 32;
    __shared__ __half As[BM][BK + 8];       // 128 x 40
    __shared__ __half Bs[BK][BN + 8];       // 32 x 72 (row = 144B, 16B-multiple)
    __shared__ float  Cs[8][32][36];        // ldm=36 floats = 144B (16B-multiple, legal)

    int tid  = threadIdx.x;
    int warp = tid >> 5;
    int lane = tid & 31;
    int wm = warp >> 1;     // 0..3 (rows)
    int wn = warp & 1;      // 0..1 (cols)
    int bm = blockIdx.x * BM;

    wmma::fragment<wmma::accumulator, 16, 16, 16, float> acc[2][2];
#pragma unroll
    for (int r = 0; r < 2; r++)
#pragma unroll
        for (int c = 0; c < 2; c++) wmma::fill_fragment(acc[r][c], 0.f);

    for (int k0 = 0; k0 < D1; k0 += BK) {
#pragma unroll
        for (int q = tid; q < (BM * BK) / 8; q += 256) {
            int r  = q >> 2;
            int ch = (q & 3) * 8;
            *(uint4*)&As[r][ch] = *(const uint4*)(A + (size_t)(bm + r) * D1 + k0 + ch);
        }
        {
            int r  = tid >> 3;        // 8 chunks per row
            int ch = (tid & 7) * 8;
            *(uint4*)&Bs[r][ch] = *(const uint4*)(B + (size_t)(k0 + r) * D2 + ch);
        }
        __syncthreads();
#pragma unroll
        for (int kk = 0; kk < BK; kk += 16) {
            wmma::fragment<wmma::matrix_a, 16, 16, 16, __half, wmma::row_major> af[2];
            wmma::fragment<wmma::matrix_b, 16, 16, 16, __half, wmma::row_major> bf[2];
#pragma unroll
            for (int r = 0; r < 2; r++)
                wmma::load_matrix_sync(af[r], &As[wm * 32 + r * 16][kk], BK + 8);
#pragma unroll
            for (int c = 0; c < 2; c++)
                wmma::load_matrix_sync(bf[c], &Bs[kk][wn * 32 + c * 16], BN + 8);
#pragma unroll
            for (int r = 0; r < 2; r++)
#pragma unroll
                for (int c = 0; c < 2; c++)
                    wmma::mma_sync(acc[r][c], af[r], bf[c], acc[r][c]);
        }
        __syncthreads();
    }

#pragma unroll
    for (int r = 0; r < 2; r++)
#pragma unroll
        for (int c = 0; c < 2; c++)
            wmma::store_matrix_sync(&Cs[warp][r * 16][c * 16], acc[r][c], 36, wmma::mem_row_major);
    __syncwarp();

    float* rowp = &Cs[warp][lane][0];
    size_t grow = (size_t)(bm + wm * 32 + lane) * D2 + wn * 32;
#pragma unroll
    for (int ch = 0; ch < 4; ch++) {
        float4 v0 = make_float4(rowp[ch * 8 + 0], rowp[ch * 8 + 1], rowp[ch * 8 + 2], rowp[ch * 8 + 3]);
        float4 v1 = make_float4(rowp[ch * 8 + 4], rowp[ch * 8 + 5], rowp[ch * 8 + 6], rowp[ch * 8 + 7]);
        uint2 a = f4_to_h4(v0);
        uint2 b = f4_to_h4(v1);
        *(uint4*)(Cg + grow + ch * 8) = make_uint4(a.x, a.y, b.x, b.y);
    }
}

// ---------------- final hop (D=64, self loops, half gather) + bias + log_softmax ----------------
__global__ void __launch_bounds__(256) k_out(
    const float* __restrict__ dinv2,
    const int* __restrict__ rowptr, const int* __restrict__ colidx,
    const float* __restrict__ b2, float* __restrict__ out, int n)
{
    int node = (blockIdx.x * blockDim.x + threadIdx.x) >> 5;
    int lane = threadIdx.x & 31;
    if (node >= n) return;
    int beg = rowptr[node], end = rowptr[node + 1];

    float di = __ldg(dinv2 + node);
    float2 sv = __half22float2(__ldg(((const __half2*)(g_gh + (size_t)node * D2)) + lane));
    float ax = di * sv.x;
    float ay = di * sv.y;

    for (int e0 = beg; e0 < end; e0 += 32) {
        int idx = e0 + lane;
        int c = 0; float w = 0.f;
        if (idx < end) { c = colidx[idx]; w = __ldg(dinv2 + c); }
        int cnt = min(32, end - e0);
        int j = 0;
        for (; j + 4 <= cnt; j += 4) {
            int   c0 = __shfl_sync(~0u, c, j + 0); float w0 = __shfl_sync(~0u, w, j + 0);
            int   c1 = __shfl_sync(~0u, c, j + 1); float w1 = __shfl_sync(~0u, w, j + 1);
            int   c2 = __shfl_sync(~0u, c, j + 2); float w2 = __shfl_sync(~0u, w, j + 2);
            int   c3 = __shfl_sync(~0u, c, j + 3); float w3 = __shfl_sync(~0u, w, j + 3);
            float2 v0 = __half22float2(__ldg(((const __half2*)(g_gh + (size_t)c0 * D2)) + lane));
            float2 v1 = __half22float2(__ldg(((const __half2*)(g_gh + (size_t)c1 * D2)) + lane));
            float2 v2 = __half22float2(__ldg(((const __half2*)(g_gh + (size_t)c2 * D2)) + lane));
            float2 v3 = __half22float2(__ldg(((const __half2*)(g_gh + (size_t)c3 * D2)) + lane));
            ax = fmaf(w0, v0.x, ax); ay = fmaf(w0, v0.y, ay);
            ax = fmaf(w1, v1.x, ax); ay = fmaf(w1, v1.y, ay);
            ax = fmaf(w2, v2.x, ax); ay = fmaf(w2, v2.y, ay);
            ax = fmaf(w3, v3.x, ax); ay = fmaf(w3, v3.y, ay);
        }
        for (; j < cnt; j++) {
            int   cj = __shfl_sync(~0u, c, j);
            float wj = __shfl_sync(~0u, w, j);
            float2 v = __half22float2(__ldg(((const __half2*)(g_gh + (size_t)cj * D2)) + lane));
            ax = fmaf(wj, v.x, ax); ay = fmaf(wj, v.y, ay);
        }
    }

    float p0 = di * ax + __ldg(b2 + lane * 2);
    float p1 = di * ay + __ldg(b2 + lane * 2 + 1);

    float m = fmaxf(p0, p1);
#pragma unroll
    for (int o = 16; o; o >>= 1) m = fmaxf(m, __shfl_xor_sync(~0u, m, o));
    float esum = expf(p0 - m) + expf(p1 - m);
#pragma unroll
    for (int o = 16; o; o >>= 1) esum += __shfl_xor_sync(~0u, esum, o);
    float lse = m + logf(esum);

    float2 res = make_float2(p0 - lse, p1 - lse);
    ((float2*)(out + (size_t)node * D2))[lane] = res;
}

// ---------------- launch ----------------
extern "C" void kernel_launch(void* const* d_in, const int* in_sizes, int n_in,
                              void* d_out, int out_size) {
    const float* x    = (const float*)d_in[0];
    const int*   esrc = (const int*)d_in[1];
    const int*   edst = (const int*)d_in[2];
    const float* W1   = (const float*)d_in[3];
    const float* b1   = (const float*)d_in[4];
    const float* W2   = (const float*)d_in[5];
    const float* b2   = (const float*)d_in[6];
    float* out = (float*)d_out;

    int n = in_sizes[0] / D1;   // 100000
    int e = in_sizes[1];        // 3200000

    __half *xh, *h1, *h2, *w1h, *w2h, *acth, *gh;
    float *dinv1, *dinv2;
    int *rowptr, *colidx;
    cudaGetSymbolAddress((void**)&xh, g_xh);
    cudaGetSymbolAddress((void**)&h1, g_h1);
    cudaGetSymbolAddress((void**)&h2, g_h2);
    cudaGetSymbolAddress((void**)&w1h, g_w1h);
    cudaGetSymbolAddress((void**)&w2h, g_w2h);
    cudaGetSymbolAddress((void**)&acth, g_acth);
    cudaGetSymbolAddress((void**)&gh, g_gh);
    cudaGetSymbolAddress((void**)&dinv1, g_dinv1);
    cudaGetSymbolAddress((void**)&dinv2, g_dinv2);
    cudaGetSymbolAddress((void**)&rowptr, g_rowptr);
    cudaGetSymbolAddress((void**)&colidx, g_col);

    int nb = (n + 255) / 256;          // 391
    int eb = (e + 255) / 256;
    int hopBlocks = (n * 32 + 255) / 256;

    // preprocessing
    k_prep<<<2048, 256>>>(x, W1, W2, n);
    k_count<<<eb, 256>>>(edst, e);
    k_dinvreduce<<<nb, 256>>>(n);
    k_scatter<<<nb, 256>>>(nb, n);
    k_fill<<<eb, 256>>>(esrc, edst, e);

    // conv1: two hops (half path)
    k_hop_h<<<hopBlocks, 256>>>(xh, h1, dinv1, rowptr, colidx, 1.0f, n);
    k_hop_h<<<hopBlocks, 256>>>(h1, h2, dinv1, rowptr, colidx, 0.36787944117144233f, n);

    // GEMM1 (tensor cores) with fused bias+SELU epilogue -> half
    dim3 g1(NNP / 128, 2);
    k_gemm1<<<g1, 256>>>(h2, w1h, b1, acth);

    // GEMM2 (tensor cores, half out via legal smem staging)
    k_gemm2<<<NNP / 128, 256>>>(acth, w2h, gh);

    k_out<<<hopBlocks, 256>>>(dinv2, rowptr, colidx, b2, out, n);
}

// round 9
// speedup vs baseline: 2.6971x; 1.0317x over previous
#include <cuda_runtime.h>
#include <cuda_fp16.h>
#include <mma.h>
#include <math.h>

using namespace nvcuda;

#define NN 100000
#define NNP 100096           // padded to multiple of 128 for wmma tiles
#define NE 3200000
#define D1 256
#define D2 64
#define NPARTMAX 512

// ---------------- static device scratch ----------------
// g_cnt / g_woff are zero on first call and re-zeroed by k_hop_h at the end of
// every call (deterministic state restoration), so k_prep can count directly.
__device__ int    g_cnt[NN];
__device__ int    g_woff[NN];
__device__ int    g_rowptr[NN + 1];
__device__ int    g_part[NPARTMAX];
__device__ int    g_col[NE];
__device__ float  g_dinv1[NN];
__device__ float  g_dinv2[NN];
__device__ __half g_xh[(size_t)NN * D1];     // x in half
__device__ __half g_h1[(size_t)NN * D1];     // hop1 out
__device__ __half g_h2[(size_t)NNP * D1];    // hop2 out (padded; pad rows stay 0)
__device__ __half g_w1h[D1 * D1];            // W1 half
__device__ __half g_w2h[D1 * D2];            // W2 half
__device__ __half g_acth[(size_t)NNP * D1];  // selu(h2@W1+b1) in half
__device__ __half g_gh[(size_t)NNP * D2];    // gemm2 out half (gather source)

// ---------------- helpers ----------------
__device__ __forceinline__ float selu_f(float x) {
    const float sc = 1.0507009873554804934f;
    const float al = 1.6732632423543772848f;
    return x > 0.f ? sc * x : sc * al * expm1f(x);
}

__device__ __forceinline__ void acch8(float2 a[4], float w, float4 v) {
    __half2* hp = (__half2*)&v;
#pragma unroll
    for (int q = 0; q < 4; q++) {
        float2 f = __half22float2(hp[q]);
        a[q].x = fmaf(w, f.x, a[q].x);
        a[q].y = fmaf(w, f.y, a[q].y);
    }
}

__device__ __forceinline__ uint2 f4_to_h4(float4 v) {
    __half2 h0 = __floats2half2_rn(v.x, v.y);
    __half2 h1 = __floats2half2_rn(v.z, v.w);
    return make_uint2(*(unsigned*)&h0, *(unsigned*)&h1);
}

// ---------------- preprocessing ----------------
// convert x/W1/W2 -> half AND count in-degrees (g_cnt assumed pre-zeroed)
__global__ void k_prep(const float* __restrict__ x, const float* __restrict__ W1,
                       const float* __restrict__ W2, const int* __restrict__ dst,
                       int n, int e) {
    int stride = gridDim.x * blockDim.x;
    int gtid = blockIdx.x * blockDim.x + threadIdx.x;
    int total = n * (D1 / 4);   // float4 groups
    for (int i = gtid; i < total; i += stride) {
        ((uint2*)g_xh)[i] = f4_to_h4(__ldg(((const float4*)x) + i));
        if (i < (D1 * D1) / 4) ((uint2*)g_w1h)[i] = f4_to_h4(__ldg(((const float4*)W1) + i));
        if (i < (D1 * D2) / 4) ((uint2*)g_w2h)[i] = f4_to_h4(__ldg(((const float4*)W2) + i));
    }
    for (int j = gtid; j < e; j += stride)
        atomicAdd(&g_cnt[dst[j]], 1);
}

__global__ void k_dinvreduce(int n) {
    __shared__ int s[256];
    int t = threadIdx.x;
    int i = blockIdx.x * 256 + t;
    int d = 0;
    if (i < n) {
        d = g_cnt[i];
        g_dinv1[i] = d > 0 ? rsqrtf((float)d) : 0.f;
        g_dinv2[i] = rsqrtf((float)(d + 1));
    }
    s[t] = d;
    __syncthreads();
    for (int o = 128; o; o >>= 1) { if (t < o) s[t] += s[t + o]; __syncthreads(); }
    if (t == 0) g_part[blockIdx.x] = s[0];
}

__global__ void k_scatter(int nparts, int n) {
    __shared__ int spart[NPARTMAX];
    __shared__ int s[256];
    __shared__ int red[8];
    int t = threadIdx.x;
    int b = blockIdx.x;

    for (int i = t; i < nparts; i += 256) spart[i] = g_part[i];
    __syncthreads();

    int loc = 0;
    for (int i = t; i < b; i += 256) loc += spart[i];
#pragma unroll
    for (int o = 16; o; o >>= 1) loc += __shfl_xor_sync(~0u, loc, o);
    if ((t & 31) == 0) red[t >> 5] = loc;
    __syncthreads();
    int blockpre = red[0] + red[1] + red[2] + red[3] + red[4] + red[5] + red[6] + red[7];

    if (b == 0 && t == 0) {
        int tot = 0;
        for (int i = 0; i < nparts; i++) tot += spart[i];
        g_rowptr[n] = tot;
    }

    int i = b * 256 + t;
    int v = (i < n) ? g_cnt[i] : 0;
    s[t] = v;
    __syncthreads();
    for (int o = 1; o < 256; o <<= 1) {
        int x = (t >= o) ? s[t - o] : 0;
        __syncthreads();
        s[t] += x;
        __syncthreads();
    }
    if (i < n) g_rowptr[i] = blockpre + s[t] - v;
}

__global__ void k_fill(const int* __restrict__ src, const int* __restrict__ dst, int e) {
    int i = blockIdx.x * blockDim.x + threadIdx.x;
    if (i < e) {
        int d = dst[i];
        int p = g_rowptr[d] + atomicAdd(&g_woff[d], 1);
        g_col[p] = src[i];
    }
}

// ---------------- 256-dim half->half propagation hop (8-edge MLP) ----------------
// Also restores g_cnt/g_woff to 0 for the next kernel_launch call (idempotent).
__global__ void __launch_bounds__(256) k_hop_h(
    const __half* __restrict__ xin, __half* __restrict__ xout,
    const float* __restrict__ dinv, const int* __restrict__ rowptr,
    const int* __restrict__ colidx, float coeff, int n)
{
    int node = (blockIdx.x * blockDim.x + threadIdx.x) >> 5;
    int lane = threadIdx.x & 31;
    if (node >= n) return;
    int beg = rowptr[node], end = rowptr[node + 1];

    if (lane == 0) { g_cnt[node] = 0; g_woff[node] = 0; }

    float2 a[4];
#pragma unroll
    for (int q = 0; q < 4; q++) a[q] = make_float2(0.f, 0.f);

    for (int e0 = beg; e0 < end; e0 += 32) {
        int idx = e0 + lane;
        int c = 0; float w = 0.f;
        if (idx < end) { c = colidx[idx]; w = __ldg(dinv + c); }
        int cnt = min(32, end - e0);
        int j = 0;
        for (; j + 8 <= cnt; j += 8) {
            int cc[8]; float ww[8];
#pragma unroll
            for (int q = 0; q < 8; q++) {
                cc[q] = __shfl_sync(~0u, c, j + q);
                ww[q] = __shfl_sync(~0u, w, j + q);
            }
            float4 v[8];
#pragma unroll
            for (int q = 0; q < 8; q++)
                v[q] = __ldg(((const float4*)(xin + (size_t)cc[q] * D1)) + lane);
#pragma unroll
            for (int q = 0; q < 8; q++) acch8(a, ww[q], v[q]);
        }
        for (; j < cnt; j++) {
            int   cj = __shfl_sync(~0u, c, j);
            float wj = __shfl_sync(~0u, w, j);
            float4 v = __ldg(((const float4*)(xin + (size_t)cj * D1)) + lane);
            acch8(a, wj, v);
        }
    }

    float s = coeff * __ldg(dinv + node);
    __half2 o0 = __floats2half2_rn(s * a[0].x, s * a[0].y);
    __half2 o1 = __floats2half2_rn(s * a[1].x, s * a[1].y);
    __half2 o2 = __floats2half2_rn(s * a[2].x, s * a[2].y);
    __half2 o3 = __floats2half2_rn(s * a[3].x, s * a[3].y);
    uint4 u;
    u.x = *(unsigned*)&o0; u.y = *(unsigned*)&o1;
    u.z = *(unsigned*)&o2; u.w = *(unsigned*)&o3;
    ((uint4*)(xout + (size_t)node * D1))[lane] = u;
}

// ---------------- GEMM1 + fused bias/SELU epilogue -> half ----------------
__global__ void __launch_bounds__(256) k_gemm1(
    const __half* __restrict__ A, const __half* __restrict__ B,
    const float* __restrict__ bias, __half* __restrict__ Cg)
{
    const int BM = 128, BN = 128, BK = 32;
    const int AS_BYTES = BM * (BK + 8) * 2;             // 10240
    const int BS_BYTES = BK * (BN + 8) * 2;             // 8704
    const int CS_BYTES = 8 * 16 * 68 * 4;               // 34816
    __shared__ __align__(16) char smem_buf[CS_BYTES > AS_BYTES + BS_BYTES ? CS_BYTES : AS_BYTES + BS_BYTES];

    __half (*As)[BK + 8] = reinterpret_cast<__half(*)[BK + 8]>(smem_buf);
    __half (*Bs)[BN + 8] = reinterpret_cast<__half(*)[BN + 8]>(smem_buf + AS_BYTES);
    float  (*Cs)[68]     = reinterpret_cast<float(*)[68]>(smem_buf);  // reused after mainloop

    int tid  = threadIdx.x;
    int warp = tid >> 5;
    int lane = tid & 31;
    int wm = warp >> 1;
    int wn = warp & 1;
    int bm = blockIdx.x * BM;
    int bn = blockIdx.y * BN;

    wmma::fragment<wmma::accumulator, 16, 16, 16, float> acc[2][4];
#pragma unroll
    for (int r = 0; r < 2; r++)
#pragma unroll
        for (int c = 0; c < 4; c++) wmma::fill_fragment(acc[r][c], 0.f);

    for (int k0 = 0; k0 < D1; k0 += BK) {
#pragma unroll
        for (int q = tid; q < (BM * BK) / 8; q += 256) {
            int r  = q >> 2;
            int ch = (q & 3) * 8;
            *(uint4*)&As[r][ch] = *(const uint4*)(A + (size_t)(bm + r) * D1 + k0 + ch);
        }
#pragma unroll
        for (int q = tid; q < (BK * BN) / 8; q += 256) {
            int r  = q >> 4;
            int ch = (q & 15) * 8;
            *(uint4*)&Bs[r][ch] = *(const uint4*)(B + (size_t)(k0 + r) * D1 + bn + ch);
        }
        __syncthreads();
#pragma unroll
        for (int kk = 0; kk < BK; kk += 16) {
            wmma::fragment<wmma::matrix_a, 16, 16, 16, __half, wmma::row_major> af[2];
            wmma::fragment<wmma::matrix_b, 16, 16, 16, __half, wmma::row_major> bf[4];
#pragma unroll
            for (int r = 0; r < 2; r++)
                wmma::load_matrix_sync(af[r], &As[wm * 32 + r * 16][kk], BK + 8);
#pragma unroll
            for (int c = 0; c < 4; c++)
                wmma::load_matrix_sync(bf[c], &Bs[kk][wn * 64 + c * 16], BN + 8);
#pragma unroll
            for (int r = 0; r < 2; r++)
#pragma unroll
                for (int c = 0; c < 4; c++)
                    wmma::mma_sync(acc[r][c], af[r], bf[c], acc[r][c]);
        }
        __syncthreads();
    }

    int colbase = bn + wn * 64;
    float bl[32];
    {
        int cb = colbase + (lane & 1) * 32;
#pragma unroll
        for (int ch = 0; ch < 8; ch++) {
            float4 b4 = __ldg((const float4*)(bias + cb + ch * 4));
            bl[ch * 4 + 0] = b4.x; bl[ch * 4 + 1] = b4.y;
            bl[ch * 4 + 2] = b4.z; bl[ch * 4 + 3] = b4.w;
        }
    }
#pragma unroll
    for (int r = 0; r < 2; r++) {
#pragma unroll
        for (int c = 0; c < 4; c++)
            wmma::store_matrix_sync(&Cs[warp * 16][c * 16], acc[r][c], 68, wmma::mem_row_major);
        __syncwarp();
        int row = lane >> 1;
        int half_sel = (lane & 1) * 32;
        float* rowp = &Cs[warp * 16 + row][half_sel];
        size_t grow = (size_t)(bm + wm * 32 + r * 16 + row) * D1 + colbase + half_sel;
#pragma unroll
        for (int ch = 0; ch < 4; ch++) {
            float4 v0 = make_float4(selu_f(rowp[ch * 8 + 0] + bl[ch * 8 + 0]),
                                    selu_f(rowp[ch * 8 + 1] + bl[ch * 8 + 1]),
                                    selu_f(rowp[ch * 8 + 2] + bl[ch * 8 + 2]),
                                    selu_f(rowp[ch * 8 + 3] + bl[ch * 8 + 3]));
            float4 v1 = make_float4(selu_f(rowp[ch * 8 + 4] + bl[ch * 8 + 4]),
                                    selu_f(rowp[ch * 8 + 5] + bl[ch * 8 + 5]),
                                    selu_f(rowp[ch * 8 + 6] + bl[ch * 8 + 6]),
                                    selu_f(rowp[ch * 8 + 7] + bl[ch * 8 + 7]));
            uint2 pa = f4_to_h4(v0);
            uint2 pb = f4_to_h4(v1);
            *(uint4*)(Cg + grow + ch * 8) = make_uint4(pa.x, pa.y, pb.x, pb.y);
        }
        __syncwarp();
    }
}

// ---------------- GEMM2 (smem-staged wmma, half out) ----------------
__global__ void __launch_bounds__(256) k_gemm2(
    const __half* __restrict__ A, const __half* __restrict__ B, __half* __restrict__ Cg)
{
    const int BM = 128, BN = 64, BK = 32;
    __shared__ __half As[BM][BK + 8];
    __shared__ __half Bs[BK][BN + 8];
    __shared__ float  Cs[8][32][36];

    int tid  = threadIdx.x;
    int warp = tid >> 5;
    int lane = tid & 31;
    int wm = warp >> 1;
    int wn = warp & 1;
    int bm = blockIdx.x * BM;

    wmma::fragment<wmma::accumulator, 16, 16, 16, float> acc[2][2];
#pragma unroll
    for (int r = 0; r < 2; r++)
#pragma unroll
        for (int c = 0; c < 2; c++) wmma::fill_fragment(acc[r][c], 0.f);

    for (int k0 = 0; k0 < D1; k0 += BK) {
#pragma unroll
        for (int q = tid; q < (BM * BK) / 8; q += 256) {
            int r  = q >> 2;
            int ch = (q & 3) * 8;
            *(uint4*)&As[r][ch] = *(const uint4*)(A + (size_t)(bm + r) * D1 + k0 + ch);
        }
        {
            int r  = tid >> 3;
            int ch = (tid & 7) * 8;
            *(uint4*)&Bs[r][ch] = *(const uint4*)(B + (size_t)(k0 + r) * D2 + ch);
        }
        __syncthreads();
#pragma unroll
        for (int kk = 0; kk < BK; kk += 16) {
            wmma::fragment<wmma::matrix_a, 16, 16, 16, __half, wmma::row_major> af[2];
            wmma::fragment<wmma::matrix_b, 16, 16, 16, __half, wmma::row_major> bf[2];
#pragma unroll
            for (int r = 0; r < 2; r++)
                wmma::load_matrix_sync(af[r], &As[wm * 32 + r * 16][kk], BK + 8);
#pragma unroll
            for (int c = 0; c < 2; c++)
                wmma::load_matrix_sync(bf[c], &Bs[kk][wn * 32 + c * 16], BN + 8);
#pragma unroll
            for (int r = 0; r < 2; r++)
#pragma unroll
                for (int c = 0; c < 2; c++)
                    wmma::mma_sync(acc[r][c], af[r], bf[c], acc[r][c]);
        }
        __syncthreads();
    }

#pragma unroll
    for (int r = 0; r < 2; r++)
#pragma unroll
        for (int c = 0; c < 2; c++)
            wmma::store_matrix_sync(&Cs[warp][r * 16][c * 16], acc[r][c], 36, wmma::mem_row_major);
    __syncwarp();

    float* rowp = &Cs[warp][lane][0];
    size_t grow = (size_t)(bm + wm * 32 + lane) * D2 + wn * 32;
#pragma unroll
    for (int ch = 0; ch < 4; ch++) {
        float4 v0 = make_float4(rowp[ch * 8 + 0], rowp[ch * 8 + 1], rowp[ch * 8 + 2], rowp[ch * 8 + 3]);
        float4 v1 = make_float4(rowp[ch * 8 + 4], rowp[ch * 8 + 5], rowp[ch * 8 + 6], rowp[ch * 8 + 7]);
        uint2 a = f4_to_h4(v0);
        uint2 b = f4_to_h4(v1);
        *(uint4*)(Cg + grow + ch * 8) = make_uint4(a.x, a.y, b.x, b.y);
    }
}

// ---------------- final hop (D=64, self loops, half gather, 8-edge MLP) ----------------
__global__ void __launch_bounds__(256) k_out(
    const float* __restrict__ dinv2,
    const int* __restrict__ rowptr, const int* __restrict__ colidx,
    const float* __restrict__ b2, float* __restrict__ out, int n)
{
    int node = (blockIdx.x * blockDim.x + threadIdx.x) >> 5;
    int lane = threadIdx.x & 31;
    if (node >= n) return;
    int beg = rowptr[node], end = rowptr[node + 1];

    float di = __ldg(dinv2 + node);
    float2 sv = __half22float2(__ldg(((const __half2*)(g_gh + (size_t)node * D2)) + lane));
    float ax = di * sv.x;
    float ay = di * sv.y;

    for (int e0 = beg; e0 < end; e0 += 32) {
        int idx = e0 + lane;
        int c = 0; float w = 0.f;
        if (idx < end) { c = colidx[idx]; w = __ldg(dinv2 + c); }
        int cnt = min(32, end - e0);
        int j = 0;
        for (; j + 8 <= cnt; j += 8) {
            int cc[8]; float ww[8];
#pragma unroll
            for (int q = 0; q < 8; q++) {
                cc[q] = __shfl_sync(~0u, c, j + q);
                ww[q] = __shfl_sync(~0u, w, j + q);
            }
            float2 v[8];
#pragma unroll
            for (int q = 0; q < 8; q++)
                v[q] = __half22float2(__ldg(((const __half2*)(g_gh + (size_t)cc[q] * D2)) + lane));
#pragma unroll
            for (int q = 0; q < 8; q++) {
                ax = fmaf(ww[q], v[q].x, ax);
                ay = fmaf(ww[q], v[q].y, ay);
            }
        }
        for (; j < cnt; j++) {
            int   cj = __shfl_sync(~0u, c, j);
            float wj = __shfl_sync(~0u, w, j);
            float2 v = __half22float2(__ldg(((const __half2*)(g_gh + (size_t)cj * D2)) + lane));
            ax = fmaf(wj, v.x, ax); ay = fmaf(wj, v.y, ay);
        }
    }

    float p0 = di * ax + __ldg(b2 + lane * 2);
    float p1 = di * ay + __ldg(b2 + lane * 2 + 1);

    float m = fmaxf(p0, p1);
#pragma unroll
    for (int o = 16; o; o >>= 1) m = fmaxf(m, __shfl_xor_sync(~0u, m, o));
    float esum = expf(p0 - m) + expf(p1 - m);
#pragma unroll
    for (int o = 16; o; o >>= 1) esum += __shfl_xor_sync(~0u, esum, o);
    float lse = m + logf(esum);

    float2 res = make_float2(p0 - lse, p1 - lse);
    ((float2*)(out + (size_t)node * D2))[lane] = res;
}

// ---------------- launch ----------------
extern "C" void kernel_launch(void* const* d_in, const int* in_sizes, int n_in,
                              void* d_out, int out_size) {
    const float* x    = (const float*)d_in[0];
    const int*   esrc = (const int*)d_in[1];
    const int*   edst = (const int*)d_in[2];
    const float* W1   = (const float*)d_in[3];
    const float* b1   = (const float*)d_in[4];
    const float* W2   = (const float*)d_in[5];
    const float* b2   = (const float*)d_in[6];
    float* out = (float*)d_out;

    int n = in_sizes[0] / D1;   // 100000
    int e = in_sizes[1];        // 3200000

    __half *xh, *h1, *h2, *w1h, *w2h, *acth, *gh;
    float *dinv1, *dinv2;
    int *rowptr, *colidx;
    cudaGetSymbolAddress((void**)&xh, g_xh);
    cudaGetSymbolAddress((void**)&h1, g_h1);
    cudaGetSymbolAddress((void**)&h2, g_h2);
    cudaGetSymbolAddress((void**)&w1h, g_w1h);
    cudaGetSymbolAddress((void**)&w2h, g_w2h);
    cudaGetSymbolAddress((void**)&acth, g_acth);
    cudaGetSymbolAddress((void**)&gh, g_gh);
    cudaGetSymbolAddress((void**)&dinv1, g_dinv1);
    cudaGetSymbolAddress((void**)&dinv2, g_dinv2);
    cudaGetSymbolAddress((void**)&rowptr, g_rowptr);
    cudaGetSymbolAddress((void**)&colidx, g_col);

    int nb = (n + 255) / 256;          // 391
    int eb = (e + 255) / 256;
    int hopBlocks = (n * 32 + 255) / 256;

    // preprocessing (count fused into prep; cnt/woff restored to 0 by k_hop_h)
    k_prep<<<2048, 256>>>(x, W1, W2, edst, n, e);
    k_dinvreduce<<<nb, 256>>>(n);
    k_scatter<<<nb, 256>>>(nb, n);
    k_fill<<<eb, 256>>>(esrc, edst, e);

    // conv1: two hops (half path)
    k_hop_h<<<hopBlocks, 256>>>(xh, h1, dinv1, rowptr, colidx, 1.0f, n);
    k_hop_h<<<hopBlocks, 256>>>(h1, h2, dinv1, rowptr, colidx, 0.36787944117144233f, n);

    // GEMM1 (tensor cores) with fused bias+SELU epilogue -> half
    dim3 g1(NNP / 128, 2);
    k_gemm1<<<g1, 256>>>(h2, w1h, b1, acth);

    // GEMM2 (tensor cores, half out)
    k_gemm2<<<NNP / 128, 256>>>(acth, w2h, gh);

    k_out<<<hopBlocks, 256>>>(dinv2, rowptr, colidx, b2, out, n);
}

// round 10
// speedup vs baseline: 2.9721x; 1.1020x over previous
#include <cuda_runtime.h>
#include <cuda_fp16.h>
#include <mma.h>
#include <math.h>

using namespace nvcuda;

#define NN 100000
#define NNP 100096           // padded to multiple of 128 for wmma tiles
#define NE 3200000
#define D1 256
#define D2 64
#define NPARTMAX 512

// ---------------- static device scratch ----------------
// g_cnt is zero on first call and re-zeroed by k_convx every call.
// g_woff is (re)initialized by k_scatter every call.
__device__ int    g_cnt[NN];
__device__ int    g_woff[NN];
__device__ int    g_rowptr[NN + 1];
__device__ int    g_part[NPARTMAX];
__device__ int    g_col[NE];
__device__ float  g_dinv1[NN];
__device__ float  g_dinv2[NN];
__device__ __half g_xh[(size_t)NN * D1];     // u0 = dinv1[i] * x[i,:] in half
__device__ __half g_h1[(size_t)NN * D1];     // u1 = dinv1^2 * (A u0)
__device__ __half g_h2[(size_t)NNP * D1];    // coeff * dinv1 * (A u1)  (pad rows stay 0)
__device__ __half g_w1h[D1 * D1];            // W1 half
__device__ __half g_w2h[D1 * D2];            // W2 half
__device__ __half g_acth[(size_t)NNP * D1];  // selu(h2@W1+b1) in half
__device__ __half g_gh[(size_t)NNP * D2];    // dinv2[i] * (acth@W2)[i,:] in half

// ---------------- helpers ----------------
__device__ __forceinline__ float selu_f(float x) {
    const float sc = 1.0507009873554804934f;
    const float al = 1.6732632423543772848f;
    return x > 0.f ? sc * x : sc * al * expm1f(x);
}

__device__ __forceinline__ void addh8(float2 a[4], float4 v) {
    __half2* hp = (__half2*)&v;
#pragma unroll
    for (int q = 0; q < 4; q++) {
        float2 f = __half22float2(hp[q]);
        a[q].x += f.x;
        a[q].y += f.y;
    }
}

__device__ __forceinline__ uint2 f4_to_h4(float4 v) {
    __half2 h0 = __floats2half2_rn(v.x, v.y);
    __half2 h1 = __floats2half2_rn(v.z, v.w);
    return make_uint2(*(unsigned*)&h0, *(unsigned*)&h1);
}

// ---------------- preprocessing ----------------
// count in-degrees (g_cnt pre-zeroed) + convert W1/W2 to half
__global__ void k_count(const int* __restrict__ dst, const float* __restrict__ W1,
                        const float* __restrict__ W2, int e) {
    int stride = gridDim.x * blockDim.x;
    int gtid = blockIdx.x * blockDim.x + threadIdx.x;
    for (int j = gtid; j < e; j += stride)
        atomicAdd(&g_cnt[dst[j]], 1);
    if (gtid < (D1 * D1) / 4) ((uint2*)g_w1h)[gtid] = f4_to_h4(__ldg(((const float4*)W1) + gtid));
    if (gtid < (D1 * D2) / 4) ((uint2*)g_w2h)[gtid] = f4_to_h4(__ldg(((const float4*)W2) + gtid));
}

__global__ void k_dinvreduce(int n) {
    __shared__ int s[256];
    int t = threadIdx.x;
    int i = blockIdx.x * 256 + t;
    int d = 0;
    if (i < n) {
        d = g_cnt[i];
        g_dinv1[i] = d > 0 ? rsqrtf((float)d) : 0.f;
        g_dinv2[i] = rsqrtf((float)(d + 1));
    }
    s[t] = d;
    __syncthreads();
    for (int o = 128; o; o >>= 1) { if (t < o) s[t] += s[t + o]; __syncthreads(); }
    if (t == 0) g_part[blockIdx.x] = s[0];
}

// writes rowptr AND initializes g_woff = rowptr (fill uses woff directly)
__global__ void k_scatter(int nparts, int n) {
    __shared__ int spart[NPARTMAX];
    __shared__ int s[256];
    __shared__ int red[8];
    int t = threadIdx.x;
    int b = blockIdx.x;

    for (int i = t; i < nparts; i += 256) spart[i] = g_part[i];
    __syncthreads();

    int loc = 0;
    for (int i = t; i < b; i += 256) loc += spart[i];
#pragma unroll
    for (int o = 16; o; o >>= 1) loc += __shfl_xor_sync(~0u, loc, o);
    if ((t & 31) == 0) red[t >> 5] = loc;
    __syncthreads();
    int blockpre = red[0] + red[1] + red[2] + red[3] + red[4] + red[5] + red[6] + red[7];

    if (b == 0 && t == 0) {
        int tot = 0;
        for (int i = 0; i < nparts; i++) tot += spart[i];
        g_rowptr[n] = tot;
    }

    int i = b * 256 + t;
    int v = (i < n) ? g_cnt[i] : 0;
    s[t] = v;
    __syncthreads();
    for (int o = 1; o < 256; o <<= 1) {
        int x = (t >= o) ? s[t - o] : 0;
        __syncthreads();
        s[t] += x;
        __syncthreads();
    }
    if (i < n) {
        int rp = blockpre + s[t] - v;
        g_rowptr[i] = rp;
        g_woff[i] = rp;
    }
}

// fill CSR columns; woff IS the running write pointer (no rowptr gather)
__global__ void k_fill(const int* __restrict__ src, const int* __restrict__ dst, int e) {
    int i = blockIdx.x * blockDim.x + threadIdx.x;
    if (i < e) {
        int p = atomicAdd(&g_woff[dst[i]], 1);
        g_col[p] = src[i];
    }
}

// convert x -> half, pre-scaled by dinv1[row]; also restore g_cnt = 0
__global__ void k_convx(const float* __restrict__ x, int n) {
    int stride = gridDim.x * blockDim.x;
    int total = n * (D1 / 4);
    for (int i = blockIdx.x * blockDim.x + threadIdx.x; i < total; i += stride) {
        int row = i >> 6;               // 64 float4 groups per row
        float s = __ldg(g_dinv1 + row);
        float4 v = __ldg(((const float4*)x) + i);
        v.x *= s; v.y *= s; v.z *= s; v.w *= s;
        ((uint2*)g_xh)[i] = f4_to_h4(v);
        if (i < n) g_cnt[i] = 0;
    }
}

// ---------------- weightless 256-dim propagation hop ----------------
// out[i] = scale_i * sum_{j in row i} in[col_j],
// scale_i = dinv1[i]^2 (hop1) or coeff*dinv1[i] (hop2)
template<bool SQUARED>
__global__ void __launch_bounds__(256) k_hop_h(
    const __half* __restrict__ xin, __half* __restrict__ xout,
    const float* __restrict__ dinv, const int* __restrict__ rowptr,
    const int* __restrict__ colidx, float coeff, int n)
{
    int node = (blockIdx.x * blockDim.x + threadIdx.x) >> 5;
    int lane = threadIdx.x & 31;
    if (node >= n) return;
    int beg = rowptr[node], end = rowptr[node + 1];

    float2 a[4];
#pragma unroll
    for (int q = 0; q < 4; q++) a[q] = make_float2(0.f, 0.f);

    for (int e0 = beg; e0 < end; e0 += 32) {
        int idx = e0 + lane;
        int c = (idx < end) ? colidx[idx] : 0;
        int cnt = min(32, end - e0);
        int j = 0;
        for (; j + 8 <= cnt; j += 8) {
            int cc[8];
#pragma unroll
            for (int q = 0; q < 8; q++) cc[q] = __shfl_sync(~0u, c, j + q);
            float4 v[8];
#pragma unroll
            for (int q = 0; q < 8; q++)
                v[q] = __ldg(((const float4*)(xin + (size_t)cc[q] * D1)) + lane);
#pragma unroll
            for (int q = 0; q < 8; q++) addh8(a, v[q]);
        }
        for (; j < cnt; j++) {
            int cj = __shfl_sync(~0u, c, j);
            addh8(a, __ldg(((const float4*)(xin + (size_t)cj * D1)) + lane));
        }
    }

    float d = __ldg(dinv + node);
    float s = SQUARED ? d * d : coeff * d;
    __half2 o0 = __floats2half2_rn(s * a[0].x, s * a[0].y);
    __half2 o1 = __floats2half2_rn(s * a[1].x, s * a[1].y);
    __half2 o2 = __floats2half2_rn(s * a[2].x, s * a[2].y);
    __half2 o3 = __floats2half2_rn(s * a[3].x, s * a[3].y);
    uint4 u;
    u.x = *(unsigned*)&o0; u.y = *(unsigned*)&o1;
    u.z = *(unsigned*)&o2; u.w = *(unsigned*)&o3;
    ((uint4*)(xout + (size_t)node * D1))[lane] = u;
}

// ---------------- GEMM1 + fused bias/SELU epilogue -> half ----------------
__global__ void __launch_bounds__(256) k_gemm1(
    const __half* __restrict__ A, const __half* __restrict__ B,
    const float* __restrict__ bias, __half* __restrict__ Cg)
{
    const int BM = 128, BN = 128, BK = 32;
    const int AS_BYTES = BM * (BK + 8) * 2;
    const int BS_BYTES = BK * (BN + 8) * 2;
    const int CS_BYTES = 8 * 16 * 68 * 4;
    __shared__ __align__(16) char smem_buf[CS_BYTES > AS_BYTES + BS_BYTES ? CS_BYTES : AS_BYTES + BS_BYTES];

    __half (*As)[BK + 8] = reinterpret_cast<__half(*)[BK + 8]>(smem_buf);
    __half (*Bs)[BN + 8] = reinterpret_cast<__half(*)[BN + 8]>(smem_buf + AS_BYTES);
    float  (*Cs)[68]     = reinterpret_cast<float(*)[68]>(smem_buf);

    int tid  = threadIdx.x;
    int warp = tid >> 5;
    int lane = tid & 31;
    int wm = warp >> 1;
    int wn = warp & 1;
    int bm = blockIdx.x * BM;
    int bn = blockIdx.y * BN;

    wmma::fragment<wmma::accumulator, 16, 16, 16, float> acc[2][4];
#pragma unroll
    for (int r = 0; r < 2; r++)
#pragma unroll
        for (int c = 0; c < 4; c++) wmma::fill_fragment(acc[r][c], 0.f);

    for (int k0 = 0; k0 < D1; k0 += BK) {
#pragma unroll
        for (int q = tid; q < (BM * BK) / 8; q += 256) {
            int r  = q >> 2;
            int ch = (q & 3) * 8;
            *(uint4*)&As[r][ch] = *(const uint4*)(A + (size_t)(bm + r) * D1 + k0 + ch);
        }
#pragma unroll
        for (int q = tid; q < (BK * BN) / 8; q += 256) {
            int r  = q >> 4;
            int ch = (q & 15) * 8;
            *(uint4*)&Bs[r][ch] = *(const uint4*)(B + (size_t)(k0 + r) * D1 + bn + ch);
        }
        __syncthreads();
#pragma unroll
        for (int kk = 0; kk < BK; kk += 16) {
            wmma::fragment<wmma::matrix_a, 16, 16, 16, __half, wmma::row_major> af[2];
            wmma::fragment<wmma::matrix_b, 16, 16, 16, __half, wmma::row_major> bf[4];
#pragma unroll
            for (int r = 0; r < 2; r++)
                wmma::load_matrix_sync(af[r], &As[wm * 32 + r * 16][kk], BK + 8);
#pragma unroll
            for (int c = 0; c < 4; c++)
                wmma::load_matrix_sync(bf[c], &Bs[kk][wn * 64 + c * 16], BN + 8);
#pragma unroll
            for (int r = 0; r < 2; r++)
#pragma unroll
                for (int c = 0; c < 4; c++)
                    wmma::mma_sync(acc[r][c], af[r], bf[c], acc[r][c]);
        }
        __syncthreads();
    }

    int colbase = bn + wn * 64;
    float bl[32];
    {
        int cb = colbase + (lane & 1) * 32;
#pragma unroll
        for (int ch = 0; ch < 8; ch++) {
            float4 b4 = __ldg((const float4*)(bias + cb + ch * 4));
            bl[ch * 4 + 0] = b4.x; bl[ch * 4 + 1] = b4.y;
            bl[ch * 4 + 2] = b4.z; bl[ch * 4 + 3] = b4.w;
        }
    }
#pragma unroll
    for (int r = 0; r < 2; r++) {
#pragma unroll
        for (int c = 0; c < 4; c++)
            wmma::store_matrix_sync(&Cs[warp * 16][c * 16], acc[r][c], 68, wmma::mem_row_major);
        __syncwarp();
        int row = lane >> 1;
        int half_sel = (lane & 1) * 32;
        float* rowp = &Cs[warp * 16 + row][half_sel];
        size_t grow = (size_t)(bm + wm * 32 + r * 16 + row) * D1 + colbase + half_sel;
#pragma unroll
        for (int ch = 0; ch < 4; ch++) {
            float4 v0 = make_float4(selu_f(rowp[ch * 8 + 0] + bl[ch * 8 + 0]),
                                    selu_f(rowp[ch * 8 + 1] + bl[ch * 8 + 1]),
                                    selu_f(rowp[ch * 8 + 2] + bl[ch * 8 + 2]),
                                    selu_f(rowp[ch * 8 + 3] + bl[ch * 8 + 3]));
            float4 v1 = make_float4(selu_f(rowp[ch * 8 + 4] + bl[ch * 8 + 4]),
                                    selu_f(rowp[ch * 8 + 5] + bl[ch * 8 + 5]),
                                    selu_f(rowp[ch * 8 + 6] + bl[ch * 8 + 6]),
                                    selu_f(rowp[ch * 8 + 7] + bl[ch * 8 + 7]));
            uint2 pa = f4_to_h4(v0);
            uint2 pb = f4_to_h4(v1);
            *(uint4*)(Cg + grow + ch * 8) = make_uint4(pa.x, pa.y, pb.x, pb.y);
        }
        __syncwarp();
    }
}

// ---------------- GEMM2 (half out, rows pre-scaled by dinv2) ----------------
__global__ void __launch_bounds__(256) k_gemm2(
    const __half* __restrict__ A, const __half* __restrict__ B,
    const float* __restrict__ dinv2, __half* __restrict__ Cg, int n)
{
    const int BM = 128, BN = 64, BK = 32;
    __shared__ __half As[BM][BK + 8];
    __shared__ __half Bs[BK][BN + 8];
    __shared__ float  Cs[8][32][36];

    int tid  = threadIdx.x;
    int warp = tid >> 5;
    int lane = tid & 31;
    int wm = warp >> 1;
    int wn = warp & 1;
    int bm = blockIdx.x * BM;

    wmma::fragment<wmma::accumulator, 16, 16, 16, float> acc[2][2];
#pragma unroll
    for (int r = 0; r < 2; r++)
#pragma unroll
        for (int c = 0; c < 2; c++) wmma::fill_fragment(acc[r][c], 0.f);

    for (int k0 = 0; k0 < D1; k0 += BK) {
#pragma unroll
        for (int q = tid; q < (BM * BK) / 8; q += 256) {
            int r  = q >> 2;
            int ch = (q & 3) * 8;
            *(uint4*)&As[r][ch] = *(const uint4*)(A + (size_t)(bm + r) * D1 + k0 + ch);
        }
        {
            int r  = tid >> 3;
            int ch = (tid & 7) * 8;
            *(uint4*)&Bs[r][ch] = *(const uint4*)(B + (size_t)(k0 + r) * D2 + ch);
        }
        __syncthreads();
#pragma unroll
        for (int kk = 0; kk < BK; kk += 16) {
            wmma::fragment<wmma::matrix_a, 16, 16, 16, __half, wmma::row_major> af[2];
            wmma::fragment<wmma::matrix_b, 16, 16, 16, __half, wmma::row_major> bf[2];
#pragma unroll
            for (int r = 0; r < 2; r++)
                wmma::load_matrix_sync(af[r], &As[wm * 32 + r * 16][kk], BK + 8);
#pragma unroll
            for (int c = 0; c < 2; c++)
                wmma::load_matrix_sync(bf[c], &Bs[kk][wn * 32 + c * 16], BN + 8);
#pragma unroll
            for (int r = 0; r < 2; r++)
#pragma unroll
                for (int c = 0; c < 2; c++)
                    wmma::mma_sync(acc[r][c], af[r], bf[c], acc[r][c]);
        }
        __syncthreads();
    }

#pragma unroll
    for (int r = 0; r < 2; r++)
#pragma unroll
        for (int c = 0; c < 2; c++)
            wmma::store_matrix_sync(&Cs[warp][r * 16][c * 16], acc[r][c], 36, wmma::mem_row_major);
    __syncwarp();

    int row = bm + wm * 32 + lane;
    float dv = (row < n) ? __ldg(dinv2 + row) : 0.f;
    float* rowp = &Cs[warp][lane][0];
    size_t grow = (size_t)row * D2 + wn * 32;
#pragma unroll
    for (int ch = 0; ch < 4; ch++) {
        float4 v0 = make_float4(dv * rowp[ch * 8 + 0], dv * rowp[ch * 8 + 1],
                                dv * rowp[ch * 8 + 2], dv * rowp[ch * 8 + 3]);
        float4 v1 = make_float4(dv * rowp[ch * 8 + 4], dv * rowp[ch * 8 + 5],
                                dv * rowp[ch * 8 + 6], dv * rowp[ch * 8 + 7]);
        uint2 a = f4_to_h4(v0);
        uint2 b = f4_to_h4(v1);
        *(uint4*)(Cg + grow + ch * 8) = make_uint4(a.x, a.y, b.x, b.y);
    }
}

// ---------------- final hop (weightless gather of gh=D2*g) + bias + log_softmax ----------------
__global__ void __launch_bounds__(256) k_out(
    const float* __restrict__ dinv2,
    const int* __restrict__ rowptr, const int* __restrict__ colidx,
    const float* __restrict__ b2, float* __restrict__ out, int n)
{
    int node = (blockIdx.x * blockDim.x + threadIdx.x) >> 5;
    int lane = threadIdx.x & 31;
    if (node >= n) return;
    int beg = rowptr[node], end = rowptr[node + 1];

    // self loop term (gh already scaled by dinv2)
    float2 sv = __half22float2(__ldg(((const __half2*)(g_gh + (size_t)node * D2)) + lane));
    float ax = sv.x;
    float ay = sv.y;

    for (int e0 = beg; e0 < end; e0 += 32) {
        int idx = e0 + lane;
        int c = (idx < end) ? colidx[idx] : 0;
        int cnt = min(32, end - e0);
        int j = 0;
        for (; j + 8 <= cnt; j += 8) {
            int cc[8];
#pragma unroll
            for (int q = 0; q < 8; q++) cc[q] = __shfl_sync(~0u, c, j + q);
            float2 v[8];
#pragma unroll
            for (int q = 0; q < 8; q++)
                v[q] = __half22float2(__ldg(((const __half2*)(g_gh + (size_t)cc[q] * D2)) + lane));
#pragma unroll
            for (int q = 0; q < 8; q++) { ax += v[q].x; ay += v[q].y; }
        }
        for (; j < cnt; j++) {
            int cj = __shfl_sync(~0u, c, j);
            float2 v = __half22float2(__ldg(((const __half2*)(g_gh + (size_t)cj * D2)) + lane));
            ax += v.x; ay += v.y;
        }
    }

    float di = __ldg(dinv2 + node);
    float p0 = di * ax + __ldg(b2 + lane * 2);
    float p1 = di * ay + __ldg(b2 + lane * 2 + 1);

    float m = fmaxf(p0, p1);
#pragma unroll
    for (int o = 16; o; o >>= 1) m = fmaxf(m, __shfl_xor_sync(~0u, m, o));
    float esum = expf(p0 - m) + expf(p1 - m);
#pragma unroll
    for (int o = 16; o; o >>= 1) esum += __shfl_xor_sync(~0u, esum, o);
    float lse = m + logf(esum);

    float2 res = make_float2(p0 - lse, p1 - lse);
    ((float2*)(out + (size_t)node * D2))[lane] = res;
}

// ---------------- launch ----------------
extern "C" void kernel_launch(void* const* d_in, const int* in_sizes, int n_in,
                              void* d_out, int out_size) {
    const float* x    = (const float*)d_in[0];
    const int*   esrc = (const int*)d_in[1];
    const int*   edst = (const int*)d_in[2];
    const float* W1   = (const float*)d_in[3];
    const float* b1   = (const float*)d_in[4];
    const float* W2   = (const float*)d_in[5];
    const float* b2   = (const float*)d_in[6];
    float* out = (float*)d_out;

    int n = in_sizes[0] / D1;   // 100000
    int e = in_sizes[1];        // 3200000

    __half *xh, *h1, *h2, *w1h, *w2h, *acth, *gh;
    float *dinv1, *dinv2;
    int *rowptr, *colidx;
    cudaGetSymbolAddress((void**)&xh, g_xh);
    cudaGetSymbolAddress((void**)&h1, g_h1);
    cudaGetSymbolAddress((void**)&h2, g_h2);
    cudaGetSymbolAddress((void**)&w1h, g_w1h);
    cudaGetSymbolAddress((void**)&w2h, g_w2h);
    cudaGetSymbolAddress((void**)&acth, g_acth);
    cudaGetSymbolAddress((void**)&gh, g_gh);
    cudaGetSymbolAddress((void**)&dinv1, g_dinv1);
    cudaGetSymbolAddress((void**)&dinv2, g_dinv2);
    cudaGetSymbolAddress((void**)&rowptr, g_rowptr);
    cudaGetSymbolAddress((void**)&colidx, g_col);

    int nb = (n + 255) / 256;          // 391
    int eb = (e + 255) / 256;
    int hopBlocks = (n * 32 + 255) / 256;

    // CSR build + scaled conversion
    k_count<<<2048, 256>>>(edst, W1, W2, e);
    k_dinvreduce<<<nb, 256>>>(n);
    k_scatter<<<nb, 256>>>(nb, n);
    k_fill<<<eb, 256>>>(esrc, edst, e);
    k_convx<<<2048, 256>>>(x, n);

    // conv1: two weightless hops
    k_hop_h<true ><<<hopBlocks, 256>>>(xh, h1, dinv1, rowptr, colidx, 1.0f, n);
    k_hop_h<false><<<hopBlocks, 256>>>(h1, h2, dinv1, rowptr, colidx, 0.36787944117144233f, n);

    // GEMM1 (fused bias+SELU) and GEMM2 (fused dinv2 scale)
    dim3 g1(NNP / 128, 2);
    k_gemm1<<<g1, 256>>>(h2, w1h, b1, acth);
    k_gemm2<<<NNP / 128, 256>>>(acth, w2h, dinv2, gh, n);

    k_out<<<hopBlocks, 256>>>(dinv2, rowptr, colidx, b2, out, n);
}

// round 11
// speedup vs baseline: 2.9918x; 1.0066x over previous
#include <cuda_runtime.h>
#include <cuda_fp16.h>
#include <mma.h>
#include <math.h>

using namespace nvcuda;

#define NN 100000
#define NNP 100096           // padded to multiple of 128 for wmma tiles
#define NE 3200000
#define D1 256
#define D2 64
#define NPARTMAX 512

// ---------------- static device scratch ----------------
// g_cnt is zero on first call and re-zeroed by the convx half of k_fillconv.
// g_woff is (re)initialized by k_scatter every call.
__device__ int    g_cnt[NN];
__device__ int    g_woff[NN];
__device__ int    g_rowptr[NN + 1];
__device__ int    g_part[NPARTMAX];
__device__ int    g_col[NE];
__device__ float  g_dinv1[NN];
__device__ float  g_dinv2[NN];
__device__ __half g_xh[(size_t)NN * D1];     // u0 = dinv1[i] * x[i,:] in half
__device__ __half g_h1[(size_t)NN * D1];     // u1 = dinv1^2 * (A u0)
__device__ __half g_h2[(size_t)NNP * D1];    // coeff * dinv1 * (A u1)  (pad rows stay 0)
__device__ __half g_w1h[D1 * D1];            // W1 half
__device__ __half g_w2h[D1 * D2];            // W2 half
__device__ __half g_acth[(size_t)NNP * D1];  // selu(h2@W1+b1) in half
__device__ __half g_gh[(size_t)NNP * D2];    // dinv2[i] * (acth@W2)[i,:] in half

// ---------------- helpers ----------------
__device__ __forceinline__ float selu_f(float x) {
    const float sc = 1.0507009873554804934f;
    const float al = 1.6732632423543772848f;
    return x > 0.f ? sc * x : sc * al * expm1f(x);
}

__device__ __forceinline__ void addh8(float2 a[4], float4 v) {
    __half2* hp = (__half2*)&v;
#pragma unroll
    for (int q = 0; q < 4; q++) {
        float2 f = __half22float2(hp[q]);
        a[q].x += f.x;
        a[q].y += f.y;
    }
}

__device__ __forceinline__ uint2 f4_to_h4(float4 v) {
    __half2 h0 = __floats2half2_rn(v.x, v.y);
    __half2 h1 = __floats2half2_rn(v.z, v.w);
    return make_uint2(*(unsigned*)&h0, *(unsigned*)&h1);
}

// ---------------- preprocessing ----------------
// count in-degrees (g_cnt pre-zeroed) + convert W1/W2 to half
__global__ void k_count(const int* __restrict__ dst, const float* __restrict__ W1,
                        const float* __restrict__ W2, int e) {
    int stride = gridDim.x * blockDim.x;
    int gtid = blockIdx.x * blockDim.x + threadIdx.x;
    for (int j = gtid; j < e; j += stride)
        atomicAdd(&g_cnt[dst[j]], 1);
    if (gtid < (D1 * D1) / 4) ((uint2*)g_w1h)[gtid] = f4_to_h4(__ldg(((const float4*)W1) + gtid));
    if (gtid < (D1 * D2) / 4) ((uint2*)g_w2h)[gtid] = f4_to_h4(__ldg(((const float4*)W2) + gtid));
}

__global__ void k_dinvreduce(int n) {
    __shared__ int s[256];
    int t = threadIdx.x;
    int i = blockIdx.x * 256 + t;
    int d = 0;
    if (i < n) {
        d = g_cnt[i];
        g_dinv1[i] = d > 0 ? rsqrtf((float)d) : 0.f;
        g_dinv2[i] = rsqrtf((float)(d + 1));
    }
    s[t] = d;
    __syncthreads();
    for (int o = 128; o; o >>= 1) { if (t < o) s[t] += s[t + o]; __syncthreads(); }
    if (t == 0) g_part[blockIdx.x] = s[0];
}

// writes rowptr AND initializes g_woff = rowptr (fill uses woff directly)
__global__ void k_scatter(int nparts, int n) {
    __shared__ int spart[NPARTMAX];
    __shared__ int s[256];
    __shared__ int red[8];
    int t = threadIdx.x;
    int b = blockIdx.x;

    for (int i = t; i < nparts; i += 256) spart[i] = g_part[i];
    __syncthreads();

    int loc = 0;
    for (int i = t; i < b; i += 256) loc += spart[i];
#pragma unroll
    for (int o = 16; o; o >>= 1) loc += __shfl_xor_sync(~0u, loc, o);
    if ((t & 31) == 0) red[t >> 5] = loc;
    __syncthreads();
    int blockpre = red[0] + red[1] + red[2] + red[3] + red[4] + red[5] + red[6] + red[7];

    if (b == 0 && t == 0) {
        int tot = 0;
        for (int i = 0; i < nparts; i++) tot += spart[i];
        g_rowptr[n] = tot;
    }

    int i = b * 256 + t;
    int v = (i < n) ? g_cnt[i] : 0;
    s[t] = v;
    __syncthreads();
    for (int o = 1; o < 256; o <<= 1) {
        int x = (t >= o) ? s[t - o] : 0;
        __syncthreads();
        s[t] += x;
        __syncthreads();
    }
    if (i < n) {
        int rp = blockpre + s[t] - v;
        g_rowptr[i] = rp;
        g_woff[i] = rp;
    }
}

// fused: CSR column fill (blocks [0, fillBlocks)) + x->half scaled conversion
// (blocks [fillBlocks, gridDim)). Fill is atomic-latency-bound (issue ~5%),
// convx is streaming-bandwidth-bound; co-scheduling them overlaps the two.
__global__ void k_fillconv(const int* __restrict__ src, const int* __restrict__ dst,
                           const float* __restrict__ x, int e, int n, int fillBlocks) {
    if ((int)blockIdx.x < fillBlocks) {
        int i = blockIdx.x * 256 + threadIdx.x;
        if (i < e) {
            int p = atomicAdd(&g_woff[dst[i]], 1);
            g_col[p] = src[i];
        }
    } else {
        int stride = (gridDim.x - fillBlocks) * 256;
        int total = n * (D1 / 4);
        for (int i = (blockIdx.x - fillBlocks) * 256 + threadIdx.x; i < total; i += stride) {
            int row = i >> 6;               // 64 float4 groups per row
            float s = __ldg(g_dinv1 + row);
            float4 v = __ldg(((const float4*)x) + i);
            v.x *= s; v.y *= s; v.z *= s; v.w *= s;
            ((uint2*)g_xh)[i] = f4_to_h4(v);
            if (i < n) g_cnt[i] = 0;        // restore for next call
        }
    }
}

// ---------------- weightless 256-dim propagation hop ----------------
// out[i] = scale_i * sum_{j in row i} in[col_j],
// scale_i = dinv1[i]^2 (hop1) or coeff*dinv1[i] (hop2)
template<bool SQUARED>
__global__ void __launch_bounds__(256) k_hop_h(
    const __half* __restrict__ xin, __half* __restrict__ xout,
    const float* __restrict__ dinv, const int* __restrict__ rowptr,
    const int* __restrict__ colidx, float coeff, int n)
{
    int node = (blockIdx.x * blockDim.x + threadIdx.x) >> 5;
    int lane = threadIdx.x & 31;
    if (node >= n) return;
    int beg = rowptr[node], end = rowptr[node + 1];

    float2 a[4];
#pragma unroll
    for (int q = 0; q < 4; q++) a[q] = make_float2(0.f, 0.f);

    for (int e0 = beg; e0 < end; e0 += 32) {
        int idx = e0 + lane;
        int c = (idx < end) ? colidx[idx] : 0;
        int cnt = min(32, end - e0);
        int j = 0;
        for (; j + 8 <= cnt; j += 8) {
            int cc[8];
#pragma unroll
            for (int q = 0; q < 8; q++) cc[q] = __shfl_sync(~0u, c, j + q);
            float4 v[8];
#pragma unroll
            for (int q = 0; q < 8; q++)
                v[q] = __ldg(((const float4*)(xin + (size_t)cc[q] * D1)) + lane);
#pragma unroll
            for (int q = 0; q < 8; q++) addh8(a, v[q]);
        }
        for (; j < cnt; j++) {
            int cj = __shfl_sync(~0u, c, j);
            addh8(a, __ldg(((const float4*)(xin + (size_t)cj * D1)) + lane));
        }
    }

    float d = __ldg(dinv + node);
    float s = SQUARED ? d * d : coeff * d;
    __half2 o0 = __floats2half2_rn(s * a[0].x, s * a[0].y);
    __half2 o1 = __floats2half2_rn(s * a[1].x, s * a[1].y);
    __half2 o2 = __floats2half2_rn(s * a[2].x, s * a[2].y);
    __half2 o3 = __floats2half2_rn(s * a[3].x, s * a[3].y);
    uint4 u;
    u.x = *(unsigned*)&o0; u.y = *(unsigned*)&o1;
    u.z = *(unsigned*)&o2; u.w = *(unsigned*)&o3;
    ((uint4*)(xout + (size_t)node * D1))[lane] = u;
}

// ---------------- GEMM1 + fused bias/SELU epilogue -> half ----------------
__global__ void __launch_bounds__(256) k_gemm1(
    const __half* __restrict__ A, const __half* __restrict__ B,
    const float* __restrict__ bias, __half* __restrict__ Cg)
{
    const int BM = 128, BN = 128, BK = 32;
    const int AS_BYTES = BM * (BK + 8) * 2;
    const int BS_BYTES = BK * (BN + 8) * 2;
    const int CS_BYTES = 8 * 16 * 68 * 4;
    __shared__ __align__(16) char smem_buf[CS_BYTES > AS_BYTES + BS_BYTES ? CS_BYTES : AS_BYTES + BS_BYTES];

    __half (*As)[BK + 8] = reinterpret_cast<__half(*)[BK + 8]>(smem_buf);
    __half (*Bs)[BN + 8] = reinterpret_cast<__half(*)[BN + 8]>(smem_buf + AS_BYTES);
    float  (*Cs)[68]     = reinterpret_cast<float(*)[68]>(smem_buf);

    int tid  = threadIdx.x;
    int warp = tid >> 5;
    int lane = tid & 31;
    int wm = warp >> 1;
    int wn = warp & 1;
    int bm = blockIdx.x * BM;
    int bn = blockIdx.y * BN;

    wmma::fragment<wmma::accumulator, 16, 16, 16, float> acc[2][4];
#pragma unroll
    for (int r = 0; r < 2; r++)
#pragma unroll
        for (int c = 0; c < 4; c++) wmma::fill_fragment(acc[r][c], 0.f);

    for (int k0 = 0; k0 < D1; k0 += BK) {
#pragma unroll
        for (int q = tid; q < (BM * BK) / 8; q += 256) {
            int r  = q >> 2;
            int ch = (q & 3) * 8;
            *(uint4*)&As[r][ch] = *(const uint4*)(A + (size_t)(bm + r) * D1 + k0 + ch);
        }
#pragma unroll
        for (int q = tid; q < (BK * BN) / 8; q += 256) {
            int r  = q >> 4;
            int ch = (q & 15) * 8;
            *(uint4*)&Bs[r][ch] = *(const uint4*)(B + (size_t)(k0 + r) * D1 + bn + ch);
        }
        __syncthreads();
#pragma unroll
        for (int kk = 0; kk < BK; kk += 16) {
            wmma::fragment<wmma::matrix_a, 16, 16, 16, __half, wmma::row_major> af[2];
            wmma::fragment<wmma::matrix_b, 16, 16, 16, __half, wmma::row_major> bf[4];
#pragma unroll
            for (int r = 0; r < 2; r++)
                wmma::load_matrix_sync(af[r], &As[wm * 32 + r * 16][kk], BK + 8);
#pragma unroll
            for (int c = 0; c < 4; c++)
                wmma::load_matrix_sync(bf[c], &Bs[kk][wn * 64 + c * 16], BN + 8);
#pragma unroll
            for (int r = 0; r < 2; r++)
#pragma unroll
                for (int c = 0; c < 4; c++)
                    wmma::mma_sync(acc[r][c], af[r], bf[c], acc[r][c]);
        }
        __syncthreads();
    }

    int colbase = bn + wn * 64;
    float bl[32];
    {
        int cb = colbase + (lane & 1) * 32;
#pragma unroll
        for (int ch = 0; ch < 8; ch++) {
            float4 b4 = __ldg((const float4*)(bias + cb + ch * 4));
            bl[ch * 4 + 0] = b4.x; bl[ch * 4 + 1] = b4.y;
            bl[ch * 4 + 2] = b4.z; bl[ch * 4 + 3] = b4.w;
        }
    }
#pragma unroll
    for (int r = 0; r < 2; r++) {
#pragma unroll
        for (int c = 0; c < 4; c++)
            wmma::store_matrix_sync(&Cs[warp * 16][c * 16], acc[r][c], 68, wmma::mem_row_major);
        __syncwarp();
        int row = lane >> 1;
        int half_sel = (lane & 1) * 32;
        float* rowp = &Cs[warp * 16 + row][half_sel];
        size_t grow = (size_t)(bm + wm * 32 + r * 16 + row) * D1 + colbase + half_sel;
#pragma unroll
        for (int ch = 0; ch < 4; ch++) {
            float4 v0 = make_float4(selu_f(rowp[ch * 8 + 0] + bl[ch * 8 + 0]),
                                    selu_f(rowp[ch * 8 + 1] + bl[ch * 8 + 1]),
                                    selu_f(rowp[ch * 8 + 2] + bl[ch * 8 + 2]),
                                    selu_f(rowp[ch * 8 + 3] + bl[ch * 8 + 3]));
            float4 v1 = make_float4(selu_f(rowp[ch * 8 + 4] + bl[ch * 8 + 4]),
                                    selu_f(rowp[ch * 8 + 5] + bl[ch * 8 + 5]),
                                    selu_f(rowp[ch * 8 + 6] + bl[ch * 8 + 6]),
                                    selu_f(rowp[ch * 8 + 7] + bl[ch * 8 + 7]));
            uint2 pa = f4_to_h4(v0);
            uint2 pb = f4_to_h4(v1);
            *(uint4*)(Cg + grow + ch * 8) = make_uint4(pa.x, pa.y, pb.x, pb.y);
        }
        __syncwarp();
    }
}

// ---------------- GEMM2 (half out, rows pre-scaled by dinv2) ----------------
__global__ void __launch_bounds__(256) k_gemm2(
    const __half* __restrict__ A, const __half* __restrict__ B,
    const float* __restrict__ dinv2, __half* __restrict__ Cg, int n)
{
    const int BM = 128, BN = 64, BK = 32;
    __shared__ __half As[BM][BK + 8];
    __shared__ __half Bs[BK][BN + 8];
    __shared__ float  Cs[8][32][36];

    int tid  = threadIdx.x;
    int warp = tid >> 5;
    int lane = tid & 31;
    int wm = warp >> 1;
    int wn = warp & 1;
    int bm = blockIdx.x * BM;

    wmma::fragment<wmma::accumulator, 16, 16, 16, float> acc[2][2];
#pragma unroll
    for (int r = 0; r < 2; r++)
#pragma unroll
        for (int c = 0; c < 2; c++) wmma::fill_fragment(acc[r][c], 0.f);

    for (int k0 = 0; k0 < D1; k0 += BK) {
#pragma unroll
        for (int q = tid; q < (BM * BK) / 8; q += 256) {
            int r  = q >> 2;
            int ch = (q & 3) * 8;
            *(uint4*)&As[r][ch] = *(const uint4*)(A + (size_t)(bm + r) * D1 + k0 + ch);
        }
        {
            int r  = tid >> 3;
            int ch = (tid & 7) * 8;
            *(uint4*)&Bs[r][ch] = *(const uint4*)(B + (size_t)(k0 + r) * D2 + ch);
        }
        __syncthreads();
#pragma unroll
        for (int kk = 0; kk < BK; kk += 16) {
            wmma::fragment<wmma::matrix_a, 16, 16, 16, __half, wmma::row_major> af[2];
            wmma::fragment<wmma::matrix_b, 16, 16, 16, __half, wmma::row_major> bf[2];
#pragma unroll
            for (int r = 0; r < 2; r++)
                wmma::load_matrix_sync(af[r], &As[wm * 32 + r * 16][kk], BK + 8);
#pragma unroll
            for (int c = 0; c < 2; c++)
                wmma::load_matrix_sync(bf[c], &Bs[kk][wn * 32 + c * 16], BN + 8);
#pragma unroll
            for (int r = 0; r < 2; r++)
#pragma unroll
                for (int c = 0; c < 2; c++)
                    wmma::mma_sync(acc[r][c], af[r], bf[c], acc[r][c]);
        }
        __syncthreads();
    }

#pragma unroll
    for (int r = 0; r < 2; r++)
#pragma unroll
        for (int c = 0; c < 2; c++)
            wmma::store_matrix_sync(&Cs[warp][r * 16][c * 16], acc[r][c], 36, wmma::mem_row_major);
    __syncwarp();

    int row = bm + wm * 32 + lane;
    float dv = (row < n) ? __ldg(dinv2 + row) : 0.f;
    float* rowp = &Cs[warp][lane][0];
    size_t grow = (size_t)row * D2 + wn * 32;
#pragma unroll
    for (int ch = 0; ch < 4; ch++) {
        float4 v0 = make_float4(dv * rowp[ch * 8 + 0], dv * rowp[ch * 8 + 1],
                                dv * rowp[ch * 8 + 2], dv * rowp[ch * 8 + 3]);
        float4 v1 = make_float4(dv * rowp[ch * 8 + 4], dv * rowp[ch * 8 + 5],
                                dv * rowp[ch * 8 + 6], dv * rowp[ch * 8 + 7]);
        uint2 a = f4_to_h4(v0);
        uint2 b = f4_to_h4(v1);
        *(uint4*)(Cg + grow + ch * 8) = make_uint4(a.x, a.y, b.x, b.y);
    }
}

// ---------------- final hop (weightless gather of gh=D2*g) + bias + log_softmax ----------------
__global__ void __launch_bounds__(256) k_out(
    const float* __restrict__ dinv2,
    const int* __restrict__ rowptr, const int* __restrict__ colidx,
    const float* __restrict__ b2, float* __restrict__ out, int n)
{
    int node = (blockIdx.x * blockDim.x + threadIdx.x) >> 5;
    int lane = threadIdx.x & 31;
    if (node >= n) return;
    int beg = rowptr[node], end = rowptr[node + 1];

    // self loop term (gh already scaled by dinv2)
    float2 sv = __half22float2(__ldg(((const __half2*)(g_gh + (size_t)node * D2)) + lane));
    float ax = sv.x;
    float ay = sv.y;

    for (int e0 = beg; e0 < end; e0 += 32) {
        int idx = e0 + lane;
        int c = (idx < end) ? colidx[idx] : 0;
        int cnt = min(32, end - e0);
        int j = 0;
        for (; j + 8 <= cnt; j += 8) {
            int cc[8];
#pragma unroll
            for (int q = 0; q < 8; q++) cc[q] = __shfl_sync(~0u, c, j + q);
            float2 v[8];
#pragma unroll
            for (int q = 0; q < 8; q++)
                v[q] = __half22float2(__ldg(((const __half2*)(g_gh + (size_t)cc[q] * D2)) + lane));
#pragma unroll
            for (int q = 0; q < 8; q++) { ax += v[q].x; ay += v[q].y; }
        }
        for (; j < cnt; j++) {
            int cj = __shfl_sync(~0u, c, j);
            float2 v = __half22float2(__ldg(((const __half2*)(g_gh + (size_t)cj * D2)) + lane));
            ax += v.x; ay += v.y;
        }
    }

    float di = __ldg(dinv2 + node);
    float p0 = di * ax + __ldg(b2 + lane * 2);
    float p1 = di * ay + __ldg(b2 + lane * 2 + 1);

    float m = fmaxf(p0, p1);
#pragma unroll
    for (int o = 16; o; o >>= 1) m = fmaxf(m, __shfl_xor_sync(~0u, m, o));
    float esum = expf(p0 - m) + expf(p1 - m);
#pragma unroll
    for (int o = 16; o; o >>= 1) esum += __shfl_xor_sync(~0u, esum, o);
    float lse = m + logf(esum);

    float2 res = make_float2(p0 - lse, p1 - lse);
    ((float2*)(out + (size_t)node * D2))[lane] = res;
}

// ---------------- launch ----------------
extern "C" void kernel_launch(void* const* d_in, const int* in_sizes, int n_in,
                              void* d_out, int out_size) {
    const float* x    = (const float*)d_in[0];
    const int*   esrc = (const int*)d_in[1];
    const int*   edst = (const int*)d_in[2];
    const float* W1   = (const float*)d_in[3];
    const float* b1   = (const float*)d_in[4];
    const float* W2   = (const float*)d_in[5];
    const float* b2   = (const float*)d_in[6];
    float* out = (float*)d_out;

    int n = in_sizes[0] / D1;   // 100000
    int e = in_sizes[1];        // 3200000

    __half *xh, *h1, *h2, *w1h, *w2h, *acth, *gh;
    float *dinv1, *dinv2;
    int *rowptr, *colidx;
    cudaGetSymbolAddress((void**)&xh, g_xh);
    cudaGetSymbolAddress((void**)&h1, g_h1);
    cudaGetSymbolAddress((void**)&h2, g_h2);
    cudaGetSymbolAddress((void**)&w1h, g_w1h);
    cudaGetSymbolAddress((void**)&w2h, g_w2h);
    cudaGetSymbolAddress((void**)&acth, g_acth);
    cudaGetSymbolAddress((void**)&gh, g_gh);
    cudaGetSymbolAddress((void**)&dinv1, g_dinv1);
    cudaGetSymbolAddress((void**)&dinv2, g_dinv2);
    cudaGetSymbolAddress((void**)&rowptr, g_rowptr);
    cudaGetSymbolAddress((void**)&colidx, g_col);

    int nb = (n + 255) / 256;          // 391
    int eb = (e + 255) / 256;          // 12500
    int hopBlocks = (n * 32 + 255) / 256;

    // CSR build + scaled conversion (fill+convx fused for SM-level overlap)
    k_count<<<2048, 256>>>(edst, W1, W2, e);
    k_dinvreduce<<<nb, 256>>>(n);
    k_scatter<<<nb, 256>>>(nb, n);
    k_fillconv<<<eb + 2048, 256>>>(esrc, edst, x, e, n, eb);

    // conv1: two weightless hops
    k_hop_h<true ><<<hopBlocks, 256>>>(xh, h1, dinv1, rowptr, colidx, 1.0f, n);
    k_hop_h<false><<<hopBlocks, 256>>>(h1, h2, dinv1, rowptr, colidx, 0.36787944117144233f, n);

    // GEMM1 (fused bias+SELU) and GEMM2 (fused dinv2 scale)
    dim3 g1(NNP / 128, 2);
    k_gemm1<<<g1, 256>>>(h2, w1h, b1, acth);
    k_gemm2<<<NNP / 128, 256>>>(acth, w2h, dinv2, gh, n);

    k_out<<<hopBlocks, 256>>>(dinv2, rowptr, colidx, b2, out, n);
}

// round 12
// speedup vs baseline: 3.0387x; 1.0157x over previous
#include <cuda_runtime.h>
#include <cuda_fp16.h>
#include <mma.h>
#include <math.h>

using namespace nvcuda;

#define NN 100000
#define NNP 100096           // padded to multiple of 128 for wmma tiles
#define NE 3200000
#define D1 256
#define D2 64
#define NPARTMAX 512

// ---------------- static device scratch ----------------
// g_cnt is zero on first call and re-zeroed by the convx blocks of k_fillconv.
// g_woff is (re)initialized by k_scatter every call.
__device__ int    g_cnt[NN];
__device__ int    g_woff[NN];
__device__ int    g_rowptr[NN + 1];
__device__ int    g_part[NPARTMAX];
__device__ int    g_col[NE];
__device__ float  g_dinv1[NN];
__device__ float  g_dinv2[NN];
__device__ __half g_xh[(size_t)NN * D1];     // u0 = dinv1[i] * x[i,:] in half
__device__ __half g_h1[(size_t)NN * D1];     // u1 = dinv1^2 * (A u0)
__device__ __half g_h2[(size_t)NNP * D1];    // coeff * dinv1 * (A u1)  (pad rows stay 0)
__device__ __half g_w1h[D1 * D1];            // W1 half
__device__ __half g_w2h[D1 * D2];            // W2 half
__device__ __half g_acth[(size_t)NNP * D1];  // selu(h2@W1+b1) in half
__device__ __half g_gh[(size_t)NNP * D2];    // dinv2[i] * (acth@W2)[i,:] in half

// ---------------- helpers ----------------
__device__ __forceinline__ float selu_f(float x) {
    const float sc = 1.0507009873554804934f;
    const float al = 1.6732632423543772848f;
    return x > 0.f ? sc * x : sc * al * expm1f(x);
}

__device__ __forceinline__ void addh8(float2 a[4], float4 v) {
    __half2* hp = (__half2*)&v;
#pragma unroll
    for (int q = 0; q < 4; q++) {
        float2 f = __half22float2(hp[q]);
        a[q].x += f.x;
        a[q].y += f.y;
    }
}

__device__ __forceinline__ uint2 f4_to_h4(float4 v) {
    __half2 h0 = __floats2half2_rn(v.x, v.y);
    __half2 h1 = __floats2half2_rn(v.z, v.w);
    return make_uint2(*(unsigned*)&h0, *(unsigned*)&h1);
}

// ---------------- preprocessing ----------------
// count in-degrees (g_cnt pre-zeroed) + convert W1/W2 to half
__global__ void k_count(const int* __restrict__ dst, const float* __restrict__ W1,
                        const float* __restrict__ W2, int e) {
    int stride = gridDim.x * blockDim.x;
    int gtid = blockIdx.x * blockDim.x + threadIdx.x;
    for (int j = gtid; j < e; j += stride)
        atomicAdd(&g_cnt[dst[j]], 1);
    if (gtid < (D1 * D1) / 4) ((uint2*)g_w1h)[gtid] = f4_to_h4(__ldg(((const float4*)W1) + gtid));
    if (gtid < (D1 * D2) / 4) ((uint2*)g_w2h)[gtid] = f4_to_h4(__ldg(((const float4*)W2) + gtid));
}

__global__ void k_dinvreduce(int n) {
    __shared__ int s[256];
    int t = threadIdx.x;
    int i = blockIdx.x * 256 + t;
    int d = 0;
    if (i < n) {
        d = g_cnt[i];
        g_dinv1[i] = d > 0 ? rsqrtf((float)d) : 0.f;
        g_dinv2[i] = rsqrtf((float)(d + 1));
    }
    s[t] = d;
    __syncthreads();
    for (int o = 128; o; o >>= 1) { if (t < o) s[t] += s[t + o]; __syncthreads(); }
    if (t == 0) g_part[blockIdx.x] = s[0];
}

// writes rowptr AND initializes g_woff = rowptr (fill uses woff directly)
__global__ void k_scatter(int nparts, int n) {
    __shared__ int spart[NPARTMAX];
    __shared__ int s[256];
    __shared__ int red[8];
    int t = threadIdx.x;
    int b = blockIdx.x;

    for (int i = t; i < nparts; i += 256) spart[i] = g_part[i];
    __syncthreads();

    int loc = 0;
    for (int i = t; i < b; i += 256) loc += spart[i];
#pragma unroll
    for (int o = 16; o; o >>= 1) loc += __shfl_xor_sync(~0u, loc, o);
    if ((t & 31) == 0) red[t >> 5] = loc;
    __syncthreads();
    int blockpre = red[0] + red[1] + red[2] + red[3] + red[4] + red[5] + red[6] + red[7];

    if (b == 0 && t == 0) {
        int tot = 0;
        for (int i = 0; i < nparts; i++) tot += spart[i];
        g_rowptr[n] = tot;
    }

    int i = b * 256 + t;
    int v = (i < n) ? g_cnt[i] : 0;
    s[t] = v;
    __syncthreads();
    for (int o = 1; o < 256; o <<= 1) {
        int x = (t >= o) ? s[t - o] : 0;
        __syncthreads();
        s[t] += x;
        __syncthreads();
    }
    if (i < n) {
        int rp = blockpre + s[t] - v;
        g_rowptr[i] = rp;
        g_woff[i] = rp;
    }
}

// fused CSR fill + x->half conversion with STRIPED roles: within each group of
// 8 consecutive blocks, slots 0-6 do fill, slot 7 does convx. This way every
// scheduling wave mixes latency-bound atomic blocks with streaming blocks.
__global__ void k_fillconv(const int* __restrict__ src, const int* __restrict__ dst,
                           const float* __restrict__ x, int e, int n, int nGroups) {
    int g    = blockIdx.x >> 3;
    int slot = blockIdx.x & 7;
    if (slot != 7) {
        int i = (g * 7 + slot) * 256 + threadIdx.x;
        if (i < e) {
            int p = atomicAdd(&g_woff[dst[i]], 1);
            g_col[p] = src[i];
        }
    } else {
        int stride = nGroups * 256;
        int total = n * (D1 / 4);
        for (int i = g * 256 + threadIdx.x; i < total; i += stride) {
            int row = i >> 6;               // 64 float4 groups per row
            float s = __ldg(g_dinv1 + row);
            float4 v = __ldg(((const float4*)x) + i);
            v.x *= s; v.y *= s; v.z *= s; v.w *= s;
            ((uint2*)g_xh)[i] = f4_to_h4(v);
            if (i < n) g_cnt[i] = 0;        // restore for next call
        }
    }
}

// ---------------- weightless 256-dim propagation hop ----------------
// out[i] = scale_i * sum_{j in row i} in[col_j],
// scale_i = dinv1[i]^2 (hop1) or coeff*dinv1[i] (hop2)
template<bool SQUARED>
__global__ void __launch_bounds__(256) k_hop_h(
    const __half* __restrict__ xin, __half* __restrict__ xout,
    const float* __restrict__ dinv, const int* __restrict__ rowptr,
    const int* __restrict__ colidx, float coeff, int n)
{
    int node = (blockIdx.x * blockDim.x + threadIdx.x) >> 5;
    int lane = threadIdx.x & 31;
    if (node >= n) return;
    int beg = rowptr[node], end = rowptr[node + 1];

    float2 a[4];
#pragma unroll
    for (int q = 0; q < 4; q++) a[q] = make_float2(0.f, 0.f);

    for (int e0 = beg; e0 < end; e0 += 32) {
        int idx = e0 + lane;
        int c = (idx < end) ? colidx[idx] : 0;
        int cnt = min(32, end - e0);
        int j = 0;
        for (; j + 8 <= cnt; j += 8) {
            int cc[8];
#pragma unroll
            for (int q = 0; q < 8; q++) cc[q] = __shfl_sync(~0u, c, j + q);
            float4 v[8];
#pragma unroll
            for (int q = 0; q < 8; q++)
                v[q] = __ldg(((const float4*)(xin + (size_t)cc[q] * D1)) + lane);
#pragma unroll
            for (int q = 0; q < 8; q++) addh8(a, v[q]);
        }
        for (; j < cnt; j++) {
            int cj = __shfl_sync(~0u, c, j);
            addh8(a, __ldg(((const float4*)(xin + (size_t)cj * D1)) + lane));
        }
    }

    float d = __ldg(dinv + node);
    float s = SQUARED ? d * d : coeff * d;
    __half2 o0 = __floats2half2_rn(s * a[0].x, s * a[0].y);
    __half2 o1 = __floats2half2_rn(s * a[1].x, s * a[1].y);
    __half2 o2 = __floats2half2_rn(s * a[2].x, s * a[2].y);
    __half2 o3 = __floats2half2_rn(s * a[3].x, s * a[3].y);
    uint4 u;
    u.x = *(unsigned*)&o0; u.y = *(unsigned*)&o1;
    u.z = *(unsigned*)&o2; u.w = *(unsigned*)&o3;
    ((uint4*)(xout + (size_t)node * D1))[lane] = u;
}

// ---------------- GEMM1 + fused bias/SELU epilogue -> half ----------------
__global__ void __launch_bounds__(256) k_gemm1(
    const __half* __restrict__ A, const __half* __restrict__ B,
    const float* __restrict__ bias, __half* __restrict__ Cg)
{
    const int BM = 128, BN = 128, BK = 32;
    const int AS_BYTES = BM * (BK + 8) * 2;
    const int BS_BYTES = BK * (BN + 8) * 2;
    const int CS_BYTES = 8 * 16 * 68 * 4;
    __shared__ __align__(16) char smem_buf[CS_BYTES > AS_BYTES + BS_BYTES ? CS_BYTES : AS_BYTES + BS_BYTES];

    __half (*As)[BK + 8] = reinterpret_cast<__half(*)[BK + 8]>(smem_buf);
    __half (*Bs)[BN + 8] = reinterpret_cast<__half(*)[BN + 8]>(smem_buf + AS_BYTES);
    float  (*Cs)[68]     = reinterpret_cast<float(*)[68]>(smem_buf);

    int tid  = threadIdx.x;
    int warp = tid >> 5;
    int lane = tid & 31;
    int wm = warp >> 1;
    int wn = warp & 1;
    int bm = blockIdx.x * BM;
    int bn = blockIdx.y * BN;

    wmma::fragment<wmma::accumulator, 16, 16, 16, float> acc[2][4];
#pragma unroll
    for (int r = 0; r < 2; r++)
#pragma unroll
        for (int c = 0; c < 4; c++) wmma::fill_fragment(acc[r][c], 0.f);

    for (int k0 = 0; k0 < D1; k0 += BK) {
#pragma unroll
        for (int q = tid; q < (BM * BK) / 8; q += 256) {
            int r  = q >> 2;
            int ch = (q & 3) * 8;
            *(uint4*)&As[r][ch] = *(const uint4*)(A + (size_t)(bm + r) * D1 + k0 + ch);
        }
#pragma unroll
        for (int q = tid; q < (BK * BN) / 8; q += 256) {
            int r  = q >> 4;
            int ch = (q & 15) * 8;
            *(uint4*)&Bs[r][ch] = *(const uint4*)(B + (size_t)(k0 + r) * D1 + bn + ch);
        }
        __syncthreads();
#pragma unroll
        for (int kk = 0; kk < BK; kk += 16) {
            wmma::fragment<wmma::matrix_a, 16, 16, 16, __half, wmma::row_major> af[2];
            wmma::fragment<wmma::matrix_b, 16, 16, 16, __half, wmma::row_major> bf[4];
#pragma unroll
            for (int r = 0; r < 2; r++)
                wmma::load_matrix_sync(af[r], &As[wm * 32 + r * 16][kk], BK + 8);
#pragma unroll
            for (int c = 0; c < 4; c++)
                wmma::load_matrix_sync(bf[c], &Bs[kk][wn * 64 + c * 16], BN + 8);
#pragma unroll
            for (int r = 0; r < 2; r++)
#pragma unroll
                for (int c = 0; c < 4; c++)
                    wmma::mma_sync(acc[r][c], af[r], bf[c], acc[r][c]);
        }
        __syncthreads();
    }

    int colbase = bn + wn * 64;
    float bl[32];
    {
        int cb = colbase + (lane & 1) * 32;
#pragma unroll
        for (int ch = 0; ch < 8; ch++) {
            float4 b4 = __ldg((const float4*)(bias + cb + ch * 4));
            bl[ch * 4 + 0] = b4.x; bl[ch * 4 + 1] = b4.y;
            bl[ch * 4 + 2] = b4.z; bl[ch * 4 + 3] = b4.w;
        }
    }
#pragma unroll
    for (int r = 0; r < 2; r++) {
#pragma unroll
        for (int c = 0; c < 4; c++)
            wmma::store_matrix_sync(&Cs[warp * 16][c * 16], acc[r][c], 68, wmma::mem_row_major);
        __syncwarp();
        int row = lane >> 1;
        int half_sel = (lane & 1) * 32;
        float* rowp = &Cs[warp * 16 + row][half_sel];
        size_t grow = (size_t)(bm + wm * 32 + r * 16 + row) * D1 + colbase + half_sel;
#pragma unroll
        for (int ch = 0; ch < 4; ch++) {
            float4 v0 = make_float4(selu_f(rowp[ch * 8 + 0] + bl[ch * 8 + 0]),
                                    selu_f(rowp[ch * 8 + 1] + bl[ch * 8 + 1]),
                                    selu_f(rowp[ch * 8 + 2] + bl[ch * 8 + 2]),
                                    selu_f(rowp[ch * 8 + 3] + bl[ch * 8 + 3]));
            float4 v1 = make_float4(selu_f(rowp[ch * 8 + 4] + bl[ch * 8 + 4]),
                                    selu_f(rowp[ch * 8 + 5] + bl[ch * 8 + 5]),
                                    selu_f(rowp[ch * 8 + 6] + bl[ch * 8 + 6]),
                                    selu_f(rowp[ch * 8 + 7] + bl[ch * 8 + 7]));
            uint2 pa = f4_to_h4(v0);
            uint2 pb = f4_to_h4(v1);
            *(uint4*)(Cg + grow + ch * 8) = make_uint4(pa.x, pa.y, pb.x, pb.y);
        }
        __syncwarp();
    }
}

// ---------------- GEMM2 (half out, rows pre-scaled by dinv2) ----------------
__global__ void __launch_bounds__(256) k_gemm2(
    const __half* __restrict__ A, const __half* __restrict__ B,
    const float* __restrict__ dinv2, __half* __restrict__ Cg, int n)
{
    const int BM = 128, BN = 64, BK = 32;
    __shared__ __half As[BM][BK + 8];
    __shared__ __half Bs[BK][BN + 8];
    __shared__ float  Cs[8][32][36];

    int tid  = threadIdx.x;
    int warp = tid >> 5;
    int lane = tid & 31;
    int wm = warp >> 1;
    int wn = warp & 1;
    int bm = blockIdx.x * BM;

    wmma::fragment<wmma::accumulator, 16, 16, 16, float> acc[2][2];
#pragma unroll
    for (int r = 0; r < 2; r++)
#pragma unroll
        for (int c = 0; c < 2; c++) wmma::fill_fragment(acc[r][c], 0.f);

    for (int k0 = 0; k0 < D1; k0 += BK) {
#pragma unroll
        for (int q = tid; q < (BM * BK) / 8; q += 256) {
            int r  = q >> 2;
            int ch = (q & 3) * 8;
            *(uint4*)&As[r][ch] = *(const uint4*)(A + (size_t)(bm + r) * D1 + k0 + ch);
        }
        {
            int r  = tid >> 3;
            int ch = (tid & 7) * 8;
            *(uint4*)&Bs[r][ch] = *(const uint4*)(B + (size_t)(k0 + r) * D2 + ch);
        }
        __syncthreads();
#pragma unroll
        for (int kk = 0; kk < BK; kk += 16) {
            wmma::fragment<wmma::matrix_a, 16, 16, 16, __half, wmma::row_major> af[2];
            wmma::fragment<wmma::matrix_b, 16, 16, 16, __half, wmma::row_major> bf[2];
#pragma unroll
            for (int r = 0; r < 2; r++)
                wmma::load_matrix_sync(af[r], &As[wm * 32 + r * 16][kk], BK + 8);
#pragma unroll
            for (int c = 0; c < 2; c++)
                wmma::load_matrix_sync(bf[c], &Bs[kk][wn * 32 + c * 16], BN + 8);
#pragma unroll
            for (int r = 0; r < 2; r++)
#pragma unroll
                for (int c = 0; c < 2; c++)
                    wmma::mma_sync(acc[r][c], af[r], bf[c], acc[r][c]);
        }
        __syncthreads();
    }

#pragma unroll
    for (int r = 0; r < 2; r++)
#pragma unroll
        for (int c = 0; c < 2; c++)
            wmma::store_matrix_sync(&Cs[warp][r * 16][c * 16], acc[r][c], 36, wmma::mem_row_major);
    __syncwarp();

    int row = bm + wm * 32 + lane;
    float dv = (row < n) ? __ldg(dinv2 + row) : 0.f;
    float* rowp = &Cs[warp][lane][0];
    size_t grow = (size_t)row * D2 + wn * 32;
#pragma unroll
    for (int ch = 0; ch < 4; ch++) {
        float4 v0 = make_float4(dv * rowp[ch * 8 + 0], dv * rowp[ch * 8 + 1],
                                dv * rowp[ch * 8 + 2], dv * rowp[ch * 8 + 3]);
        float4 v1 = make_float4(dv * rowp[ch * 8 + 4], dv * rowp[ch * 8 + 5],
                                dv * rowp[ch * 8 + 6], dv * rowp[ch * 8 + 7]);
        uint2 a = f4_to_h4(v0);
        uint2 b = f4_to_h4(v1);
        *(uint4*)(Cg + grow + ch * 8) = make_uint4(a.x, a.y, b.x, b.y);
    }
}

// ---------------- final hop (weightless gather of gh=D2*g) + bias + log_softmax ----------------
__global__ void __launch_bounds__(256) k_out(
    const float* __restrict__ dinv2,
    const int* __restrict__ rowptr, const int* __restrict__ colidx,
    const float* __restrict__ b2, float* __restrict__ out, int n)
{
    int node = (blockIdx.x * blockDim.x + threadIdx.x) >> 5;
    int lane = threadIdx.x & 31;
    if (node >= n) return;
    int beg = rowptr[node], end = rowptr[node + 1];

    // self loop term (gh already scaled by dinv2)
    float2 sv = __half22float2(__ldg(((const __half2*)(g_gh + (size_t)node * D2)) + lane));
    float ax = sv.x;
    float ay = sv.y;

    for (int e0 = beg; e0 < end; e0 += 32) {
        int idx = e0 + lane;
        int c = (idx < end) ? colidx[idx] : 0;
        int cnt = min(32, end - e0);
        int j = 0;
        for (; j + 8 <= cnt; j += 8) {
            int cc[8];
#pragma unroll
            for (int q = 0; q < 8; q++) cc[q] = __shfl_sync(~0u, c, j + q);
            float2 v[8];
#pragma unroll
            for (int q = 0; q < 8; q++)
                v[q] = __half22float2(__ldg(((const __half2*)(g_gh + (size_t)cc[q] * D2)) + lane));
#pragma unroll
            for (int q = 0; q < 8; q++) { ax += v[q].x; ay += v[q].y; }
        }
        for (; j < cnt; j++) {
            int cj = __shfl_sync(~0u, c, j);
            float2 v = __half22float2(__ldg(((const __half2*)(g_gh + (size_t)cj * D2)) + lane));
            ax += v.x; ay += v.y;
        }
    }

    float di = __ldg(dinv2 + node);
    float p0 = di * ax + __ldg(b2 + lane * 2);
    float p1 = di * ay + __ldg(b2 + lane * 2 + 1);

    float m = fmaxf(p0, p1);
#pragma unroll
    for (int o = 16; o; o >>= 1) m = fmaxf(m, __shfl_xor_sync(~0u, m, o));
    float esum = expf(p0 - m) + expf(p1 - m);
#pragma unroll
    for (int o = 16; o; o >>= 1) esum += __shfl_xor_sync(~0u, esum, o);
    float lse = m + logf(esum);

    float2 res = make_float2(p0 - lse, p1 - lse);
    ((float2*)(out + (size_t)node * D2))[lane] = res;
}

// ---------------- launch ----------------
extern "C" void kernel_launch(void* const* d_in, const int* in_sizes, int n_in,
                              void* d_out, int out_size) {
    const float* x    = (const float*)d_in[0];
    const int*   esrc = (const int*)d_in[1];
    const int*   edst = (const int*)d_in[2];
    const float* W1   = (const float*)d_in[3];
    const float* b1   = (const float*)d_in[4];
    const float* W2   = (const float*)d_in[5];
    const float* b2   = (const float*)d_in[6];
    float* out = (float*)d_out;

    int n = in_sizes[0] / D1;   // 100000
    int e = in_sizes[1];        // 3200000

    __half *xh, *h1, *h2, *w1h, *w2h, *acth, *gh;
    float *dinv1, *dinv2;
    int *rowptr, *colidx;
    cudaGetSymbolAddress((void**)&xh, g_xh);
    cudaGetSymbolAddress((void**)&h1, g_h1);
    cudaGetSymbolAddress((void**)&h2, g_h2);
    cudaGetSymbolAddress((void**)&w1h, g_w1h);
    cudaGetSymbolAddress((void**)&w2h, g_w2h);
    cudaGetSymbolAddress((void**)&acth, g_acth);
    cudaGetSymbolAddress((void**)&gh, g_gh);
    cudaGetSymbolAddress((void**)&dinv1, g_dinv1);
    cudaGetSymbolAddress((void**)&dinv2, g_dinv2);
    cudaGetSymbolAddress((void**)&rowptr, g_rowptr);
    cudaGetSymbolAddress((void**)&colidx, g_col);

    int nb = (n + 255) / 256;          // 391
    int eb = (e + 255) / 256;          // 12500
    int hopBlocks = (n * 32 + 255) / 256;

    // CSR build + scaled conversion (fill+convx striped 7:1 for true co-residence)
    int nGroups = (eb + 6) / 7;        // 1786 groups of 8 blocks (7 fill + 1 convx)
    k_count<<<2048, 256>>>(edst, W1, W2, e);
    k_dinvreduce<<<nb, 256>>>(n);
    k_scatter<<<nb, 256>>>(nb, n);
    k_fillconv<<<nGroups * 8, 256>>>(esrc, edst, x, e, n, nGroups);

    // conv1: two weightless hops
    k_hop_h<true ><<<hopBlocks, 256>>>(xh, h1, dinv1, rowptr, colidx, 1.0f, n);
    k_hop_h<false><<<hopBlocks, 256>>>(h1, h2, dinv1, rowptr, colidx, 0.36787944117144233f, n);

    // GEMM1 (fused bias+SELU) and GEMM2 (fused dinv2 scale)
    dim3 g1(NNP / 128, 2);
    k_gemm1<<<g1, 256>>>(h2, w1h, b1, acth);
    k_gemm2<<<NNP / 128, 256>>>(acth, w2h, dinv2, gh, n);

    k_out<<<hopBlocks, 256>>>(dinv2, rowptr, colidx, b2, out, n);
}

// round 13
// speedup vs baseline: 3.1088x; 1.0231x over previous
#include <cuda_runtime.h>
#include <cuda_fp16.h>
#include <mma.h>
#include <math.h>

using namespace nvcuda;

#define NN 100000
#define NNP 100096           // padded to multiple of 128 for wmma tiles
#define NE 3200000
#define D1 256
#define D2 64
#define NPARTMAX 512

// ---------------- static device scratch ----------------
// g_cnt is zero on first call and re-zeroed by the convx blocks of k_fillconv.
// g_woff is (re)initialized by k_scatter every call.
__device__ int    g_cnt[NN];
__device__ int    g_woff[NN];
__device__ int    g_rowptr[NN + 1];
__device__ int    g_part[NPARTMAX];
__device__ int    g_col[NE];
__device__ float  g_dinv1[NN];
__device__ float  g_dinv2[NN];
__device__ __half g_xh[(size_t)NN * D1];     // u0 = dinv1[i] * x[i,:] in half
__device__ __half g_h1[(size_t)NN * D1];     // u1 = dinv1^2 * (A u0)
__device__ __half g_h2[(size_t)NNP * D1];    // coeff * dinv1 * (A u1)  (pad rows stay 0)
__device__ __half g_w1h[D1 * D1];            // W1 half
__device__ __half g_w2h[D1 * D2];            // W2 half
__device__ __half g_acth[(size_t)NNP * D1];  // selu(h2@W1+b1) in half
__device__ __half g_gh[(size_t)NNP * D2];    // dinv2[i] * (acth@W2)[i,:] in half

// ---------------- helpers ----------------
__device__ __forceinline__ float selu_f(float x) {
    const float sc = 1.0507009873554804934f;
    const float al = 1.6732632423543772848f;
    return x > 0.f ? sc * x : sc * al * expm1f(x);
}

__device__ __forceinline__ void addh8(float2 a[4], float4 v) {
    __half2* hp = (__half2*)&v;
#pragma unroll
    for (int q = 0; q < 4; q++) {
        float2 f = __half22float2(hp[q]);
        a[q].x += f.x;
        a[q].y += f.y;
    }
}

__device__ __forceinline__ uint2 f4_to_h4(float4 v) {
    __half2 h0 = __floats2half2_rn(v.x, v.y);
    __half2 h1 = __floats2half2_rn(v.z, v.w);
    return make_uint2(*(unsigned*)&h0, *(unsigned*)&h1);
}

// ---------------- preprocessing ----------------
// count in-degrees (g_cnt pre-zeroed) + convert W1/W2 to half
__global__ void k_count(const int* __restrict__ dst, const float* __restrict__ W1,
                        const float* __restrict__ W2, int e) {
    int stride = gridDim.x * blockDim.x;
    int gtid = blockIdx.x * blockDim.x + threadIdx.x;
    for (int j = gtid; j < e; j += stride)
        atomicAdd(&g_cnt[dst[j]], 1);
    if (gtid < (D1 * D1) / 4) ((uint2*)g_w1h)[gtid] = f4_to_h4(__ldg(((const float4*)W1) + gtid));
    if (gtid < (D1 * D2) / 4) ((uint2*)g_w2h)[gtid] = f4_to_h4(__ldg(((const float4*)W2) + gtid));
}

__global__ void k_dinvreduce(int n) {
    __shared__ int s[256];
    int t = threadIdx.x;
    int i = blockIdx.x * 256 + t;
    int d = 0;
    if (i < n) {
        d = g_cnt[i];
        g_dinv1[i] = d > 0 ? rsqrtf((float)d) : 0.f;
        g_dinv2[i] = rsqrtf((float)(d + 1));
    }
    s[t] = d;
    __syncthreads();
    for (int o = 128; o; o >>= 1) { if (t < o) s[t] += s[t + o]; __syncthreads(); }
    if (t == 0) g_part[blockIdx.x] = s[0];
}

// writes rowptr AND initializes g_woff = rowptr (fill uses woff directly)
__global__ void k_scatter(int nparts, int n) {
    __shared__ int spart[NPARTMAX];
    __shared__ int s[256];
    __shared__ int red[8];
    int t = threadIdx.x;
    int b = blockIdx.x;

    for (int i = t; i < nparts; i += 256) spart[i] = g_part[i];
    __syncthreads();

    int loc = 0;
    for (int i = t; i < b; i += 256) loc += spart[i];
#pragma unroll
    for (int o = 16; o; o >>= 1) loc += __shfl_xor_sync(~0u, loc, o);
    if ((t & 31) == 0) red[t >> 5] = loc;
    __syncthreads();
    int blockpre = red[0] + red[1] + red[2] + red[3] + red[4] + red[5] + red[6] + red[7];

    if (b == 0 && t == 0) {
        int tot = 0;
        for (int i = 0; i < nparts; i++) tot += spart[i];
        g_rowptr[n] = tot;
    }

    int i = b * 256 + t;
    int v = (i < n) ? g_cnt[i] : 0;
    s[t] = v;
    __syncthreads();
    for (int o = 1; o < 256; o <<= 1) {
        int x = (t >= o) ? s[t - o] : 0;
        __syncthreads();
        s[t] += x;
        __syncthreads();
    }
    if (i < n) {
        int rp = blockpre + s[t] - v;
        g_rowptr[i] = rp;
        g_woff[i] = rp;
    }
}

// fused CSR fill + x->half conversion with STRIPED roles (7:1 fill:convx)
__global__ void k_fillconv(const int* __restrict__ src, const int* __restrict__ dst,
                           const float* __restrict__ x, int e, int n, int nGroups) {
    int g    = blockIdx.x >> 3;
    int slot = blockIdx.x & 7;
    if (slot != 7) {
        int i = (g * 7 + slot) * 256 + threadIdx.x;
        if (i < e) {
            int p = atomicAdd(&g_woff[dst[i]], 1);
            g_col[p] = src[i];
        }
    } else {
        int stride = nGroups * 256;
        int total = n * (D1 / 4);
        for (int i = g * 256 + threadIdx.x; i < total; i += stride) {
            int row = i >> 6;               // 64 float4 groups per row
            float s = __ldg(g_dinv1 + row);
            float4 v = __ldg(((const float4*)x) + i);
            v.x *= s; v.y *= s; v.z *= s; v.w *= s;
            ((uint2*)g_xh)[i] = f4_to_h4(v);
            if (i < n) g_cnt[i] = 0;        // restore for next call
        }
    }
}

// ---------------- weightless 256-dim propagation hop ----------------
template<bool SQUARED>
__global__ void __launch_bounds__(256) k_hop_h(
    const __half* __restrict__ xin, __half* __restrict__ xout,
    const float* __restrict__ dinv, const int* __restrict__ rowptr,
    const int* __restrict__ colidx, float coeff, int n)
{
    int node = (blockIdx.x * blockDim.x + threadIdx.x) >> 5;
    int lane = threadIdx.x & 31;
    if (node >= n) return;
    int beg = rowptr[node], end = rowptr[node + 1];

    float2 a[4];
#pragma unroll
    for (int q = 0; q < 4; q++) a[q] = make_float2(0.f, 0.f);

    for (int e0 = beg; e0 < end; e0 += 32) {
        int idx = e0 + lane;
        int c = (idx < end) ? colidx[idx] : 0;
        int cnt = min(32, end - e0);
        int j = 0;
        for (; j + 8 <= cnt; j += 8) {
            int cc[8];
#pragma unroll
            for (int q = 0; q < 8; q++) cc[q] = __shfl_sync(~0u, c, j + q);
            float4 v[8];
#pragma unroll
            for (int q = 0; q < 8; q++)
                v[q] = __ldg(((const float4*)(xin + (size_t)cc[q] * D1)) + lane);
#pragma unroll
            for (int q = 0; q < 8; q++) addh8(a, v[q]);
        }
        for (; j < cnt; j++) {
            int cj = __shfl_sync(~0u, c, j);
            addh8(a, __ldg(((const float4*)(xin + (size_t)cj * D1)) + lane));
        }
    }

    float d = __ldg(dinv + node);
    float s = SQUARED ? d * d : coeff * d;
    __half2 o0 = __floats2half2_rn(s * a[0].x, s * a[0].y);
    __half2 o1 = __floats2half2_rn(s * a[1].x, s * a[1].y);
    __half2 o2 = __floats2half2_rn(s * a[2].x, s * a[2].y);
    __half2 o3 = __floats2half2_rn(s * a[3].x, s * a[3].y);
    uint4 u;
    u.x = *(unsigned*)&o0; u.y = *(unsigned*)&o1;
    u.z = *(unsigned*)&o2; u.w = *(unsigned*)&o3;
    ((uint4*)(xout + (size_t)node * D1))[lane] = u;
}

// ---------------- GEMM1 (reg-prefetch pipelined) + fused bias/SELU -> half ----------------
__global__ void __launch_bounds__(256) k_gemm1(
    const __half* __restrict__ A, const __half* __restrict__ B,
    const float* __restrict__ bias, __half* __restrict__ Cg)
{
    const int BM = 128, BN = 128, BK = 32;
    const int AS_BYTES = BM * (BK + 8) * 2;
    const int BS_BYTES = BK * (BN + 8) * 2;
    const int CS_BYTES = 8 * 16 * 68 * 4;
    __shared__ __align__(16) char smem_buf[CS_BYTES > AS_BYTES + BS_BYTES ? CS_BYTES : AS_BYTES + BS_BYTES];

    __half (*As)[BK + 8] = reinterpret_cast<__half(*)[BK + 8]>(smem_buf);
    __half (*Bs)[BN + 8] = reinterpret_cast<__half(*)[BN + 8]>(smem_buf + AS_BYTES);
    float  (*Cs)[68]     = reinterpret_cast<float(*)[68]>(smem_buf);

    int tid  = threadIdx.x;
    int warp = tid >> 5;
    int lane = tid & 31;
    int wm = warp >> 1;
    int wn = warp & 1;
    int bm = blockIdx.x * BM;
    int bn = blockIdx.y * BN;

    // per-thread tile chunk coordinates
    int ra = tid >> 2, ca = (tid & 3) * 8;        // A: rows ra, ra+64
    int rb = tid >> 4, cb = (tid & 15) * 8;       // B: rows rb, rb+16

    wmma::fragment<wmma::accumulator, 16, 16, 16, float> acc[2][4];
#pragma unroll
    for (int r = 0; r < 2; r++)
#pragma unroll
        for (int c = 0; c < 4; c++) wmma::fill_fragment(acc[r][c], 0.f);

    // prefetch tile 0
    uint4 pa0 = *(const uint4*)(A + (size_t)(bm + ra) * D1 + ca);
    uint4 pa1 = *(const uint4*)(A + (size_t)(bm + ra + 64) * D1 + ca);
    uint4 pb0 = *(const uint4*)(B + (size_t)rb * D1 + bn + cb);
    uint4 pb1 = *(const uint4*)(B + (size_t)(rb + 16) * D1 + bn + cb);

    for (int k0 = 0; k0 < D1; k0 += BK) {
        *(uint4*)&As[ra][ca]      = pa0;
        *(uint4*)&As[ra + 64][ca] = pa1;
        *(uint4*)&Bs[rb][cb]      = pb0;
        *(uint4*)&Bs[rb + 16][cb] = pb1;
        __syncthreads();

        int kn = k0 + BK;
        if (kn < D1) {   // prefetch next tile while mma runs
            pa0 = *(const uint4*)(A + (size_t)(bm + ra) * D1 + kn + ca);
            pa1 = *(const uint4*)(A + (size_t)(bm + ra + 64) * D1 + kn + ca);
            pb0 = *(const uint4*)(B + (size_t)(kn + rb) * D1 + bn + cb);
            pb1 = *(const uint4*)(B + (size_t)(kn + rb + 16) * D1 + bn + cb);
        }
#pragma unroll
        for (int kk = 0; kk < BK; kk += 16) {
            wmma::fragment<wmma::matrix_a, 16, 16, 16, __half, wmma::row_major> af[2];
            wmma::fragment<wmma::matrix_b, 16, 16, 16, __half, wmma::row_major> bf[4];
#pragma unroll
            for (int r = 0; r < 2; r++)
                wmma::load_matrix_sync(af[r], &As[wm * 32 + r * 16][kk], BK + 8);
#pragma unroll
            for (int c = 0; c < 4; c++)
                wmma::load_matrix_sync(bf[c], &Bs[kk][wn * 64 + c * 16], BN + 8);
#pragma unroll
            for (int r = 0; r < 2; r++)
#pragma unroll
                for (int c = 0; c < 4; c++)
                    wmma::mma_sync(acc[r][c], af[r], bf[c], acc[r][c]);
        }
        __syncthreads();
    }

    int colbase = bn + wn * 64;
    float bl[32];
    {
        int cb2 = colbase + (lane & 1) * 32;
#pragma unroll
        for (int ch = 0; ch < 8; ch++) {
            float4 b4 = __ldg((const float4*)(bias + cb2 + ch * 4));
            bl[ch * 4 + 0] = b4.x; bl[ch * 4 + 1] = b4.y;
            bl[ch * 4 + 2] = b4.z; bl[ch * 4 + 3] = b4.w;
        }
    }
#pragma unroll
    for (int r = 0; r < 2; r++) {
#pragma unroll
        for (int c = 0; c < 4; c++)
            wmma::store_matrix_sync(&Cs[warp * 16][c * 16], acc[r][c], 68, wmma::mem_row_major);
        __syncwarp();
        int row = lane >> 1;
        int half_sel = (lane & 1) * 32;
        float* rowp = &Cs[warp * 16 + row][half_sel];
        size_t grow = (size_t)(bm + wm * 32 + r * 16 + row) * D1 + colbase + half_sel;
#pragma unroll
        for (int ch = 0; ch < 4; ch++) {
            float4 v0 = make_float4(selu_f(rowp[ch * 8 + 0] + bl[ch * 8 + 0]),
                                    selu_f(rowp[ch * 8 + 1] + bl[ch * 8 + 1]),
                                    selu_f(rowp[ch * 8 + 2] + bl[ch * 8 + 2]),
                                    selu_f(rowp[ch * 8 + 3] + bl[ch * 8 + 3]));
            float4 v1 = make_float4(selu_f(rowp[ch * 8 + 4] + bl[ch * 8 + 4]),
                                    selu_f(rowp[ch * 8 + 5] + bl[ch * 8 + 5]),
                                    selu_f(rowp[ch * 8 + 6] + bl[ch * 8 + 6]),
                                    selu_f(rowp[ch * 8 + 7] + bl[ch * 8 + 7]));
            uint2 pa = f4_to_h4(v0);
            uint2 pb = f4_to_h4(v1);
            *(uint4*)(Cg + grow + ch * 8) = make_uint4(pa.x, pa.y, pb.x, pb.y);
        }
        __syncwarp();
    }
}

// ---------------- GEMM2 (reg-prefetch pipelined, half out, dinv2-scaled) ----------------
__global__ void __launch_bounds__(256) k_gemm2(
    const __half* __restrict__ A, const __half* __restrict__ B,
    const float* __restrict__ dinv2, __half* __restrict__ Cg, int n)
{
    const int BM = 128, BN = 64, BK = 32;
    __shared__ __half As[BM][BK + 8];
    __shared__ __half Bs[BK][BN + 8];
    __shared__ float  Cs[8][32][36];

    int tid  = threadIdx.x;
    int warp = tid >> 5;
    int lane = tid & 31;
    int wm = warp >> 1;
    int wn = warp & 1;
    int bm = blockIdx.x * BM;

    int ra = tid >> 2, ca = (tid & 3) * 8;    // A: rows ra, ra+64
    int rb = tid >> 3, cb = (tid & 7) * 8;    // B: row rb

    wmma::fragment<wmma::accumulator, 16, 16, 16, float> acc[2][2];
#pragma unroll
    for (int r = 0; r < 2; r++)
#pragma unroll
        for (int c = 0; c < 2; c++) wmma::fill_fragment(acc[r][c], 0.f);

    uint4 pa0 = *(const uint4*)(A + (size_t)(bm + ra) * D1 + ca);
    uint4 pa1 = *(const uint4*)(A + (size_t)(bm + ra + 64) * D1 + ca);
    uint4 pb0 = *(const uint4*)(B + (size_t)rb * D2 + cb);

    for (int k0 = 0; k0 < D1; k0 += BK) {
        *(uint4*)&As[ra][ca]      = pa0;
        *(uint4*)&As[ra + 64][ca] = pa1;
        *(uint4*)&Bs[rb][cb]      = pb0;
        __syncthreads();

        int kn = k0 + BK;
        if (kn < D1) {
            pa0 = *(const uint4*)(A + (size_t)(bm + ra) * D1 + kn + ca);
            pa1 = *(const uint4*)(A + (size_t)(bm + ra + 64) * D1 + kn + ca);
            pb0 = *(const uint4*)(B + (size_t)(kn + rb) * D2 + cb);
        }
#pragma unroll
        for (int kk = 0; kk < BK; kk += 16) {
            wmma::fragment<wmma::matrix_a, 16, 16, 16, __half, wmma::row_major> af[2];
            wmma::fragment<wmma::matrix_b, 16, 16, 16, __half, wmma::row_major> bf[2];
#pragma unroll
            for (int r = 0; r < 2; r++)
                wmma::load_matrix_sync(af[r], &As[wm * 32 + r * 16][kk], BK + 8);
#pragma unroll
            for (int c = 0; c < 2; c++)
                wmma::load_matrix_sync(bf[c], &Bs[kk][wn * 32 + c * 16], BN + 8);
#pragma unroll
            for (int r = 0; r < 2; r++)
#pragma unroll
                for (int c = 0; c < 2; c++)
                    wmma::mma_sync(acc[r][c], af[r], bf[c], acc[r][c]);
        }
        __syncthreads();
    }

#pragma unroll
    for (int r = 0; r < 2; r++)
#pragma unroll
        for (int c = 0; c < 2; c++)
            wmma::store_matrix_sync(&Cs[warp][r * 16][c * 16], acc[r][c], 36, wmma::mem_row_major);
    __syncwarp();

    int row = bm + wm * 32 + lane;
    float dv = (row < n) ? __ldg(dinv2 + row) : 0.f;
    float* rowp = &Cs[warp][lane][0];
    size_t grow = (size_t)row * D2 + wn * 32;
#pragma unroll
    for (int ch = 0; ch < 4; ch++) {
        float4 v0 = make_float4(dv * rowp[ch * 8 + 0], dv * rowp[ch * 8 + 1],
                                dv * rowp[ch * 8 + 2], dv * rowp[ch * 8 + 3]);
        float4 v1 = make_float4(dv * rowp[ch * 8 + 4], dv * rowp[ch * 8 + 5],
                                dv * rowp[ch * 8 + 6], dv * rowp[ch * 8 + 7]);
        uint2 a = f4_to_h4(v0);
        uint2 b = f4_to_h4(v1);
        *(uint4*)(Cg + grow + ch * 8) = make_uint4(a.x, a.y, b.x, b.y);
    }
}

// ---------------- final hop (weightless gather of gh=D2*g) + bias + log_softmax ----------------
__global__ void __launch_bounds__(256) k_out(
    const float* __restrict__ dinv2,
    const int* __restrict__ rowptr, const int* __restrict__ colidx,
    const float* __restrict__ b2, float* __restrict__ out, int n)
{
    int node = (blockIdx.x * blockDim.x + threadIdx.x) >> 5;
    int lane = threadIdx.x & 31;
    if (node >= n) return;
    int beg = rowptr[node], end = rowptr[node + 1];

    float2 sv = __half22float2(__ldg(((const __half2*)(g_gh + (size_t)node * D2)) + lane));
    float ax = sv.x;
    float ay = sv.y;

    for (int e0 = beg; e0 < end; e0 += 32) {
        int idx = e0 + lane;
        int c = (idx < end) ? colidx[idx] : 0;
        int cnt = min(32, end - e0);
        int j = 0;
        for (; j + 8 <= cnt; j += 8) {
            int cc[8];
#pragma unroll
            for (int q = 0; q < 8; q++) cc[q] = __shfl_sync(~0u, c, j + q);
            float2 v[8];
#pragma unroll
            for (int q = 0; q < 8; q++)
                v[q] = __half22float2(__ldg(((const __half2*)(g_gh + (size_t)cc[q] * D2)) + lane));
#pragma unroll
            for (int q = 0; q < 8; q++) { ax += v[q].x; ay += v[q].y; }
        }
        for (; j < cnt; j++) {
            int cj = __shfl_sync(~0u, c, j);
            float2 v = __half22float2(__ldg(((const __half2*)(g_gh + (size_t)cj * D2)) + lane));
            ax += v.x; ay += v.y;
        }
    }

    float di = __ldg(dinv2 + node);
    float p0 = di * ax + __ldg(b2 + lane * 2);
    float p1 = di * ay + __ldg(b2 + lane * 2 + 1);

    float m = fmaxf(p0, p1);
#pragma unroll
    for (int o = 16; o; o >>= 1) m = fmaxf(m, __shfl_xor_sync(~0u, m, o));
    float esum = expf(p0 - m) + expf(p1 - m);
#pragma unroll
    for (int o = 16; o; o >>= 1) esum += __shfl_xor_sync(~0u, esum, o);
    float lse = m + logf(esum);

    float2 res = make_float2(p0 - lse, p1 - lse);
    ((float2*)(out + (size_t)node * D2))[lane] = res;
}

// ---------------- launch ----------------
extern "C" void kernel_launch(void* const* d_in, const int* in_sizes, int n_in,
                              void* d_out, int out_size) {
    const float* x    = (const float*)d_in[0];
    const int*   esrc = (const int*)d_in[1];
    const int*   edst = (const int*)d_in[2];
    const float* W1   = (const float*)d_in[3];
    const float* b1   = (const float*)d_in[4];
    const float* W2   = (const float*)d_in[5];
    const float* b2   = (const float*)d_in[6];
    float* out = (float*)d_out;

    int n = in_sizes[0] / D1;   // 100000
    int e = in_sizes[1];        // 3200000

    __half *xh, *h1, *h2, *w1h, *w2h, *acth, *gh;
    float *dinv1, *dinv2;
    int *rowptr, *colidx;
    cudaGetSymbolAddress((void**)&xh, g_xh);
    cudaGetSymbolAddress((void**)&h1, g_h1);
    cudaGetSymbolAddress((void**)&h2, g_h2);
    cudaGetSymbolAddress((void**)&w1h, g_w1h);
    cudaGetSymbolAddress((void**)&w2h, g_w2h);
    cudaGetSymbolAddress((void**)&acth, g_acth);
    cudaGetSymbolAddress((void**)&gh, g_gh);
    cudaGetSymbolAddress((void**)&dinv1, g_dinv1);
    cudaGetSymbolAddress((void**)&dinv2, g_dinv2);
    cudaGetSymbolAddress((void**)&rowptr, g_rowptr);
    cudaGetSymbolAddress((void**)&colidx, g_col);

    int nb = (n + 255) / 256;          // 391
    int eb = (e + 255) / 256;          // 12500
    int hopBlocks = (n * 32 + 255) / 256;

    int nGroups = (eb + 6) / 7;        // 1786 groups of 8 blocks (7 fill + 1 convx)
    k_count<<<2048, 256>>>(edst, W1, W2, e);
    k_dinvreduce<<<nb, 256>>>(n);
    k_scatter<<<nb, 256>>>(nb, n);
    k_fillconv<<<nGroups * 8, 256>>>(esrc, edst, x, e, n, nGroups);

    // conv1: two weightless hops
    k_hop_h<true ><<<hopBlocks, 256>>>(xh, h1, dinv1, rowptr, colidx, 1.0f, n);
    k_hop_h<false><<<hopBlocks, 256>>>(h1, h2, dinv1, rowptr, colidx, 0.36787944117144233f, n);

    // GEMM1 (fused bias+SELU) and GEMM2 (fused dinv2 scale), both pipelined
    dim3 g1(NNP / 128, 2);
    k_gemm1<<<g1, 256>>>(h2, w1h, b1, acth);
    k_gemm2<<<NNP / 128, 256>>>(acth, w2h, dinv2, gh, n);

    k_out<<<hopBlocks, 256>>>(dinv2, rowptr, colidx, b2, out, n);
}

// round 14
// speedup vs baseline: 3.1097x; 1.0003x over previous
#include <cuda_runtime.h>
#include <cuda_fp16.h>
#include <mma.h>
#include <math.h>

using namespace nvcuda;

#define NN 100000
#define NNP 100096           // padded to multiple of 128 for wmma tiles
#define NE 3200000
#define D1 256
#define D2 64
#define NPARTMAX 512

// ---------------- static device scratch ----------------
// g_cnt is zero on first call and re-zeroed by the convx blocks of k_fillconv.
// g_woff is (re)initialized by k_scatter every call.
__device__ int    g_cnt[NN];
__device__ int    g_woff[NN];
__device__ int    g_rowptr[NN + 1];
__device__ int    g_part[NPARTMAX];
__device__ int    g_col[NE];
__device__ float  g_dinv1[NN];
__device__ float  g_dinv2[NN];
__device__ __half g_xh[(size_t)NN * D1];     // u0 = dinv1[i] * x[i,:] in half
__device__ __half g_h1[(size_t)NN * D1];     // u1 = dinv1^2 * (A u0)
__device__ __half g_h2[(size_t)NNP * D1];    // coeff * dinv1 * (A u1)  (pad rows stay 0)
__device__ __half g_w1h[D1 * D1];            // W1 half
__device__ __half g_w2h[D1 * D2];            // W2 half
__device__ __half g_acth[(size_t)NNP * D1];  // selu(h2@W1+b1) in half
__device__ __half g_gh[(size_t)NNP * D2];    // dinv2[i] * (acth@W2)[i,:] in half

// ---------------- helpers ----------------
__device__ __forceinline__ float selu_f(float x) {
    const float sc = 1.0507009873554804934f;
    const float al = 1.6732632423543772848f;
    return x > 0.f ? sc * x : sc * al * expm1f(x);
}

__device__ __forceinline__ void addh8(float2 a[4], float4 v) {
    __half2* hp = (__half2*)&v;
#pragma unroll
    for (int q = 0; q < 4; q++) {
        float2 f = __half22float2(hp[q]);
        a[q].x += f.x;
        a[q].y += f.y;
    }
}

__device__ __forceinline__ uint2 f4_to_h4(float4 v) {
    __half2 h0 = __floats2half2_rn(v.x, v.y);
    __half2 h1 = __floats2half2_rn(v.z, v.w);
    return make_uint2(*(unsigned*)&h0, *(unsigned*)&h1);
}

// ---------------- preprocessing ----------------
// count in-degrees, 4 edges/thread via int4 (g_cnt pre-zeroed) + convert W1/W2
__global__ void k_count(const int* __restrict__ dst, const float* __restrict__ W1,
                        const float* __restrict__ W2, int e) {
    int stride = gridDim.x * blockDim.x;
    int gtid = blockIdx.x * blockDim.x + threadIdx.x;
    int e4 = e >> 2;
    const int4* dst4 = (const int4*)dst;
    for (int j = gtid; j < e4; j += stride) {
        int4 d = __ldg(dst4 + j);
        atomicAdd(&g_cnt[d.x], 1);
        atomicAdd(&g_cnt[d.y], 1);
        atomicAdd(&g_cnt[d.z], 1);
        atomicAdd(&g_cnt[d.w], 1);
    }
    // tail
    for (int j = (e4 << 2) + gtid; j < e; j += stride)
        atomicAdd(&g_cnt[dst[j]], 1);
    if (gtid < (D1 * D1) / 4) ((uint2*)g_w1h)[gtid] = f4_to_h4(__ldg(((const float4*)W1) + gtid));
    if (gtid < (D1 * D2) / 4) ((uint2*)g_w2h)[gtid] = f4_to_h4(__ldg(((const float4*)W2) + gtid));
}

__global__ void k_dinvreduce(int n) {
    __shared__ int s[256];
    int t = threadIdx.x;
    int i = blockIdx.x * 256 + t;
    int d = 0;
    if (i < n) {
        d = g_cnt[i];
        g_dinv1[i] = d > 0 ? rsqrtf((float)d) : 0.f;
        g_dinv2[i] = rsqrtf((float)(d + 1));
    }
    s[t] = d;
    __syncthreads();
    for (int o = 128; o; o >>= 1) { if (t < o) s[t] += s[t + o]; __syncthreads(); }
    if (t == 0) g_part[blockIdx.x] = s[0];
}

// writes rowptr AND initializes g_woff = rowptr (fill uses woff directly)
__global__ void k_scatter(int nparts, int n) {
    __shared__ int spart[NPARTMAX];
    __shared__ int s[256];
    __shared__ int red[8];
    int t = threadIdx.x;
    int b = blockIdx.x;

    for (int i = t; i < nparts; i += 256) spart[i] = g_part[i];
    __syncthreads();

    int loc = 0;
    for (int i = t; i < b; i += 256) loc += spart[i];
#pragma unroll
    for (int o = 16; o; o >>= 1) loc += __shfl_xor_sync(~0u, loc, o);
    if ((t & 31) == 0) red[t >> 5] = loc;
    __syncthreads();
    int blockpre = red[0] + red[1] + red[2] + red[3] + red[4] + red[5] + red[6] + red[7];

    if (b == 0 && t == 0) {
        int tot = 0;
        for (int i = 0; i < nparts; i++) tot += spart[i];
        g_rowptr[n] = tot;
    }

    int i = b * 256 + t;
    int v = (i < n) ? g_cnt[i] : 0;
    s[t] = v;
    __syncthreads();
    for (int o = 1; o < 256; o <<= 1) {
        int x = (t >= o) ? s[t - o] : 0;
        __syncthreads();
        s[t] += x;
        __syncthreads();
    }
    if (i < n) {
        int rp = blockpre + s[t] - v;
        g_rowptr[i] = rp;
        g_woff[i] = rp;
    }
}

// fused CSR fill (2 edges/thread via int2) + x->half conversion, striped 3:1.
// Group of 4 blocks: slots 0-2 fill (512 edges each), slot 3 convx.
__global__ void k_fillconv(const int* __restrict__ src, const int* __restrict__ dst,
                           const float* __restrict__ x, int e, int n, int nGroups) {
    int g    = blockIdx.x >> 2;
    int slot = blockIdx.x & 3;
    if (slot != 3) {
        int pair = (g * 3 + slot) * 256 + threadIdx.x;   // pair index (2 edges)
        int i0 = pair * 2;
        if (i0 + 1 < e) {
            int2 s2 = __ldg((const int2*)(src) + pair);
            int2 d2 = __ldg((const int2*)(dst) + pair);
            int p0 = atomicAdd(&g_woff[d2.x], 1);
            int p1 = atomicAdd(&g_woff[d2.y], 1);
            g_col[p0] = s2.x;
            g_col[p1] = s2.y;
        } else if (i0 < e) {
            int p = atomicAdd(&g_woff[dst[i0]], 1);
            g_col[p] = src[i0];
        }
    } else {
        int stride = nGroups * 256;
        int total = n * (D1 / 4);
        for (int i = g * 256 + threadIdx.x; i < total; i += stride) {
            int row = i >> 6;               // 64 float4 groups per row
            float s = __ldg(g_dinv1 + row);
            float4 v = __ldg(((const float4*)x) + i);
            v.x *= s; v.y *= s; v.z *= s; v.w *= s;
            ((uint2*)g_xh)[i] = f4_to_h4(v);
            if (i < n) g_cnt[i] = 0;        // restore for next call
        }
    }
}

// ---------------- weightless 256-dim propagation hop ----------------
template<bool SQUARED>
__global__ void __launch_bounds__(256) k_hop_h(
    const __half* __restrict__ xin, __half* __restrict__ xout,
    const float* __restrict__ dinv, const int* __restrict__ rowptr,
    const int* __restrict__ colidx, float coeff, int n)
{
    int node = (blockIdx.x * blockDim.x + threadIdx.x) >> 5;
    int lane = threadIdx.x & 31;
    if (node >= n) return;
    int beg = rowptr[node], end = rowptr[node + 1];

    float2 a[4];
#pragma unroll
    for (int q = 0; q < 4; q++) a[q] = make_float2(0.f, 0.f);

    for (int e0 = beg; e0 < end; e0 += 32) {
        int idx = e0 + lane;
        int c = (idx < end) ? colidx[idx] : 0;
        int cnt = min(32, end - e0);
        int j = 0;
        for (; j + 8 <= cnt; j += 8) {
            int cc[8];
#pragma unroll
            for (int q = 0; q < 8; q++) cc[q] = __shfl_sync(~0u, c, j + q);
            float4 v[8];
#pragma unroll
            for (int q = 0; q < 8; q++)
                v[q] = __ldg(((const float4*)(xin + (size_t)cc[q] * D1)) + lane);
#pragma unroll
            for (int q = 0; q < 8; q++) addh8(a, v[q]);
        }
        for (; j < cnt; j++) {
            int cj = __shfl_sync(~0u, c, j);
            addh8(a, __ldg(((const float4*)(xin + (size_t)cj * D1)) + lane));
        }
    }

    float d = __ldg(dinv + node);
    float s = SQUARED ? d * d : coeff * d;
    __half2 o0 = __floats2half2_rn(s * a[0].x, s * a[0].y);
    __half2 o1 = __floats2half2_rn(s * a[1].x, s * a[1].y);
    __half2 o2 = __floats2half2_rn(s * a[2].x, s * a[2].y);
    __half2 o3 = __floats2half2_rn(s * a[3].x, s * a[3].y);
    uint4 u;
    u.x = *(unsigned*)&o0; u.y = *(unsigned*)&o1;
    u.z = *(unsigned*)&o2; u.w = *(unsigned*)&o3;
    ((uint4*)(xout + (size_t)node * D1))[lane] = u;
}

// ---------------- GEMM1 (reg-prefetch pipelined) + fused bias/SELU -> half ----------------
__global__ void __launch_bounds__(256) k_gemm1(
    const __half* __restrict__ A, const __half* __restrict__ B,
    const float* __restrict__ bias, __half* __restrict__ Cg)
{
    const int BM = 128, BN = 128, BK = 32;
    const int AS_BYTES = BM * (BK + 8) * 2;
    const int BS_BYTES = BK * (BN + 8) * 2;
    const int CS_BYTES = 8 * 16 * 68 * 4;
    __shared__ __align__(16) char smem_buf[CS_BYTES > AS_BYTES + BS_BYTES ? CS_BYTES : AS_BYTES + BS_BYTES];

    __half (*As)[BK + 8] = reinterpret_cast<__half(*)[BK + 8]>(smem_buf);
    __half (*Bs)[BN + 8] = reinterpret_cast<__half(*)[BN + 8]>(smem_buf + AS_BYTES);
    float  (*Cs)[68]     = reinterpret_cast<float(*)[68]>(smem_buf);

    int tid  = threadIdx.x;
    int warp = tid >> 5;
    int lane = tid & 31;
    int wm = warp >> 1;
    int wn = warp & 1;
    int bm = blockIdx.x * BM;
    int bn = blockIdx.y * BN;

    int ra = tid >> 2, ca = (tid & 3) * 8;        // A: rows ra, ra+64
    int rb = tid >> 4, cb = (tid & 15) * 8;       // B: rows rb, rb+16

    wmma::fragment<wmma::accumulator, 16, 16, 16, float> acc[2][4];
#pragma unroll
    for (int r = 0; r < 2; r++)
#pragma unroll
        for (int c = 0; c < 4; c++) wmma::fill_fragment(acc[r][c], 0.f);

    uint4 pa0 = *(const uint4*)(A + (size_t)(bm + ra) * D1 + ca);
    uint4 pa1 = *(const uint4*)(A + (size_t)(bm + ra + 64) * D1 + ca);
    uint4 pb0 = *(const uint4*)(B + (size_t)rb * D1 + bn + cb);
    uint4 pb1 = *(const uint4*)(B + (size_t)(rb + 16) * D1 + bn + cb);

    for (int k0 = 0; k0 < D1; k0 += BK) {
        *(uint4*)&As[ra][ca]      = pa0;
        *(uint4*)&As[ra + 64][ca] = pa1;
        *(uint4*)&Bs[rb][cb]      = pb0;
        *(uint4*)&Bs[rb + 16][cb] = pb1;
        __syncthreads();

        int kn = k0 + BK;
        if (kn < D1) {   // prefetch next tile while mma runs
            pa0 = *(const uint4*)(A + (size_t)(bm + ra) * D1 + kn + ca);
            pa1 = *(const uint4*)(A + (size_t)(bm + ra + 64) * D1 + kn + ca);
            pb0 = *(const uint4*)(B + (size_t)(kn + rb) * D1 + bn + cb);
            pb1 = *(const uint4*)(B + (size_t)(kn + rb + 16) * D1 + bn + cb);
        }
#pragma unroll
        for (int kk = 0; kk < BK; kk += 16) {
            wmma::fragment<wmma::matrix_a, 16, 16, 16, __half, wmma::row_major> af[2];
            wmma::fragment<wmma::matrix_b, 16, 16, 16, __half, wmma::row_major> bf[4];
#pragma unroll
            for (int r = 0; r < 2; r++)
                wmma::load_matrix_sync(af[r], &As[wm * 32 + r * 16][kk], BK + 8);
#pragma unroll
            for (int c = 0; c < 4; c++)
                wmma::load_matrix_sync(bf[c], &Bs[kk][wn * 64 + c * 16], BN + 8);
#pragma unroll
            for (int r = 0; r < 2; r++)
#pragma unroll
                for (int c = 0; c < 4; c++)
                    wmma::mma_sync(acc[r][c], af[r], bf[c], acc[r][c]);
        }
        __syncthreads();
    }

    int colbase = bn + wn * 64;
    float bl[32];
    {
        int cb2 = colbase + (lane & 1) * 32;
#pragma unroll
        for (int ch = 0; ch < 8; ch++) {
            float4 b4 = __ldg((const float4*)(bias + cb2 + ch * 4));
            bl[ch * 4 + 0] = b4.x; bl[ch * 4 + 1] = b4.y;
            bl[ch * 4 + 2] = b4.z; bl[ch * 4 + 3] = b4.w;
        }
    }
#pragma unroll
    for (int r = 0; r < 2; r++) {
#pragma unroll
        for (int c = 0; c < 4; c++)
            wmma::store_matrix_sync(&Cs[warp * 16][c * 16], acc[r][c], 68, wmma::mem_row_major);
        __syncwarp();
        int row = lane >> 1;
        int half_sel = (lane & 1) * 32;
        float* rowp = &Cs[warp * 16 + row][half_sel];
        size_t grow = (size_t)(bm + wm * 32 + r * 16 + row) * D1 + colbase + half_sel;
#pragma unroll
        for (int ch = 0; ch < 4; ch++) {
            float4 v0 = make_float4(selu_f(rowp[ch * 8 + 0] + bl[ch * 8 + 0]),
                                    selu_f(rowp[ch * 8 + 1] + bl[ch * 8 + 1]),
                                    selu_f(rowp[ch * 8 + 2] + bl[ch * 8 + 2]),
                                    selu_f(rowp[ch * 8 + 3] + bl[ch * 8 + 3]));
            float4 v1 = make_float4(selu_f(rowp[ch * 8 + 4] + bl[ch * 8 + 4]),
                                    selu_f(rowp[ch * 8 + 5] + bl[ch * 8 + 5]),
                                    selu_f(rowp[ch * 8 + 6] + bl[ch * 8 + 6]),
                                    selu_f(rowp[ch * 8 + 7] + bl[ch * 8 + 7]));
            uint2 pa = f4_to_h4(v0);
            uint2 pb = f4_to_h4(v1);
            *(uint4*)(Cg + grow + ch * 8) = make_uint4(pa.x, pa.y, pb.x, pb.y);
        }
        __syncwarp();
    }
}

// ---------------- GEMM2 (reg-prefetch pipelined, half out, dinv2-scaled) ----------------
__global__ void __launch_bounds__(256) k_gemm2(
    const __half* __restrict__ A, const __half* __restrict__ B,
    const float* __restrict__ dinv2, __half* __restrict__ Cg, int n)
{
    const int BM = 128, BN = 64, BK = 32;
    __shared__ __half As[BM][BK + 8];
    __shared__ __half Bs[BK][BN + 8];
    __shared__ float  Cs[8][32][36];

    int tid  = threadIdx.x;
    int warp = tid >> 5;
    int lane = tid & 31;
    int wm = warp >> 1;
    int wn = warp & 1;
    int bm = blockIdx.x * BM;

    int ra = tid >> 2, ca = (tid & 3) * 8;    // A: rows ra, ra+64
    int rb = tid >> 3, cb = (tid & 7) * 8;    // B: row rb

    wmma::fragment<wmma::accumulator, 16, 16, 16, float> acc[2][2];
#pragma unroll
    for (int r = 0; r < 2; r++)
#pragma unroll
        for (int c = 0; c < 2; c++) wmma::fill_fragment(acc[r][c], 0.f);

    uint4 pa0 = *(const uint4*)(A + (size_t)(bm + ra) * D1 + ca);
    uint4 pa1 = *(const uint4*)(A + (size_t)(bm + ra + 64) * D1 + ca);
    uint4 pb0 = *(const uint4*)(B + (size_t)rb * D2 + cb);

    for (int k0 = 0; k0 < D1; k0 += BK) {
        *(uint4*)&As[ra][ca]      = pa0;
        *(uint4*)&As[ra + 64][ca] = pa1;
        *(uint4*)&Bs[rb][cb]      = pb0;
        __syncthreads();

        int kn = k0 + BK;
        if (kn < D1) {
            pa0 = *(const uint4*)(A + (size_t)(bm + ra) * D1 + kn + ca);
            pa1 = *(const uint4*)(A + (size_t)(bm + ra + 64) * D1 + kn + ca);
            pb0 = *(const uint4*)(B + (size_t)(kn + rb) * D2 + cb);
        }
#pragma unroll
        for (int kk = 0; kk < BK; kk += 16) {
            wmma::fragment<wmma::matrix_a, 16, 16, 16, __half, wmma::row_major> af[2];
            wmma::fragment<wmma::matrix_b, 16, 16, 16, __half, wmma::row_major> bf[2];
#pragma unroll
            for (int r = 0; r < 2; r++)
                wmma::load_matrix_sync(af[r], &As[wm * 32 + r * 16][kk], BK + 8);
#pragma unroll
            for (int c = 0; c < 2; c++)
                wmma::load_matrix_sync(bf[c], &Bs[kk][wn * 32 + c * 16], BN + 8);
#pragma unroll
            for (int r = 0; r < 2; r++)
#pragma unroll
                for (int c = 0; c < 2; c++)
                    wmma::mma_sync(acc[r][c], af[r], bf[c], acc[r][c]);
        }
        __syncthreads();
    }

#pragma unroll
    for (int r = 0; r < 2; r++)
#pragma unroll
        for (int c = 0; c < 2; c++)
            wmma::store_matrix_sync(&Cs[warp][r * 16][c * 16], acc[r][c], 36, wmma::mem_row_major);
    __syncwarp();

    int row = bm + wm * 32 + lane;
    float dv = (row < n) ? __ldg(dinv2 + row) : 0.f;
    float* rowp = &Cs[warp][lane][0];
    size_t grow = (size_t)row * D2 + wn * 32;
#pragma unroll
    for (int ch = 0; ch < 4; ch++) {
        float4 v0 = make_float4(dv * rowp[ch * 8 + 0], dv * rowp[ch * 8 + 1],
                                dv * rowp[ch * 8 + 2], dv * rowp[ch * 8 + 3]);
        float4 v1 = make_float4(dv * rowp[ch * 8 + 4], dv * rowp[ch * 8 + 5],
                                dv * rowp[ch * 8 + 6], dv * rowp[ch * 8 + 7]);
        uint2 a = f4_to_h4(v0);
        uint2 b = f4_to_h4(v1);
        *(uint4*)(Cg + grow + ch * 8) = make_uint4(a.x, a.y, b.x, b.y);
    }
}

// ---------------- final hop (weightless gather of gh=D2*g) + bias + log_softmax ----------------
__global__ void __launch_bounds__(256) k_out(
    const float* __restrict__ dinv2,
    const int* __restrict__ rowptr, const int* __restrict__ colidx,
    const float* __restrict__ b2, float* __restrict__ out, int n)
{
    int node = (blockIdx.x * blockDim.x + threadIdx.x) >> 5;
    int lane = threadIdx.x & 31;
    if (node >= n) return;
    int beg = rowptr[node], end = rowptr[node + 1];

    float2 sv = __half22float2(__ldg(((const __half2*)(g_gh + (size_t)node * D2)) + lane));
    float ax = sv.x;
    float ay = sv.y;

    for (int e0 = beg; e0 < end; e0 += 32) {
        int idx = e0 + lane;
        int c = (idx < end) ? colidx[idx] : 0;
        int cnt = min(32, end - e0);
        int j = 0;
        for (; j + 8 <= cnt; j += 8) {
            int cc[8];
#pragma unroll
            for (int q = 0; q < 8; q++) cc[q] = __shfl_sync(~0u, c, j + q);
            float2 v[8];
#pragma unroll
            for (int q = 0; q < 8; q++)
                v[q] = __half22float2(__ldg(((const __half2*)(g_gh + (size_t)cc[q] * D2)) + lane));
#pragma unroll
            for (int q = 0; q < 8; q++) { ax += v[q].x; ay += v[q].y; }
        }
        for (; j < cnt; j++) {
            int cj = __shfl_sync(~0u, c, j);
            float2 v = __half22float2(__ldg(((const __half2*)(g_gh + (size_t)cj * D2)) + lane));
            ax += v.x; ay += v.y;
        }
    }

    float di = __ldg(dinv2 + node);
    float p0 = di * ax + __ldg(b2 + lane * 2);
    float p1 = di * ay + __ldg(b2 + lane * 2 + 1);

    float m = fmaxf(p0, p1);
#pragma unroll
    for (int o = 16; o; o >>= 1) m = fmaxf(m, __shfl_xor_sync(~0u, m, o));
    float esum = expf(p0 - m) + expf(p1 - m);
#pragma unroll
    for (int o = 16; o; o >>= 1) esum += __shfl_xor_sync(~0u, esum, o);
    float lse = m + logf(esum);

    float2 res = make_float2(p0 - lse, p1 - lse);
    ((float2*)(out + (size_t)node * D2))[lane] = res;
}

// ---------------- launch ----------------
extern "C" void kernel_launch(void* const* d_in, const int* in_sizes, int n_in,
                              void* d_out, int out_size) {
    const float* x    = (const float*)d_in[0];
    const int*   esrc = (const int*)d_in[1];
    const int*   edst = (const int*)d_in[2];
    const float* W1   = (const float*)d_in[3];
    const float* b1   = (const float*)d_in[4];
    const float* W2   = (const float*)d_in[5];
    const float* b2   = (const float*)d_in[6];
    float* out = (float*)d_out;

    int n = in_sizes[0] / D1;   // 100000
    int e = in_sizes[1];        // 3200000

    __half *xh, *h1, *h2, *w1h, *w2h, *acth, *gh;
    float *dinv1, *dinv2;
    int *rowptr, *colidx;
    cudaGetSymbolAddress((void**)&xh, g_xh);
    cudaGetSymbolAddress((void**)&h1, g_h1);
    cudaGetSymbolAddress((void**)&h2, g_h2);
    cudaGetSymbolAddress((void**)&w1h, g_w1h);
    cudaGetSymbolAddress((void**)&w2h, g_w2h);
    cudaGetSymbolAddress((void**)&acth, g_acth);
    cudaGetSymbolAddress((void**)&gh, g_gh);
    cudaGetSymbolAddress((void**)&dinv1, g_dinv1);
    cudaGetSymbolAddress((void**)&dinv2, g_dinv2);
    cudaGetSymbolAddress((void**)&rowptr, g_rowptr);
    cudaGetSymbolAddress((void**)&colidx, g_col);

    int nb = (n + 255) / 256;          // 391
    int hopBlocks = (n * 32 + 255) / 256;

    // fill processes 512 edges/block (2 per thread); stripe 3 fill : 1 convx
    int fillBlocks = (e + 511) / 512;              // 6250
    int nGroups = (fillBlocks + 2) / 3;            // 2084
    k_count<<<1024, 256>>>(edst, W1, W2, e);
    k_dinvreduce<<<nb, 256>>>(n);
    k_scatter<<<nb, 256>>>(nb, n);
    k_fillconv<<<nGroups * 4, 256>>>(esrc, edst, x, e, n, nGroups);

    // conv1: two weightless hops
    k_hop_h<true ><<<hopBlocks, 256>>>(xh, h1, dinv1, rowptr, colidx, 1.0f, n);
    k_hop_h<false><<<hopBlocks, 256>>>(h1, h2, dinv1, rowptr, colidx, 0.36787944117144233f, n);

    // GEMM1 (fused bias+SELU) and GEMM2 (fused dinv2 scale), both pipelined
    dim3 g1(NNP / 128, 2);
    k_gemm1<<<g1, 256>>>(h2, w1h, b1, acth);
    k_gemm2<<<NNP / 128, 256>>>(acth, w2h, dinv2, gh, n);

    k_out<<<hopBlocks, 256>>>(dinv2, rowptr, colidx, b2, out, n);
}